// round 6
// baseline (speedup 1.0000x reference)
#include <cuda_runtime.h>
#include <cuda_bf16.h>
#include <cstdint>

#define Bv      2
#define Sv      4096
#define QKVD    2048
#define NHEAD   16
#define NKVH    8
#define HDIM    64
#define NFEAT   64
#define CHUNK   128
#define NCHUNK  32
#define MROWS   (Bv*Sv)

// ---------------- scratch (device globals; no allocs allowed) ----------------
__device__ float g_qkv [(size_t)MROWS*QKVD];
__device__ float g_qp  [(size_t)MROWS*NHEAD*NFEAT];
__device__ float g_kp  [(size_t)MROWS*NKVH*NFEAT];
__device__ float g_z   [(size_t)Bv*NKVH*Sv];
__device__ float g_kvc [(size_t)Bv*NKVH*NCHUNK*NFEAT*HDIM];
__device__ float g_attn[(size_t)MROWS*1024];

__device__ int8_t g_a1 [(size_t)MROWS*1024];
__device__ int8_t g_a0 [(size_t)MROWS*1024];
__device__ int8_t g_w1a[(size_t)2048*1024];
__device__ int8_t g_w1b[(size_t)2048*1024];
__device__ int8_t g_w2a[(size_t)1024*1024];
__device__ int8_t g_w2b[(size_t)1024*1024];
__device__ float  g_sa [MROWS];
__device__ float  g_s1 [2048];
__device__ float  g_s2 [1024];

// ---------------- PTX helpers -------------------------------------------------
__device__ __forceinline__ uint32_t smem_u32(const void* p) {
    uint32_t a;
    asm("{ .reg .u64 t; cvta.to.shared.u64 t, %1; cvt.u32.u64 %0, t; }" : "=r"(a) : "l"(p));
    return a;
}
__device__ __forceinline__ void ldsm_x4(uint32_t& r0, uint32_t& r1,
                                        uint32_t& r2, uint32_t& r3, uint32_t a) {
    asm volatile("ldmatrix.sync.aligned.m8n8.x4.shared.b16 {%0,%1,%2,%3}, [%4];"
                 : "=r"(r0), "=r"(r1), "=r"(r2), "=r"(r3) : "r"(a));
}
__device__ __forceinline__ void ldsm_x2(uint32_t& r0, uint32_t& r1, uint32_t a) {
    asm volatile("ldmatrix.sync.aligned.m8n8.x2.shared.b16 {%0,%1}, [%2];"
                 : "=r"(r0), "=r"(r1) : "r"(a));
}
__device__ __forceinline__ void ldsm_x2_t(uint32_t& r0, uint32_t& r1, uint32_t a) {
    asm volatile("ldmatrix.sync.aligned.m8n8.x2.trans.shared.b16 {%0,%1}, [%2];"
                 : "=r"(r0), "=r"(r1) : "r"(a));
}
__device__ __forceinline__ void mma_bf16(float* d,
    uint32_t a0, uint32_t a1, uint32_t a2, uint32_t a3, uint32_t b0, uint32_t b1) {
    asm volatile(
        "mma.sync.aligned.m16n8k16.row.col.f32.bf16.bf16.f32 "
        "{%0,%1,%2,%3}, {%4,%5,%6,%7}, {%8,%9}, {%0,%1,%2,%3};"
        : "+f"(d[0]), "+f"(d[1]), "+f"(d[2]), "+f"(d[3])
        : "r"(a0), "r"(a1), "r"(a2), "r"(a3), "r"(b0), "r"(b1));
}
__device__ __forceinline__ void mma_s8(int* d,
    uint32_t a0, uint32_t a1, uint32_t a2, uint32_t a3, uint32_t b0, uint32_t b1) {
    asm volatile(
        "mma.sync.aligned.m16n8k32.row.col.s32.s8.s8.s32 "
        "{%0,%1,%2,%3}, {%4,%5,%6,%7}, {%8,%9}, {%0,%1,%2,%3};"
        : "+r"(d[0]), "+r"(d[1]), "+r"(d[2]), "+r"(d[3])
        : "r"(a0), "r"(a1), "r"(a2), "r"(a3), "r"(b0), "r"(b1));
}
__device__ __forceinline__ uint32_t pack2(float x, float y) {
    __nv_bfloat16 bx = __float2bfloat16(x), by = __float2bfloat16(y);
    return (uint32_t)__bfloat16_as_ushort(bx) |
           ((uint32_t)__bfloat16_as_ushort(by) << 16);
}

// ---------------- per-row int8 2-limb quantization (K=1024) -------------------
__global__ void __launch_bounds__(256) quant_rows_kernel(
    const float* __restrict__ src, int8_t* __restrict__ q1,
    int8_t* __restrict__ q0, float* __restrict__ scale)
{
    const int row = blockIdx.x;
    const int tid = threadIdx.x;
    const int lane = tid & 31, warp = tid >> 5;
    __shared__ float wm[8];
    __shared__ float smax;

    float4 v = ((const float4*)(src + (size_t)row * 1024))[tid];
    float m = fmaxf(fmaxf(fabsf(v.x), fabsf(v.y)), fmaxf(fabsf(v.z), fabsf(v.w)));
    #pragma unroll
    for (int o = 16; o >= 1; o >>= 1)
        m = fmaxf(m, __shfl_xor_sync(0xffffffffu, m, o));
    if (lane == 0) wm[warp] = m;
    __syncthreads();
    if (tid == 0) {
        float mx = wm[0];
        #pragma unroll
        for (int w = 1; w < 8; w++) mx = fmaxf(mx, wm[w]);
        smax = fmaxf(mx, 1e-20f);
        scale[row] = smax * (1.0f / 16256.0f);
    }
    __syncthreads();

    const float inv = 16256.0f / smax;
    float a[4] = {v.x*inv, v.y*inv, v.z*inv, v.w*inv};
    int i1[4], i0[4];
    #pragma unroll
    for (int j = 0; j < 4; j++) {
        float f1 = rintf(a[j] * 0.0078125f);
        i1[j] = (int)f1;
        i0[j] = (int)rintf(a[j] - f1 * 128.0f);
    }
    char4 c1 = {(char)i1[0], (char)i1[1], (char)i1[2], (char)i1[3]};
    char4 c0 = {(char)i0[0], (char)i0[1], (char)i0[2], (char)i0[3]};
    ((char4*)(q1 + (size_t)row * 1024))[tid] = c1;
    ((char4*)(q0 + (size_t)row * 1024))[tid] = c0;
}

// ---------------- int8 split GEMM: C[M,N] = A[M,K]*B[N,K]^T -------------------
// C = sa[m]*sb[n] * (2^14 * a1b1 + 2^7 * (a1b0 + a0b1)); a0b0 dropped.
#define GI_RS   80
#define GI_BUF  (128*GI_RS)
#define GI_SMEM (2*4*GI_BUF)

__global__ void __launch_bounds__(512) gemm_i8_kernel(
    const int8_t* __restrict__ A1, const int8_t* __restrict__ A0,
    const int8_t* __restrict__ B1, const int8_t* __restrict__ B0,
    const float* __restrict__ sa, const float* __restrict__ sb,
    float* __restrict__ C, int N, int K)
{
    extern __shared__ int8_t smi[];
    const int tid = threadIdx.x;
    const int m0 = blockIdx.y * 128, n0 = blockIdx.x * 128;
    const int row = tid >> 2, off = (tid & 3) * 16;

    const int8_t* gp0 = A1 + (size_t)(m0 + row) * K + off;
    const int8_t* gp1 = A0 + (size_t)(m0 + row) * K + off;
    const int8_t* gp2 = B1 + (size_t)(n0 + row) * K + off;
    const int8_t* gp3 = B0 + (size_t)(n0 + row) * K + off;

    const int wid = tid >> 5, lane = tid & 31;
    const int wm = wid >> 2, wn = wid & 3;
    const int l16 = lane & 15;

    int acc1[2][4][4], accX[2][4][4];
    #pragma unroll
    for (int mi = 0; mi < 2; mi++)
        #pragma unroll
        for (int ni = 0; ni < 4; ni++)
            #pragma unroll
            for (int r = 0; r < 4; r++) { acc1[mi][ni][r] = 0; accX[mi][ni][r] = 0; }

    const int sto = row * GI_RS + off;
    uint4 ld[4];

    ld[0] = *(const uint4*)gp0;
    ld[1] = *(const uint4*)gp1;
    ld[2] = *(const uint4*)gp2;
    ld[3] = *(const uint4*)gp3;
    #pragma unroll
    for (int a = 0; a < 4; a++)
        *(uint4*)&smi[a*GI_BUF + sto] = ld[a];
    __syncthreads();

    const int NKT = K >> 6;
    for (int kt = 0; kt < NKT; kt++) {
        const int b = kt & 1;
        if (kt + 1 < NKT) {
            const int kb = (kt + 1) << 6;
            ld[0] = *(const uint4*)(gp0 + kb);
            ld[1] = *(const uint4*)(gp1 + kb);
            ld[2] = *(const uint4*)(gp2 + kb);
            ld[3] = *(const uint4*)(gp3 + kb);
        }

        const int8_t* sA1 = smi + b*(4*GI_BUF);
        const int8_t* sA0 = sA1 + GI_BUF;
        const int8_t* sB1 = sA0 + GI_BUF;
        const int8_t* sB0 = sB1 + GI_BUF;

        #pragma unroll
        for (int k32 = 0; k32 < 64; k32 += 32) {
            uint32_t a1f[2][4], a0f[2][4];
            #pragma unroll
            for (int mi = 0; mi < 2; mi++) {
                int ro = (wm*32 + mi*16 + l16) * GI_RS + k32 + (lane >> 4) * 16;
                ldsm_x4(a1f[mi][0], a1f[mi][1], a1f[mi][2], a1f[mi][3], smem_u32(sA1 + ro));
                ldsm_x4(a0f[mi][0], a0f[mi][1], a0f[mi][2], a0f[mi][3], smem_u32(sA0 + ro));
            }
            #pragma unroll
            for (int ni = 0; ni < 4; ni++) {
                int bo = (wn*32 + ni*8 + (l16 & 7)) * GI_RS + k32 + ((l16 >> 3) & 1) * 16;
                uint32_t b1f0, b1f1, b0f0, b0f1;
                ldsm_x2(b1f0, b1f1, smem_u32(sB1 + bo));
                ldsm_x2(b0f0, b0f1, smem_u32(sB0 + bo));
                #pragma unroll
                for (int mi = 0; mi < 2; mi++) {
                    mma_s8(acc1[mi][ni], a1f[mi][0], a1f[mi][1], a1f[mi][2], a1f[mi][3], b1f0, b1f1);
                    mma_s8(accX[mi][ni], a1f[mi][0], a1f[mi][1], a1f[mi][2], a1f[mi][3], b0f0, b0f1);
                    mma_s8(accX[mi][ni], a0f[mi][0], a0f[mi][1], a0f[mi][2], a0f[mi][3], b1f0, b1f1);
                }
            }
        }

        if (kt + 1 < NKT) {
            int8_t* dst = smi + (b ^ 1)*(4*GI_BUF);
            #pragma unroll
            for (int a = 0; a < 4; a++)
                *(uint4*)&dst[a*GI_BUF + sto] = ld[a];
        }
        __syncthreads();
    }

    const int g = lane >> 2, tg = lane & 3;
    #pragma unroll
    for (int mi = 0; mi < 2; mi++) {
        int r0 = m0 + wm*32 + mi*16 + g;
        int r1 = r0 + 8;
        float s0 = sa[r0], s1 = sa[r1];
        #pragma unroll
        for (int ni = 0; ni < 4; ni++) {
            int c0 = n0 + wn*32 + ni*8 + tg*2;
            float sb0 = sb[c0], sb1 = sb[c0 + 1];
            float v00 = s0*sb0*fmaf(16384.f, __int2float_rn(acc1[mi][ni][0]),
                                    128.f * __int2float_rn(accX[mi][ni][0]));
            float v01 = s0*sb1*fmaf(16384.f, __int2float_rn(acc1[mi][ni][1]),
                                    128.f * __int2float_rn(accX[mi][ni][1]));
            float v10 = s1*sb0*fmaf(16384.f, __int2float_rn(acc1[mi][ni][2]),
                                    128.f * __int2float_rn(accX[mi][ni][2]));
            float v11 = s1*sb1*fmaf(16384.f, __int2float_rn(acc1[mi][ni][3]),
                                    128.f * __int2float_rn(accX[mi][ni][3]));
            float2 lo = {v00, v01};
            float2 hi = {v10, v11};
            *(float2*)&C[(size_t)r0 * N + c0] = lo;
            *(float2*)&C[(size_t)r1 * N + c0] = hi;
        }
    }
}

// ---------------- RoPE + relu feature projection (128 thr, 8x4 tiles) --------
__global__ void __launch_bounds__(128) ropeproj_kernel(
    const float* __restrict__ cosg, const float* __restrict__ sing,
    const float* __restrict__ proj)
{
    __shared__ float dat[64*68];   // [d][r]
    __shared__ float pj [64*68];   // [d][f]
    const int tid = threadIdx.x;
    const int rbase = blockIdx.x * 64;

    #pragma unroll
    for (int j = 0; j < 32; j++) {
        int i = tid + j*128;
        int f = i >> 6, d = i & 63;
        pj[d*68 + f] = proj[i];
    }
    #pragma unroll
    for (int j = 0; j < 32; j++) {
        int e = tid + j*128;
        int r = e >> 6, d = e & 63;
        int rho = rbase + r;
        int bs  = rho / 24;
        int h   = rho - bs*24;
        int s   = bs & (Sv-1);
        size_t base = (size_t)bs*QKVD + h*64;
        float val  = g_qkv[base + d];
        int   pd   = (d < 32) ? d + 32 : d - 32;
        float part = g_qkv[base + pd];
        float rot  = (d < 32) ? -part : part;
        dat[d*68 + r] = fmaf(val, cosg[s*64 + d], rot * sing[s*64 + d]);
    }
    __syncthreads();

    const int rq = tid >> 4, fq = tid & 15;
    float acc[8][4];
    #pragma unroll
    for (int i = 0; i < 8; i++)
        #pragma unroll
        for (int j = 0; j < 4; j++) acc[i][j] = 0.f;

    #pragma unroll
    for (int k = 0; k < 64; k++) {
        float4 a0 = *(const float4*)&dat[k*68 + rq*8];
        float4 a1 = *(const float4*)&dat[k*68 + rq*8 + 4];
        float4 bv = *(const float4*)&pj [k*68 + fq*4];
        float av[8] = {a0.x,a0.y,a0.z,a0.w,a1.x,a1.y,a1.z,a1.w};
        #pragma unroll
        for (int i = 0; i < 8; i++) {
            acc[i][0] = fmaf(av[i], bv.x, acc[i][0]);
            acc[i][1] = fmaf(av[i], bv.y, acc[i][1]);
            acc[i][2] = fmaf(av[i], bv.z, acc[i][2]);
            acc[i][3] = fmaf(av[i], bv.w, acc[i][3]);
        }
    }

    const float ratio = (float)(0.125 * (0.125 + 1e-4));
    #pragma unroll
    for (int i = 0; i < 8; i++) {
        int rho = rbase + rq*8 + i;
        int bs  = rho / 24;
        int h   = rho - bs*24;
        float4 o;
        o.x = fmaxf(acc[i][0]*ratio, 0.f);
        o.y = fmaxf(acc[i][1]*ratio, 0.f);
        o.z = fmaxf(acc[i][2]*ratio, 0.f);
        o.w = fmaxf(acc[i][3]*ratio, 0.f);
        if (h < NHEAD) {
            o.x += 1e-4f; o.y += 1e-4f; o.z += 1e-4f; o.w += 1e-4f;
            *(float4*)&g_qp[((size_t)bs*NHEAD + h)*NFEAT + fq*4] = o;
        } else {
            *(float4*)&g_kp[((size_t)bs*NKVH + (h - NHEAD))*NFEAT + fq*4] = o;
        }
    }
}

// ---------------- kp row sums (parallel) --------------------------------------
__global__ void __launch_bounds__(256) kpsum_kernel()
{
    int r = blockIdx.x * 256 + threadIdx.x;
    int bs = r >> 3, kvh = r & 7;
    int b = bs >> 12, t = bs & 4095;
    const float* row = g_kp + (size_t)r * 64;
    float s = 0.f;
    #pragma unroll
    for (int f = 0; f < 64; f += 4) {
        float4 v = *(const float4*)(row + f);
        s += (v.x + v.y) + (v.z + v.w);
    }
    g_z[((size_t)(b*8 + kvh))*Sv + t] = s;
}

// ---------------- inclusive scan of g_z per (b,kvh), in place -----------------
__global__ void __launch_bounds__(256) zscan_kernel()
{
    const int bkv = blockIdx.x;
    const int tid = threadIdx.x;
    const int lane = tid & 31, warp = tid >> 5;
    __shared__ float wsum[8];
    float carry = 0.f;

    for (int tile = 0; tile < 16; tile++) {
        int t = tile*256 + tid;
        float x = g_z[(size_t)bkv*Sv + t];
        #pragma unroll
        for (int o = 1; o < 32; o <<= 1) {
            float n = __shfl_up_sync(0xffffffffu, x, o);
            if (lane >= o) x += n;
        }
        if (lane == 31) wsum[warp] = x;
        __syncthreads();
        float off = carry;
        for (int w2 = 0; w2 < warp; w2++) off += wsum[w2];
        g_z[(size_t)bkv*Sv + t] = off + x;
        float tot = 0.f;
        #pragma unroll
        for (int w2 = 0; w2 < 8; w2++) tot += wsum[w2];
        carry += tot;
        __syncthreads();
    }
}

// ---------------- per-chunk KV = Kp^T V (64x64) ------------------------------
__global__ void __launch_bounds__(256) chunkkv_kernel()
{
    extern __shared__ float cs[];
    float* Ks = cs;
    float* Vs = cs + 8192;
    const int c   = blockIdx.x;
    const int bkv = blockIdx.y;
    const int b   = bkv >> 3, kvh = bkv & 7;
    const int tid = threadIdx.x;

    #pragma unroll
    for (int j = 0; j < 32; j++) {
        int e = tid + j*256;
        int t = e >> 6, f = e & 63;
        size_t bs = (size_t)(b*Sv + c*CHUNK + t);
        Ks[e] = g_kp[(bs*NKVH + kvh)*NFEAT + f];
        Vs[e] = g_qkv[bs*QKVD + 1536 + kvh*64 + f];
    }
    __syncthreads();

    const int fq = tid >> 4, dq = tid & 15;
    float acc[4][4];
    #pragma unroll
    for (int i = 0; i < 4; i++)
        #pragma unroll
        for (int j = 0; j < 4; j++) acc[i][j] = 0.f;

    #pragma unroll 8
    for (int t = 0; t < 128; t++) {
        float4 a = *(const float4*)&Ks[t*64 + fq*4];
        float4 v = *(const float4*)&Vs[t*64 + dq*4];
        float av[4] = {a.x,a.y,a.z,a.w};
        #pragma unroll
        for (int i = 0; i < 4; i++) {
            acc[i][0] = fmaf(av[i], v.x, acc[i][0]);
            acc[i][1] = fmaf(av[i], v.y, acc[i][1]);
            acc[i][2] = fmaf(av[i], v.z, acc[i][2]);
            acc[i][3] = fmaf(av[i], v.w, acc[i][3]);
        }
    }
    size_t base = ((size_t)bkv*NCHUNK + c)*4096;
    #pragma unroll
    for (int i = 0; i < 4; i++) {
        float4 o = {acc[i][0], acc[i][1], acc[i][2], acc[i][3]};
        *(float4*)&g_kvc[base + (size_t)(fq*4 + i)*64 + dq*4] = o;
    }
}

// ---------------- exclusive chunk-prefix of KV, in place ---------------------
__global__ void __launch_bounds__(256) kvprefix_kernel()
{
    const int bkv = blockIdx.x;
    const int tid = threadIdx.x;
    float acc[16];
    #pragma unroll
    for (int j = 0; j < 16; j++) acc[j] = 0.f;
    for (int c = 0; c < NCHUNK; c++) {
        size_t base = ((size_t)bkv*NCHUNK + c)*4096;
        #pragma unroll
        for (int j = 0; j < 16; j++) {
            size_t idx = base + tid + j*256;
            float cur = g_kvc[idx];
            g_kvc[idx] = acc[j];
            acc[j] += cur;
        }
    }
}

// ---------------- stage D: mma.sync split-bf16 causal combine ----------------
#define SD_QP  72
#define SD_SP  136
#define SD_BYTES (99328*2 + 512)

__global__ void __launch_bounds__(256) stage_d_kernel()
{
    extern __shared__ __nv_bfloat16 sh[];
    __nv_bfloat16* sQh = sh;
    __nv_bfloat16* sQl = sh + 9216;
    __nv_bfloat16* sKh = sh + 18432;
    __nv_bfloat16* sKl = sh + 27648;
    __nv_bfloat16* sVh = sh + 36864;
    __nv_bfloat16* sVl = sh + 46080;
    __nv_bfloat16* sCh = sh + 55296;
    __nv_bfloat16* sCl = sh + 59904;
    __nv_bfloat16* sSh = sh + 64512;
    __nv_bfloat16* sSl = sh + 81920;
    float* dinv = (float*)(sh + 99328);

    const int c   = blockIdx.x;
    const int h   = blockIdx.y;
    const int b   = blockIdx.z;
    const int kvh = h >> 1;
    const int tid = threadIdx.x;
    const size_t t0 = (size_t)b*Sv + c*CHUNK;

    #pragma unroll
    for (int j = 0; j < 32; j++) {
        int e = tid + j*256;
        int t = e >> 6, f = e & 63;
        float q = g_qp[((t0 + t)*NHEAD + h)*NFEAT + f];
        float k = g_kp[((t0 + t)*NKVH + kvh)*NFEAT + f];
        float v = g_qkv[(t0 + t)*QKVD + 1536 + kvh*64 + f];
        __nv_bfloat16 qh = __float2bfloat16(q);
        __nv_bfloat16 kh = __float2bfloat16(k);
        __nv_bfloat16 vh = __float2bfloat16(v);
        sQh[t*SD_QP + f] = qh; sQl[t*SD_QP + f] = __float2bfloat16(q - __bfloat162float(qh));
        sKh[t*SD_QP + f] = kh; sKl[t*SD_QP + f] = __float2bfloat16(k - __bfloat162float(kh));
        sVh[t*SD_QP + f] = vh; sVl[t*SD_QP + f] = __float2bfloat16(v - __bfloat162float(vh));
    }
    #pragma unroll
    for (int j = 0; j < 16; j++) {
        int e = tid + j*256;
        int f = e >> 6, d = e & 63;
        float kv = g_kvc[(((size_t)(b*NKVH + kvh))*NCHUNK + c)*4096 + e];
        __nv_bfloat16 hh = __float2bfloat16(kv);
        sCh[f*SD_QP + d] = hh;
        sCl[f*SD_QP + d] = __float2bfloat16(kv - __bfloat162float(hh));
    }
    __syncthreads();

    if (tid < 128) {
        float s = 0.f;
        #pragma unroll
        for (int f = 0; f < 64; f++)
            s += __bfloat162float(sQh[tid*SD_QP + f]) + __bfloat162float(sQl[tid*SD_QP + f]);
        float z = g_z[((size_t)(b*NKVH + kvh))*Sv + c*CHUNK + tid];
        dinv[tid] = 1.0f / (s*z + 1e-6f);
    }
    __syncthreads();

    const int wid = tid >> 5, lane = tid & 31;
    const int l16 = lane & 15, g = lane >> 2, tg = lane & 3;
    const int mrow = wid * 16;
    const int ahalf = (lane >> 4) * 8;

    {
        float accS[16][4];
        #pragma unroll
        for (int nt = 0; nt < 16; nt++)
            #pragma unroll
            for (int r = 0; r < 4; r++) accS[nt][r] = 0.f;

        #pragma unroll
        for (int k16 = 0; k16 < 64; k16 += 16) {
            int ro = (mrow + l16)*SD_QP + k16 + ahalf;
            uint32_t ah0,ah1,ah2,ah3, al0,al1,al2,al3;
            ldsm_x4(ah0,ah1,ah2,ah3, smem_u32(sQh + ro));
            ldsm_x4(al0,al1,al2,al3, smem_u32(sQl + ro));
            #pragma unroll
            for (int nt = 0; nt < 16; nt++) {
                int bo = (nt*8 + (l16 & 7))*SD_QP + k16 + ((l16 >> 3) & 1)*8;
                uint32_t bh0,bh1,bl0,bl1;
                ldsm_x2(bh0,bh1, smem_u32(sKh + bo));
                ldsm_x2(bl0,bl1, smem_u32(sKl + bo));
                mma_bf16(accS[nt], ah0,ah1,ah2,ah3, bh0,bh1);
                mma_bf16(accS[nt], ah0,ah1,ah2,ah3, bl0,bl1);
                mma_bf16(accS[nt], al0,al1,al2,al3, bh0,bh1);
            }
        }
        #pragma unroll
        for (int nt = 0; nt < 16; nt++) {
            int r0 = mrow + g, r1 = r0 + 8;
            int c0 = nt*8 + tg*2;
            float v00 = (c0     <= r0) ? accS[nt][0] : 0.f;
            float v01 = (c0 + 1 <= r0) ? accS[nt][1] : 0.f;
            float v10 = (c0     <= r1) ? accS[nt][2] : 0.f;
            float v11 = (c0 + 1 <= r1) ? accS[nt][3] : 0.f;
            __nv_bfloat16 h00 = __float2bfloat16(v00), h01 = __float2bfloat16(v01);
            __nv_bfloat16 h10 = __float2bfloat16(v10), h11 = __float2bfloat16(v11);
            *(uint32_t*)&sSh[r0*SD_SP + c0] =
                (uint32_t)__bfloat16_as_ushort(h00) | ((uint32_t)__bfloat16_as_ushort(h01) << 16);
            *(uint32_t*)&sSh[r1*SD_SP + c0] =
                (uint32_t)__bfloat16_as_ushort(h10) | ((uint32_t)__bfloat16_as_ushort(h11) << 16);
            *(uint32_t*)&sSl[r0*SD_SP + c0] =
                pack2(v00 - __bfloat162float(h00), v01 - __bfloat162float(h01));
            *(uint32_t*)&sSl[r1*SD_SP + c0] =
                pack2(v10 - __bfloat162float(h10), v11 - __bfloat162float(h11));
        }
    }
    __syncwarp();

    {
        float acc2[8][4];
        #pragma unroll
        for (int nt = 0; nt < 8; nt++)
            #pragma unroll
            for (int r = 0; r < 4; r++) acc2[nt][r] = 0.f;

        #pragma unroll
        for (int k16 = 0; k16 < 128; k16 += 16) {
            int ro = (mrow + l16)*SD_SP + k16 + ahalf;
            uint32_t ah0,ah1,ah2,ah3, al0,al1,al2,al3;
            ldsm_x4(ah0,ah1,ah2,ah3, smem_u32(sSh + ro));
            ldsm_x4(al0,al1,al2,al3, smem_u32(sSl + ro));
            #pragma unroll
            for (int nt = 0; nt < 8; nt++) {
                int bo = (k16 + l16)*SD_QP + nt*8;
                uint32_t bh0,bh1,bl0,bl1;
                ldsm_x2_t(bh0,bh1, smem_u32(sVh + bo));
                ldsm_x2_t(bl0,bl1, smem_u32(sVl + bo));
                mma_bf16(acc2[nt], ah0,ah1,ah2,ah3, bh0,bh1);
                mma_bf16(acc2[nt], ah0,ah1,ah2,ah3, bl0,bl1);
                mma_bf16(acc2[nt], al0,al1,al2,al3, bh0,bh1);
            }
        }
        #pragma unroll
        for (int k16 = 0; k16 < 64; k16 += 16) {
            int ro = (mrow + l16)*SD_QP + k16 + ahalf;
            uint32_t ah0,ah1,ah2,ah3, al0,al1,al2,al3;
            ldsm_x4(ah0,ah1,ah2,ah3, smem_u32(sQh + ro));
            ldsm_x4(al0,al1,al2,al3, smem_u32(sQl + ro));
            #pragma unroll
            for (int nt = 0; nt < 8; nt++) {
                int bo = (k16 + l16)*SD_QP + nt*8;
                uint32_t bh0,bh1,bl0,bl1;
                ldsm_x2_t(bh0,bh1, smem_u32(sCh + bo));
                ldsm_x2_t(bl0,bl1, smem_u32(sCl + bo));
                mma_bf16(acc2[nt], ah0,ah1,ah2,ah3, bh0,bh1);
                mma_bf16(acc2[nt], ah0,ah1,ah2,ah3, bl0,bl1);
                mma_bf16(acc2[nt], al0,al1,al2,al3, bh0,bh1);
            }
        }

        const int r0 = mrow + g, r1 = r0 + 8;
        const float d0 = dinv[r0], d1 = dinv[r1];
        #pragma unroll
        for (int nt = 0; nt < 8; nt++) {
            int c0 = nt*8 + tg*2;
            float2 o0 = {acc2[nt][0]*d0, acc2[nt][1]*d0};
            float2 o1 = {acc2[nt][2]*d1, acc2[nt][3]*d1};
            *(float2*)&g_attn[(t0 + r0)*1024 + h*64 + c0] = o0;
            *(float2*)&g_attn[(t0 + r1)*1024 + h*64 + c0] = o1;
        }
    }
}

// ---------------- launch ------------------------------------------------------
extern "C" void kernel_launch(void* const* d_in, const int* in_sizes, int n_in,
                              void* d_out, int out_size)
{
    const float* hidden = (const float*)d_in[0];
    const float* cosg   = (const float*)d_in[1];
    const float* sing   = (const float*)d_in[2];
    const float* W_qkv  = (const float*)d_in[3];
    const float* W_o    = (const float*)d_in[4];
    const float* proj   = (const float*)d_in[5];
    float* out = (float*)d_out;

    static bool attr_done = false;
    if (!attr_done) {
        cudaFuncSetAttribute(chunkkv_kernel,
            cudaFuncAttributeMaxDynamicSharedMemorySize, 65536);
        cudaFuncSetAttribute(stage_d_kernel,
            cudaFuncAttributeMaxDynamicSharedMemorySize, SD_BYTES);
        cudaFuncSetAttribute(gemm_i8_kernel,
            cudaFuncAttributeMaxDynamicSharedMemorySize, GI_SMEM);
        attr_done = true;
    }

    float* qkv  = nullptr; cudaGetSymbolAddress((void**)&qkv,  g_qkv);
    float* attn = nullptr; cudaGetSymbolAddress((void**)&attn, g_attn);
    int8_t *a1, *a0, *w1a, *w1b, *w2a, *w2b;
    float *sa, *s1, *s2;
    cudaGetSymbolAddress((void**)&a1,  g_a1);
    cudaGetSymbolAddress((void**)&a0,  g_a0);
    cudaGetSymbolAddress((void**)&w1a, g_w1a);
    cudaGetSymbolAddress((void**)&w1b, g_w1b);
    cudaGetSymbolAddress((void**)&w2a, g_w2a);
    cudaGetSymbolAddress((void**)&w2b, g_w2b);
    cudaGetSymbolAddress((void**)&sa,  g_sa);
    cudaGetSymbolAddress((void**)&s1,  g_s1);
    cudaGetSymbolAddress((void**)&s2,  g_s2);

    // 1. quantize hidden + W_qkv, int8 QKV GEMM
    quant_rows_kernel<<<MROWS, 256>>>(hidden, a1, a0, sa);
    quant_rows_kernel<<<2048, 256>>>(W_qkv, w1a, w1b, s1);
    gemm_i8_kernel<<<dim3(QKVD/128, MROWS/128), 512, GI_SMEM>>>(
        a1, a0, w1a, w1b, sa, s1, qkv, QKVD, 1024);

    // 2. rope + feature projection
    ropeproj_kernel<<<(MROWS*24)/64, 128>>>(cosg, sing, proj);
    // 3. z: parallel rowsum then scan
    kpsum_kernel<<<(MROWS*NKVH)/256, 256>>>();
    zscan_kernel<<<Bv*NKVH, 256>>>();
    // 4. per-chunk KV
    chunkkv_kernel<<<dim3(NCHUNK, Bv*NKVH), 256, 65536>>>();
    // 5. exclusive chunk prefix
    kvprefix_kernel<<<Bv*NKVH, 256>>>();
    // 6. causal combine -> fp32 attn
    stage_d_kernel<<<dim3(NCHUNK, NHEAD, Bv), 256, SD_BYTES>>>();

    // 7. quantize attn + W_o, int8 output GEMM
    quant_rows_kernel<<<MROWS, 256>>>(attn, a1, a0, sa);
    quant_rows_kernel<<<1024, 256>>>(W_o, w2a, w2b, s2);
    gemm_i8_kernel<<<dim3(1024/128, MROWS/128), 512, GI_SMEM>>>(
        a1, a0, w2a, w2b, sa, s2, out, 1024, 1024);
}

// round 8
// speedup vs baseline: 1.7600x; 1.7600x over previous
#include <cuda_runtime.h>
#include <cuda_bf16.h>
#include <cuda_fp16.h>
#include <cstdint>

#define Bv      2
#define Sv      4096
#define QKVD    2048
#define NHEAD   16
#define NKVH    8
#define HDIM    64
#define NFEAT   64
#define CHUNK   128
#define NCHUNK  32
#define MROWS   (Bv*Sv)
#define LOSCALE 2048.0f
#define LOINV   (1.0f/2048.0f)

// ---------------- scratch (device globals; no allocs allowed) ----------------
__device__ float g_qkv [(size_t)MROWS*QKVD];
__device__ float g_qp  [(size_t)MROWS*NHEAD*NFEAT];
__device__ float g_kp  [(size_t)MROWS*NKVH*NFEAT];
__device__ float g_z   [(size_t)Bv*NKVH*Sv];
__device__ float g_kvc [(size_t)Bv*NKVH*NCHUNK*NFEAT*HDIM];

__device__ __half g_ahi [(size_t)MROWS*1024];
__device__ __half g_alo [(size_t)MROWS*1024];
__device__ __half g_w1hi[(size_t)2048*1024];
__device__ __half g_w1lo[(size_t)2048*1024];
__device__ __half g_w2hi[(size_t)1024*1024];
__device__ __half g_w2lo[(size_t)1024*1024];

// ---------------- PTX helpers -------------------------------------------------
__device__ __forceinline__ uint32_t smem_u32(const void* p) {
    uint32_t a;
    asm("{ .reg .u64 t; cvta.to.shared.u64 t, %1; cvt.u32.u64 %0, t; }" : "=r"(a) : "l"(p));
    return a;
}
__device__ __forceinline__ void ldsm_x4(uint32_t& r0, uint32_t& r1,
                                        uint32_t& r2, uint32_t& r3, uint32_t a) {
    asm volatile("ldmatrix.sync.aligned.m8n8.x4.shared.b16 {%0,%1,%2,%3}, [%4];"
                 : "=r"(r0), "=r"(r1), "=r"(r2), "=r"(r3) : "r"(a));
}
__device__ __forceinline__ void ldsm_x2(uint32_t& r0, uint32_t& r1, uint32_t a) {
    asm volatile("ldmatrix.sync.aligned.m8n8.x2.shared.b16 {%0,%1}, [%2];"
                 : "=r"(r0), "=r"(r1) : "r"(a));
}
__device__ __forceinline__ void ldsm_x2_t(uint32_t& r0, uint32_t& r1, uint32_t a) {
    asm volatile("ldmatrix.sync.aligned.m8n8.x2.trans.shared.b16 {%0,%1}, [%2];"
                 : "=r"(r0), "=r"(r1) : "r"(a));
}
// bf16 -> f32 accum (stage_d)
__device__ __forceinline__ void mma_bf16(float* d,
    uint32_t a0, uint32_t a1, uint32_t a2, uint32_t a3, uint32_t b0, uint32_t b1) {
    asm volatile(
        "mma.sync.aligned.m16n8k16.row.col.f32.bf16.bf16.f32 "
        "{%0,%1,%2,%3}, {%4,%5,%6,%7}, {%8,%9}, {%0,%1,%2,%3};"
        : "+f"(d[0]), "+f"(d[1]), "+f"(d[2]), "+f"(d[3])
        : "r"(a0), "r"(a1), "r"(a2), "r"(a3), "r"(b0), "r"(b1));
}
// f16 -> f32 accum (hi*hi pass)
__device__ __forceinline__ void mma_f16_f32(float* d,
    uint32_t a0, uint32_t a1, uint32_t a2, uint32_t a3, uint32_t b0, uint32_t b1) {
    asm volatile(
        "mma.sync.aligned.m16n8k16.row.col.f32.f16.f16.f32 "
        "{%0,%1,%2,%3}, {%4,%5,%6,%7}, {%8,%9}, {%0,%1,%2,%3};"
        : "+f"(d[0]), "+f"(d[1]), "+f"(d[2]), "+f"(d[3])
        : "r"(a0), "r"(a1), "r"(a2), "r"(a3), "r"(b0), "r"(b1));
}
// f16 -> f16 accum (cross passes; 2x rate if HW supports)
__device__ __forceinline__ void mma_f16_f16(uint32_t* c,
    uint32_t a0, uint32_t a1, uint32_t a2, uint32_t a3, uint32_t b0, uint32_t b1) {
    asm volatile(
        "mma.sync.aligned.m16n8k16.row.col.f16.f16.f16.f16 "
        "{%0,%1}, {%2,%3,%4,%5}, {%6,%7}, {%0,%1};"
        : "+r"(c[0]), "+r"(c[1])
        : "r"(a0), "r"(a1), "r"(a2), "r"(a3), "r"(b0), "r"(b1));
}
__device__ __forceinline__ uint32_t pack2(float x, float y) {
    __nv_bfloat16 bx = __float2bfloat16(x), by = __float2bfloat16(y);
    return (uint32_t)__bfloat16_as_ushort(bx) |
           ((uint32_t)__bfloat16_as_ushort(by) << 16);
}
__device__ __forceinline__ uint32_t pack2h(float x, float y) {
    __half hx = __float2half(x), hy = __float2half(y);
    return (uint32_t)__half_as_ushort(hx) |
           ((uint32_t)__half_as_ushort(hy) << 16);
}

// ---------------- fp32 -> fp16 hi/lo split (lo prescaled x2048) ---------------
__global__ void __launch_bounds__(256) cvt_split_kernel(
    const float* __restrict__ src,
    __half* __restrict__ hi, __half* __restrict__ lo, int n)
{
    int i = (blockIdx.x * 256 + threadIdx.x) * 4;
    if (i >= n) return;
    float4 v = *(const float4*)(src + i);
    __half h0 = __float2half(v.x);
    __half h1 = __float2half(v.y);
    __half h2 = __float2half(v.z);
    __half h3 = __float2half(v.w);
    __half l0 = __float2half((v.x - __half2float(h0)) * LOSCALE);
    __half l1 = __float2half((v.y - __half2float(h1)) * LOSCALE);
    __half l2 = __float2half((v.z - __half2float(h2)) * LOSCALE);
    __half l3 = __float2half((v.w - __half2float(h3)) * LOSCALE);
    __half2* hp = (__half2*)(hi + i);
    __half2* lp = (__half2*)(lo + i);
    hp[0] = __half2(h0, h1); hp[1] = __half2(h2, h3);
    lp[0] = __half2(l0, l1); lp[1] = __half2(l2, l3);
}

// ---------------- mma.sync GEMM: C[M,N] = A[M,K] * B[N,K]^T -------------------
// fp16 split: C = Ahi*Bhi (f32 accum) + (Ahi*Blo' + Alo'*Bhi) (f16 accum) /2048
#define GM_PAD  40
#define GM_BUF  (128*GM_PAD)
#define GM_SMEM (2*4*GM_BUF*2)

__global__ void __launch_bounds__(256) gemm_mma_kernel(
    const __half* __restrict__ Ahi, const __half* __restrict__ Alo,
    const __half* __restrict__ Bhi, const __half* __restrict__ Blo,
    float* __restrict__ C, int N, int K)
{
    extern __shared__ __half smh[];
    const int tid = threadIdx.x;
    const int m0 = blockIdx.y * 128, n0 = blockIdx.x * 128;
    const int row = tid >> 1, off = (tid & 1) * 16;

    const __half* gp0 = Ahi + (size_t)(m0 + row) * K + off;
    const __half* gp1 = Alo + (size_t)(m0 + row) * K + off;
    const __half* gp2 = Bhi + (size_t)(n0 + row) * K + off;
    const __half* gp3 = Blo + (size_t)(n0 + row) * K + off;

    const int wid = tid >> 5, lane = tid & 31;
    const int wm = wid >> 2, wn = wid & 3;
    const int l16 = lane & 15;

    float acc[4][4][4];
    uint32_t accx[4][4][2];
    #pragma unroll
    for (int mi = 0; mi < 4; mi++)
        #pragma unroll
        for (int ni = 0; ni < 4; ni++) {
            #pragma unroll
            for (int r = 0; r < 4; r++) acc[mi][ni][r] = 0.f;
            accx[mi][ni][0] = 0u; accx[mi][ni][1] = 0u;
        }

    const int sto = row * GM_PAD + off;
    uint4 ld[4][2];

    ld[0][0] = *(const uint4*)gp0;       ld[0][1] = *(const uint4*)(gp0 + 8);
    ld[1][0] = *(const uint4*)gp1;       ld[1][1] = *(const uint4*)(gp1 + 8);
    ld[2][0] = *(const uint4*)gp2;       ld[2][1] = *(const uint4*)(gp2 + 8);
    ld[3][0] = *(const uint4*)gp3;       ld[3][1] = *(const uint4*)(gp3 + 8);
    #pragma unroll
    for (int arr = 0; arr < 4; arr++) {
        *(uint4*)&smh[arr*GM_BUF + sto]     = ld[arr][0];
        *(uint4*)&smh[arr*GM_BUF + sto + 8] = ld[arr][1];
    }
    __syncthreads();

    const int NKT = K >> 5;
    for (int kt = 0; kt < NKT; kt++) {
        const int b = kt & 1;
        if (kt + 1 < NKT) {
            const int kb = (kt + 1) << 5;
            ld[0][0] = *(const uint4*)(gp0 + kb); ld[0][1] = *(const uint4*)(gp0 + kb + 8);
            ld[1][0] = *(const uint4*)(gp1 + kb); ld[1][1] = *(const uint4*)(gp1 + kb + 8);
            ld[2][0] = *(const uint4*)(gp2 + kb); ld[2][1] = *(const uint4*)(gp2 + kb + 8);
            ld[3][0] = *(const uint4*)(gp3 + kb); ld[3][1] = *(const uint4*)(gp3 + kb + 8);
        }

        const __half* sAh = smh + b*(4*GM_BUF);
        const __half* sAl = sAh + GM_BUF;
        const __half* sBh = sAl + GM_BUF;
        const __half* sBl = sBh + GM_BUF;

        #pragma unroll
        for (int k16 = 0; k16 < 32; k16 += 16) {
            uint32_t ah[4][4], al[4][4];
            #pragma unroll
            for (int mi = 0; mi < 4; mi++) {
                int roff = (wm*64 + mi*16 + l16) * GM_PAD + k16 + (lane >> 4) * 8;
                ldsm_x4(ah[mi][0], ah[mi][1], ah[mi][2], ah[mi][3], smem_u32(sAh + roff));
                ldsm_x4(al[mi][0], al[mi][1], al[mi][2], al[mi][3], smem_u32(sAl + roff));
            }
            #pragma unroll
            for (int ni = 0; ni < 4; ni++) {
                int boff = (wn*32 + ni*8 + (l16 & 7)) * GM_PAD + k16 + ((l16 >> 3) & 1) * 8;
                uint32_t bh0, bh1, bl0, bl1;
                ldsm_x2(bh0, bh1, smem_u32(sBh + boff));
                ldsm_x2(bl0, bl1, smem_u32(sBl + boff));
                #pragma unroll
                for (int mi = 0; mi < 4; mi++) {
                    mma_f16_f32(acc[mi][ni], ah[mi][0], ah[mi][1], ah[mi][2], ah[mi][3], bh0, bh1);
                    mma_f16_f16(accx[mi][ni], ah[mi][0], ah[mi][1], ah[mi][2], ah[mi][3], bl0, bl1);
                    mma_f16_f16(accx[mi][ni], al[mi][0], al[mi][1], al[mi][2], al[mi][3], bh0, bh1);
                }
            }
        }

        if (kt + 1 < NKT) {
            __half* dst = smh + (b ^ 1)*(4*GM_BUF);
            #pragma unroll
            for (int arr = 0; arr < 4; arr++) {
                *(uint4*)&dst[arr*GM_BUF + sto]     = ld[arr][0];
                *(uint4*)&dst[arr*GM_BUF + sto + 8] = ld[arr][1];
            }
        }
        __syncthreads();
    }

    const int g = lane >> 2, tg = lane & 3;
    #pragma unroll
    for (int mi = 0; mi < 4; mi++) {
        #pragma unroll
        for (int ni = 0; ni < 4; ni++) {
            int r0 = m0 + wm*64 + mi*16 + g;
            int c0 = n0 + wn*32 + ni*8 + tg*2;
            __half2 x0 = *(__half2*)&accx[mi][ni][0];
            __half2 x1 = *(__half2*)&accx[mi][ni][1];
            float2 lo = {fmaf(__half2float(x0.x), LOINV, acc[mi][ni][0]),
                         fmaf(__half2float(x0.y), LOINV, acc[mi][ni][1])};
            float2 hi = {fmaf(__half2float(x1.x), LOINV, acc[mi][ni][2]),
                         fmaf(__half2float(x1.y), LOINV, acc[mi][ni][3])};
            *(float2*)&C[(size_t)r0 * N + c0]       = lo;
            *(float2*)&C[(size_t)(r0 + 8) * N + c0] = hi;
        }
    }
}

// ---------------- RoPE + relu feature projection + fused kp rowsum -----------
__global__ void __launch_bounds__(128) ropeproj_kernel(
    const float* __restrict__ cosg, const float* __restrict__ sing,
    const float* __restrict__ proj)
{
    __shared__ float dat[64*68];   // [d][r]
    __shared__ float pj [64*68];   // [d][f]
    const int tid = threadIdx.x;
    const int rbase = blockIdx.x * 64;

    #pragma unroll
    for (int j = 0; j < 32; j++) {
        int i = tid + j*128;
        int f = i >> 6, d = i & 63;
        pj[d*68 + f] = proj[i];
    }
    #pragma unroll
    for (int j = 0; j < 32; j++) {
        int e = tid + j*128;
        int r = e >> 6, d = e & 63;
        int rho = rbase + r;
        int bs  = rho / 24;
        int h   = rho - bs*24;
        int s   = bs & (Sv-1);
        size_t base = (size_t)bs*QKVD + h*64;
        float val  = g_qkv[base + d];
        int   pd   = (d < 32) ? d + 32 : d - 32;
        float part = g_qkv[base + pd];
        float rot  = (d < 32) ? -part : part;
        dat[d*68 + r] = fmaf(val, cosg[s*64 + d], rot * sing[s*64 + d]);
    }
    __syncthreads();

    const int rq = tid >> 4, fq = tid & 15;
    float acc[8][4];
    #pragma unroll
    for (int i = 0; i < 8; i++)
        #pragma unroll
        for (int j = 0; j < 4; j++) acc[i][j] = 0.f;

    #pragma unroll
    for (int k = 0; k < 64; k++) {
        float4 a0 = *(const float4*)&dat[k*68 + rq*8];
        float4 a1 = *(const float4*)&dat[k*68 + rq*8 + 4];
        float4 bv = *(const float4*)&pj [k*68 + fq*4];
        float av[8] = {a0.x,a0.y,a0.z,a0.w,a1.x,a1.y,a1.z,a1.w};
        #pragma unroll
        for (int i = 0; i < 8; i++) {
            acc[i][0] = fmaf(av[i], bv.x, acc[i][0]);
            acc[i][1] = fmaf(av[i], bv.y, acc[i][1]);
            acc[i][2] = fmaf(av[i], bv.z, acc[i][2]);
            acc[i][3] = fmaf(av[i], bv.w, acc[i][3]);
        }
    }

    const float ratio = (float)(0.125 * (0.125 + 1e-4));
    #pragma unroll
    for (int i = 0; i < 8; i++) {
        int rho = rbase + rq*8 + i;
        int bs  = rho / 24;
        int h   = rho - bs*24;
        float4 o;
        o.x = fmaxf(acc[i][0]*ratio, 0.f);
        o.y = fmaxf(acc[i][1]*ratio, 0.f);
        o.z = fmaxf(acc[i][2]*ratio, 0.f);
        o.w = fmaxf(acc[i][3]*ratio, 0.f);

        // fused rowsum across the 16-lane fq group (uniform row per group)
        float rs = (o.x + o.y) + (o.z + o.w);
        #pragma unroll
        for (int ofs = 1; ofs < 16; ofs <<= 1)
            rs += __shfl_xor_sync(0xffffffffu, rs, ofs);

        if (h < NHEAD) {
            o.x += 1e-4f; o.y += 1e-4f; o.z += 1e-4f; o.w += 1e-4f;
            *(float4*)&g_qp[((size_t)bs*NHEAD + h)*NFEAT + fq*4] = o;
        } else {
            int kvh = h - NHEAD;
            int b = bs >> 12, t = bs & 4095;
            if (fq == 0) g_z[((size_t)(b*NKVH + kvh))*Sv + t] = rs;
            *(float4*)&g_kp[((size_t)bs*NKVH + kvh)*NFEAT + fq*4] = o;
        }
    }
}

// ---------------- inclusive scan of g_z per (b,kvh), in place -----------------
__global__ void __launch_bounds__(256) zscan_kernel()
{
    const int bkv = blockIdx.x;
    const int tid = threadIdx.x;
    const int lane = tid & 31, warp = tid >> 5;
    __shared__ float wsum[8];
    float carry = 0.f;

    for (int tile = 0; tile < 16; tile++) {
        int t = tile*256 + tid;
        float x = g_z[(size_t)bkv*Sv + t];
        #pragma unroll
        for (int o = 1; o < 32; o <<= 1) {
            float n = __shfl_up_sync(0xffffffffu, x, o);
            if (lane >= o) x += n;
        }
        if (lane == 31) wsum[warp] = x;
        __syncthreads();
        float off = carry;
        for (int w2 = 0; w2 < warp; w2++) off += wsum[w2];
        g_z[(size_t)bkv*Sv + t] = off + x;
        float tot = 0.f;
        #pragma unroll
        for (int w2 = 0; w2 < 8; w2++) tot += wsum[w2];
        carry += tot;
        __syncthreads();
    }
}

// ---------------- per-chunk KV = Kp^T V (64x64) ------------------------------
__global__ void __launch_bounds__(256) chunkkv_kernel()
{
    extern __shared__ float cs[];
    float* Ks = cs;
    float* Vs = cs + 8192;
    const int c   = blockIdx.x;
    const int bkv = blockIdx.y;
    const int b   = bkv >> 3, kvh = bkv & 7;
    const int tid = threadIdx.x;

    #pragma unroll
    for (int j = 0; j < 32; j++) {
        int e = tid + j*256;
        int t = e >> 6, f = e & 63;
        size_t bs = (size_t)(b*Sv + c*CHUNK + t);
        Ks[e] = g_kp[(bs*NKVH + kvh)*NFEAT + f];
        Vs[e] = g_qkv[bs*QKVD + 1536 + kvh*64 + f];
    }
    __syncthreads();

    const int fq = tid >> 4, dq = tid & 15;
    float acc[4][4];
    #pragma unroll
    for (int i = 0; i < 4; i++)
        #pragma unroll
        for (int j = 0; j < 4; j++) acc[i][j] = 0.f;

    #pragma unroll 8
    for (int t = 0; t < 128; t++) {
        float4 a = *(const float4*)&Ks[t*64 + fq*4];
        float4 v = *(const float4*)&Vs[t*64 + dq*4];
        float av[4] = {a.x,a.y,a.z,a.w};
        #pragma unroll
        for (int i = 0; i < 4; i++) {
            acc[i][0] = fmaf(av[i], v.x, acc[i][0]);
            acc[i][1] = fmaf(av[i], v.y, acc[i][1]);
            acc[i][2] = fmaf(av[i], v.z, acc[i][2]);
            acc[i][3] = fmaf(av[i], v.w, acc[i][3]);
        }
    }
    size_t base = ((size_t)bkv*NCHUNK + c)*4096;
    #pragma unroll
    for (int i = 0; i < 4; i++) {
        float4 o = {acc[i][0], acc[i][1], acc[i][2], acc[i][3]};
        *(float4*)&g_kvc[base + (size_t)(fq*4 + i)*64 + dq*4] = o;
    }
}

// ---------------- exclusive chunk-prefix of KV, in place ---------------------
__global__ void __launch_bounds__(256) kvprefix_kernel()
{
    const int bkv = blockIdx.x;
    const int tid = threadIdx.x;
    float acc[16];
    #pragma unroll
    for (int j = 0; j < 16; j++) acc[j] = 0.f;
    for (int c = 0; c < NCHUNK; c++) {
        size_t base = ((size_t)bkv*NCHUNK + c)*4096;
        #pragma unroll
        for (int j = 0; j < 16; j++) {
            size_t idx = base + tid + j*256;
            float cur = g_kvc[idx];
            g_kvc[idx] = acc[j];
            acc[j] += cur;
        }
    }
}

// ---------------- stage D: mma.sync split-bf16 causal combine ----------------
#define SD_QP  72
#define SD_SP  136
#define SD_BYTES (99328*2 + 512)

__global__ void __launch_bounds__(256) stage_d_kernel()
{
    extern __shared__ __nv_bfloat16 sh[];
    __nv_bfloat16* sQh = sh;
    __nv_bfloat16* sQl = sh + 9216;
    __nv_bfloat16* sKh = sh + 18432;
    __nv_bfloat16* sKl = sh + 27648;
    __nv_bfloat16* sVh = sh + 36864;
    __nv_bfloat16* sVl = sh + 46080;
    __nv_bfloat16* sCh = sh + 55296;
    __nv_bfloat16* sCl = sh + 59904;
    __nv_bfloat16* sSh = sh + 64512;
    __nv_bfloat16* sSl = sh + 81920;
    float* dinv = (float*)(sh + 99328);

    const int c   = blockIdx.x;
    const int h   = blockIdx.y;
    const int b   = blockIdx.z;
    const int kvh = h >> 1;
    const int tid = threadIdx.x;
    const size_t t0 = (size_t)b*Sv + c*CHUNK;

    #pragma unroll
    for (int j = 0; j < 32; j++) {
        int e = tid + j*256;
        int t = e >> 6, f = e & 63;
        float q = g_qp[((t0 + t)*NHEAD + h)*NFEAT + f];
        float k = g_kp[((t0 + t)*NKVH + kvh)*NFEAT + f];
        float v = g_qkv[(t0 + t)*QKVD + 1536 + kvh*64 + f];
        __nv_bfloat16 qh = __float2bfloat16(q);
        __nv_bfloat16 kh = __float2bfloat16(k);
        __nv_bfloat16 vh = __float2bfloat16(v);
        sQh[t*SD_QP + f] = qh; sQl[t*SD_QP + f] = __float2bfloat16(q - __bfloat162float(qh));
        sKh[t*SD_QP + f] = kh; sKl[t*SD_QP + f] = __float2bfloat16(k - __bfloat162float(kh));
        sVh[t*SD_QP + f] = vh; sVl[t*SD_QP + f] = __float2bfloat16(v - __bfloat162float(vh));
    }
    #pragma unroll
    for (int j = 0; j < 16; j++) {
        int e = tid + j*256;
        int f = e >> 6, d = e & 63;
        float kv = g_kvc[(((size_t)(b*NKVH + kvh))*NCHUNK + c)*4096 + e];
        __nv_bfloat16 hh = __float2bfloat16(kv);
        sCh[f*SD_QP + d] = hh;
        sCl[f*SD_QP + d] = __float2bfloat16(kv - __bfloat162float(hh));
    }
    __syncthreads();

    if (tid < 128) {
        float s = 0.f;
        #pragma unroll
        for (int f = 0; f < 64; f++)
            s += __bfloat162float(sQh[tid*SD_QP + f]) + __bfloat162float(sQl[tid*SD_QP + f]);
        float z = g_z[((size_t)(b*NKVH + kvh))*Sv + c*CHUNK + tid];
        dinv[tid] = 1.0f / (s*z + 1e-6f);
    }
    __syncthreads();

    const int wid = tid >> 5, lane = tid & 31;
    const int l16 = lane & 15, g = lane >> 2, tg = lane & 3;
    const int mrow = wid * 16;
    const int ahalf = (lane >> 4) * 8;

    {
        float accS[16][4];
        #pragma unroll
        for (int nt = 0; nt < 16; nt++)
            #pragma unroll
            for (int r = 0; r < 4; r++) accS[nt][r] = 0.f;

        #pragma unroll
        for (int k16 = 0; k16 < 64; k16 += 16) {
            int ro = (mrow + l16)*SD_QP + k16 + ahalf;
            uint32_t ah0,ah1,ah2,ah3, al0,al1,al2,al3;
            ldsm_x4(ah0,ah1,ah2,ah3, smem_u32(sQh + ro));
            ldsm_x4(al0,al1,al2,al3, smem_u32(sQl + ro));
            #pragma unroll
            for (int nt = 0; nt < 16; nt++) {
                int bo = (nt*8 + (l16 & 7))*SD_QP + k16 + ((l16 >> 3) & 1)*8;
                uint32_t bh0,bh1,bl0,bl1;
                ldsm_x2(bh0,bh1, smem_u32(sKh + bo));
                ldsm_x2(bl0,bl1, smem_u32(sKl + bo));
                mma_bf16(accS[nt], ah0,ah1,ah2,ah3, bh0,bh1);
                mma_bf16(accS[nt], ah0,ah1,ah2,ah3, bl0,bl1);
                mma_bf16(accS[nt], al0,al1,al2,al3, bh0,bh1);
            }
        }
        #pragma unroll
        for (int nt = 0; nt < 16; nt++) {
            int r0 = mrow + g, r1 = r0 + 8;
            int c0 = nt*8 + tg*2;
            float v00 = (c0     <= r0) ? accS[nt][0] : 0.f;
            float v01 = (c0 + 1 <= r0) ? accS[nt][1] : 0.f;
            float v10 = (c0     <= r1) ? accS[nt][2] : 0.f;
            float v11 = (c0 + 1 <= r1) ? accS[nt][3] : 0.f;
            __nv_bfloat16 h00 = __float2bfloat16(v00), h01 = __float2bfloat16(v01);
            __nv_bfloat16 h10 = __float2bfloat16(v10), h11 = __float2bfloat16(v11);
            *(uint32_t*)&sSh[r0*SD_SP + c0] =
                (uint32_t)__bfloat16_as_ushort(h00) | ((uint32_t)__bfloat16_as_ushort(h01) << 16);
            *(uint32_t*)&sSh[r1*SD_SP + c0] =
                (uint32_t)__bfloat16_as_ushort(h10) | ((uint32_t)__bfloat16_as_ushort(h11) << 16);
            *(uint32_t*)&sSl[r0*SD_SP + c0] =
                pack2(v00 - __bfloat162float(h00), v01 - __bfloat162float(h01));
            *(uint32_t*)&sSl[r1*SD_SP + c0] =
                pack2(v10 - __bfloat162float(h10), v11 - __bfloat162float(h11));
        }
    }
    __syncwarp();

    {
        float acc2[8][4];
        #pragma unroll
        for (int nt = 0; nt < 8; nt++)
            #pragma unroll
            for (int r = 0; r < 4; r++) acc2[nt][r] = 0.f;

        #pragma unroll
        for (int k16 = 0; k16 < 128; k16 += 16) {
            int ro = (mrow + l16)*SD_SP + k16 + ahalf;
            uint32_t ah0,ah1,ah2,ah3, al0,al1,al2,al3;
            ldsm_x4(ah0,ah1,ah2,ah3, smem_u32(sSh + ro));
            ldsm_x4(al0,al1,al2,al3, smem_u32(sSl + ro));
            #pragma unroll
            for (int nt = 0; nt < 8; nt++) {
                int bo = (k16 + l16)*SD_QP + nt*8;
                uint32_t bh0,bh1,bl0,bl1;
                ldsm_x2_t(bh0,bh1, smem_u32(sVh + bo));
                ldsm_x2_t(bl0,bl1, smem_u32(sVl + bo));
                mma_bf16(acc2[nt], ah0,ah1,ah2,ah3, bh0,bh1);
                mma_bf16(acc2[nt], ah0,ah1,ah2,ah3, bl0,bl1);
                mma_bf16(acc2[nt], al0,al1,al2,al3, bh0,bh1);
            }
        }
        #pragma unroll
        for (int k16 = 0; k16 < 64; k16 += 16) {
            int ro = (mrow + l16)*SD_QP + k16 + ahalf;
            uint32_t ah0,ah1,ah2,ah3, al0,al1,al2,al3;
            ldsm_x4(ah0,ah1,ah2,ah3, smem_u32(sQh + ro));
            ldsm_x4(al0,al1,al2,al3, smem_u32(sQl + ro));
            #pragma unroll
            for (int nt = 0; nt < 8; nt++) {
                int bo = (k16 + l16)*SD_QP + nt*8;
                uint32_t bh0,bh1,bl0,bl1;
                ldsm_x2_t(bh0,bh1, smem_u32(sCh + bo));
                ldsm_x2_t(bl0,bl1, smem_u32(sCl + bo));
                mma_bf16(acc2[nt], ah0,ah1,ah2,ah3, bh0,bh1);
                mma_bf16(acc2[nt], ah0,ah1,ah2,ah3, bl0,bl1);
                mma_bf16(acc2[nt], al0,al1,al2,al3, bh0,bh1);
            }
        }

        const int r0 = mrow + g, r1 = r0 + 8;
        const float d0 = dinv[r0], d1 = dinv[r1];
        #pragma unroll
        for (int nt = 0; nt < 8; nt++) {
            int c0 = nt*8 + tg*2;
            float o00 = acc2[nt][0]*d0, o01 = acc2[nt][1]*d0;
            float o10 = acc2[nt][2]*d1, o11 = acc2[nt][3]*d1;
            size_t a0 = (t0 + r0)*1024 + h*64 + c0;
            size_t a1 = (t0 + r1)*1024 + h*64 + c0;
            __half h00 = __float2half(o00), h01 = __float2half(o01);
            __half h10 = __float2half(o10), h11 = __float2half(o11);
            *(uint32_t*)&g_ahi[a0] =
                (uint32_t)__half_as_ushort(h00) | ((uint32_t)__half_as_ushort(h01) << 16);
            *(uint32_t*)&g_ahi[a1] =
                (uint32_t)__half_as_ushort(h10) | ((uint32_t)__half_as_ushort(h11) << 16);
            *(uint32_t*)&g_alo[a0] =
                pack2h((o00 - __half2float(h00))*LOSCALE, (o01 - __half2float(h01))*LOSCALE);
            *(uint32_t*)&g_alo[a1] =
                pack2h((o10 - __half2float(h10))*LOSCALE, (o11 - __half2float(h11))*LOSCALE);
        }
    }
}

// ---------------- launch ------------------------------------------------------
extern "C" void kernel_launch(void* const* d_in, const int* in_sizes, int n_in,
                              void* d_out, int out_size)
{
    const float* hidden = (const float*)d_in[0];
    const float* cosg   = (const float*)d_in[1];
    const float* sing   = (const float*)d_in[2];
    const float* W_qkv  = (const float*)d_in[3];
    const float* W_o    = (const float*)d_in[4];
    const float* proj   = (const float*)d_in[5];
    float* out = (float*)d_out;

    static bool attr_done = false;
    if (!attr_done) {
        cudaFuncSetAttribute(chunkkv_kernel,
            cudaFuncAttributeMaxDynamicSharedMemorySize, 65536);
        cudaFuncSetAttribute(stage_d_kernel,
            cudaFuncAttributeMaxDynamicSharedMemorySize, SD_BYTES);
        cudaFuncSetAttribute(gemm_mma_kernel,
            cudaFuncAttributeMaxDynamicSharedMemorySize, GM_SMEM);
        attr_done = true;
    }

    float* qkv = nullptr; cudaGetSymbolAddress((void**)&qkv, g_qkv);
    __half *ahi, *alo, *w1hi, *w1lo, *w2hi, *w2lo;
    cudaGetSymbolAddress((void**)&ahi,  g_ahi);
    cudaGetSymbolAddress((void**)&alo,  g_alo);
    cudaGetSymbolAddress((void**)&w1hi, g_w1hi);
    cudaGetSymbolAddress((void**)&w1lo, g_w1lo);
    cudaGetSymbolAddress((void**)&w2hi, g_w2hi);
    cudaGetSymbolAddress((void**)&w2lo, g_w2lo);

    // 1. split-convert hidden + W_qkv, fp16 split QKV GEMM
    cvt_split_kernel<<<(MROWS*1024)/1024, 256>>>(hidden, ahi, alo, MROWS*1024);
    cvt_split_kernel<<<(2048*1024)/1024, 256>>>(W_qkv, w1hi, w1lo, 2048*1024);
    gemm_mma_kernel<<<dim3(QKVD/128, MROWS/128), 256, GM_SMEM>>>(
        ahi, alo, w1hi, w1lo, qkv, QKVD, 1024);

    // 2. rope + feature projection (+ fused kp rowsums into g_z)
    ropeproj_kernel<<<(MROWS*24)/64, 128>>>(cosg, sing, proj);
    // 3. z scan (in place over fused rowsums)
    zscan_kernel<<<Bv*NKVH, 256>>>();
    // 4. per-chunk KV
    chunkkv_kernel<<<dim3(NCHUNK, Bv*NKVH), 256, 65536>>>();
    // 5. exclusive chunk prefix
    kvprefix_kernel<<<Bv*NKVH, 256>>>();
    // 6. causal combine -> writes fp16 hi/lo attn directly
    stage_d_kernel<<<dim3(NCHUNK, NHEAD, Bv), 256, SD_BYTES>>>();

    // 7. split-convert W_o, fp16 split output GEMM
    cvt_split_kernel<<<(1024*1024)/1024, 256>>>(W_o, w2hi, w2lo, 1024*1024);
    gemm_mma_kernel<<<dim3(1024/128, MROWS/128), 256, GM_SMEM>>>(
        ahi, alo, w2hi, w2lo, out, 1024, 1024);
}

// round 10
// speedup vs baseline: 2.1836x; 1.2407x over previous
#include <cuda_runtime.h>
#include <cuda_bf16.h>
#include <cuda_fp16.h>
#include <cstdint>

#define Bv      2
#define Sv      4096
#define QKVD    2048
#define NHEAD   16
#define NKVH    8
#define HDIM    64
#define NFEAT   64
#define CHUNK   128
#define NCHUNK  32
#define MROWS   (Bv*Sv)
#define LOSCALE 2048.0f
#define LOINV   (1.0f/2048.0f)

// ---------------- scratch (device globals; no allocs allowed) ----------------
__device__ float g_qkv [(size_t)MROWS*QKVD];
__device__ float g_qp  [(size_t)MROWS*NHEAD*NFEAT];
__device__ float g_kp  [(size_t)MROWS*NKVH*NFEAT];
__device__ float g_z   [(size_t)Bv*NKVH*Sv];
__device__ float g_kvc [(size_t)Bv*NKVH*NCHUNK*NFEAT*HDIM];

__device__ __half g_ah  [(size_t)MROWS*1024];     // activations, single fp16
__device__ __half g_w1hi[(size_t)2048*1024];
__device__ __half g_w1lo[(size_t)2048*1024];
__device__ __half g_w2hi[(size_t)1024*1024];
__device__ __half g_w2lo[(size_t)1024*1024];

// ---------------- PTX helpers -------------------------------------------------
__device__ __forceinline__ uint32_t smem_u32(const void* p) {
    uint32_t a;
    asm("{ .reg .u64 t; cvta.to.shared.u64 t, %1; cvt.u32.u64 %0, t; }" : "=r"(a) : "l"(p));
    return a;
}
__device__ __forceinline__ void ldsm_x4(uint32_t& r0, uint32_t& r1,
                                        uint32_t& r2, uint32_t& r3, uint32_t a) {
    asm volatile("ldmatrix.sync.aligned.m8n8.x4.shared.b16 {%0,%1,%2,%3}, [%4];"
                 : "=r"(r0), "=r"(r1), "=r"(r2), "=r"(r3) : "r"(a));
}
__device__ __forceinline__ void ldsm_x2(uint32_t& r0, uint32_t& r1, uint32_t a) {
    asm volatile("ldmatrix.sync.aligned.m8n8.x2.shared.b16 {%0,%1}, [%2];"
                 : "=r"(r0), "=r"(r1) : "r"(a));
}
__device__ __forceinline__ void ldsm_x2_t(uint32_t& r0, uint32_t& r1, uint32_t a) {
    asm volatile("ldmatrix.sync.aligned.m8n8.x2.trans.shared.b16 {%0,%1}, [%2];"
                 : "=r"(r0), "=r"(r1) : "r"(a));
}
__device__ __forceinline__ void mma_bf16(float* d,
    uint32_t a0, uint32_t a1, uint32_t a2, uint32_t a3, uint32_t b0, uint32_t b1) {
    asm volatile(
        "mma.sync.aligned.m16n8k16.row.col.f32.bf16.bf16.f32 "
        "{%0,%1,%2,%3}, {%4,%5,%6,%7}, {%8,%9}, {%0,%1,%2,%3};"
        : "+f"(d[0]), "+f"(d[1]), "+f"(d[2]), "+f"(d[3])
        : "r"(a0), "r"(a1), "r"(a2), "r"(a3), "r"(b0), "r"(b1));
}
__device__ __forceinline__ void mma_f16_f32(float* d,
    uint32_t a0, uint32_t a1, uint32_t a2, uint32_t a3, uint32_t b0, uint32_t b1) {
    asm volatile(
        "mma.sync.aligned.m16n8k16.row.col.f32.f16.f16.f32 "
        "{%0,%1,%2,%3}, {%4,%5,%6,%7}, {%8,%9}, {%0,%1,%2,%3};"
        : "+f"(d[0]), "+f"(d[1]), "+f"(d[2]), "+f"(d[3])
        : "r"(a0), "r"(a1), "r"(a2), "r"(a3), "r"(b0), "r"(b1));
}
__device__ __forceinline__ uint32_t pack2(float x, float y) {
    __nv_bfloat16 bx = __float2bfloat16(x), by = __float2bfloat16(y);
    return (uint32_t)__bfloat16_as_ushort(bx) |
           ((uint32_t)__bfloat16_as_ushort(by) << 16);
}
__device__ __forceinline__ uint32_t pack2h(float x, float y) {
    __half hx = __float2half(x), hy = __float2half(y);
    return (uint32_t)__half_as_ushort(hx) |
           ((uint32_t)__half_as_ushort(hy) << 16);
}

// ---------------- fp32 -> fp16 single convert ---------------------------------
__global__ void __launch_bounds__(256) cvt_h_kernel(
    const float* __restrict__ src, __half* __restrict__ dst, int n)
{
    int i = (blockIdx.x * 256 + threadIdx.x) * 4;
    if (i >= n) return;
    float4 v = *(const float4*)(src + i);
    __half2* dp = (__half2*)(dst + i);
    dp[0] = __half2(__float2half(v.x), __float2half(v.y));
    dp[1] = __half2(__float2half(v.z), __float2half(v.w));
}

// ---------------- fp32 -> fp16 hi/lo split (lo prescaled x2048) ---------------
__global__ void __launch_bounds__(256) cvt_split_kernel(
    const float* __restrict__ src,
    __half* __restrict__ hi, __half* __restrict__ lo, int n)
{
    int i = (blockIdx.x * 256 + threadIdx.x) * 4;
    if (i >= n) return;
    float4 v = *(const float4*)(src + i);
    __half h0 = __float2half(v.x);
    __half h1 = __float2half(v.y);
    __half h2 = __float2half(v.z);
    __half h3 = __float2half(v.w);
    __half l0 = __float2half((v.x - __half2float(h0)) * LOSCALE);
    __half l1 = __float2half((v.y - __half2float(h1)) * LOSCALE);
    __half l2 = __float2half((v.z - __half2float(h2)) * LOSCALE);
    __half l3 = __float2half((v.w - __half2float(h3)) * LOSCALE);
    __half2* hp = (__half2*)(hi + i);
    __half2* lp = (__half2*)(lo + i);
    hp[0] = __half2(h0, h1); hp[1] = __half2(h2, h3);
    lp[0] = __half2(l0, l1); lp[1] = __half2(l2, l3);
}

// ---------------- mma.sync GEMM: C[M,N] = A[M,K] * B[N,K]^T -------------------
// 2-pass fp16 split: C = A*Bhi + (A*Blo')/2048, both f32 accumulated.
#define GM_PAD  40
#define GM_BUF  (128*GM_PAD)
#define GM_SMEM (2*3*GM_BUF*2)

__global__ void __launch_bounds__(256) gemm_mma_kernel(
    const __half* __restrict__ A,
    const __half* __restrict__ Bhi, const __half* __restrict__ Blo,
    float* __restrict__ C, int N, int K)
{
    extern __shared__ __half smh[];
    const int tid = threadIdx.x;
    const int m0 = blockIdx.y * 128, n0 = blockIdx.x * 128;
    const int row = tid >> 1, off = (tid & 1) * 16;

    const __half* gp0 = A   + (size_t)(m0 + row) * K + off;
    const __half* gp1 = Bhi + (size_t)(n0 + row) * K + off;
    const __half* gp2 = Blo + (size_t)(n0 + row) * K + off;

    const int wid = tid >> 5, lane = tid & 31;
    const int wm = wid >> 2, wn = wid & 3;
    const int l16 = lane & 15;

    float acc[4][4][4], accL[4][4][4];
    #pragma unroll
    for (int mi = 0; mi < 4; mi++)
        #pragma unroll
        for (int ni = 0; ni < 4; ni++)
            #pragma unroll
            for (int r = 0; r < 4; r++) { acc[mi][ni][r] = 0.f; accL[mi][ni][r] = 0.f; }

    const int sto = row * GM_PAD + off;
    uint4 ld[3][2];

    ld[0][0] = *(const uint4*)gp0;       ld[0][1] = *(const uint4*)(gp0 + 8);
    ld[1][0] = *(const uint4*)gp1;       ld[1][1] = *(const uint4*)(gp1 + 8);
    ld[2][0] = *(const uint4*)gp2;       ld[2][1] = *(const uint4*)(gp2 + 8);
    #pragma unroll
    for (int arr = 0; arr < 3; arr++) {
        *(uint4*)&smh[arr*GM_BUF + sto]     = ld[arr][0];
        *(uint4*)&smh[arr*GM_BUF + sto + 8] = ld[arr][1];
    }
    __syncthreads();

    const int NKT = K >> 5;
    for (int kt = 0; kt < NKT; kt++) {
        const int b = kt & 1;
        if (kt + 1 < NKT) {
            const int kb = (kt + 1) << 5;
            ld[0][0] = *(const uint4*)(gp0 + kb); ld[0][1] = *(const uint4*)(gp0 + kb + 8);
            ld[1][0] = *(const uint4*)(gp1 + kb); ld[1][1] = *(const uint4*)(gp1 + kb + 8);
            ld[2][0] = *(const uint4*)(gp2 + kb); ld[2][1] = *(const uint4*)(gp2 + kb + 8);
        }

        const __half* sA  = smh + b*(3*GM_BUF);
        const __half* sBh = sA + GM_BUF;
        const __half* sBl = sBh + GM_BUF;

        #pragma unroll
        for (int k16 = 0; k16 < 32; k16 += 16) {
            uint32_t af[4][4];
            #pragma unroll
            for (int mi = 0; mi < 4; mi++) {
                int roff = (wm*64 + mi*16 + l16) * GM_PAD + k16 + (lane >> 4) * 8;
                ldsm_x4(af[mi][0], af[mi][1], af[mi][2], af[mi][3], smem_u32(sA + roff));
            }
            #pragma unroll
            for (int ni = 0; ni < 4; ni++) {
                int boff = (wn*32 + ni*8 + (l16 & 7)) * GM_PAD + k16 + ((l16 >> 3) & 1) * 8;
                uint32_t bh0, bh1, bl0, bl1;
                ldsm_x2(bh0, bh1, smem_u32(sBh + boff));
                ldsm_x2(bl0, bl1, smem_u32(sBl + boff));
                #pragma unroll
                for (int mi = 0; mi < 4; mi++) {
                    mma_f16_f32(acc [mi][ni], af[mi][0], af[mi][1], af[mi][2], af[mi][3], bh0, bh1);
                    mma_f16_f32(accL[mi][ni], af[mi][0], af[mi][1], af[mi][2], af[mi][3], bl0, bl1);
                }
            }
        }

        if (kt + 1 < NKT) {
            __half* dst = smh + (b ^ 1)*(3*GM_BUF);
            #pragma unroll
            for (int arr = 0; arr < 3; arr++) {
                *(uint4*)&dst[arr*GM_BUF + sto]     = ld[arr][0];
                *(uint4*)&dst[arr*GM_BUF + sto + 8] = ld[arr][1];
            }
        }
        __syncthreads();
    }

    const int g = lane >> 2, tg = lane & 3;
    #pragma unroll
    for (int mi = 0; mi < 4; mi++) {
        #pragma unroll
        for (int ni = 0; ni < 4; ni++) {
            int r0 = m0 + wm*64 + mi*16 + g;
            int c0 = n0 + wn*32 + ni*8 + tg*2;
            float2 lo = {fmaf(accL[mi][ni][0], LOINV, acc[mi][ni][0]),
                         fmaf(accL[mi][ni][1], LOINV, acc[mi][ni][1])};
            float2 hi = {fmaf(accL[mi][ni][2], LOINV, acc[mi][ni][2]),
                         fmaf(accL[mi][ni][3], LOINV, acc[mi][ni][3])};
            *(float2*)&C[(size_t)r0 * N + c0]       = lo;
            *(float2*)&C[(size_t)(r0 + 8) * N + c0] = hi;
        }
    }
}

// ---------------- RoPE + relu feature projection + fused kp rowsum -----------
__global__ void __launch_bounds__(128) ropeproj_kernel(
    const float* __restrict__ cosg, const float* __restrict__ sing,
    const float* __restrict__ proj)
{
    __shared__ float dat[64*68];   // [d][r]
    __shared__ float pj [64*68];   // [d][f]
    const int tid = threadIdx.x;
    const int rbase = blockIdx.x * 64;

    #pragma unroll
    for (int j = 0; j < 32; j++) {
        int i = tid + j*128;
        int f = i >> 6, d = i & 63;
        pj[d*68 + f] = proj[i];
    }
    #pragma unroll
    for (int j = 0; j < 32; j++) {
        int e = tid + j*128;
        int r = e >> 6, d = e & 63;
        int rho = rbase + r;
        int bs  = rho / 24;
        int h   = rho - bs*24;
        int s   = bs & (Sv-1);
        size_t base = (size_t)bs*QKVD + h*64;
        float val  = g_qkv[base + d];
        int   pd   = (d < 32) ? d + 32 : d - 32;
        float part = g_qkv[base + pd];
        float rot  = (d < 32) ? -part : part;
        dat[d*68 + r] = fmaf(val, cosg[s*64 + d], rot * sing[s*64 + d]);
    }
    __syncthreads();

    const int rq = tid >> 4, fq = tid & 15;
    float acc[8][4];
    #pragma unroll
    for (int i = 0; i < 8; i++)
        #pragma unroll
        for (int j = 0; j < 4; j++) acc[i][j] = 0.f;

    #pragma unroll
    for (int k = 0; k < 64; k++) {
        float4 a0 = *(const float4*)&dat[k*68 + rq*8];
        float4 a1 = *(const float4*)&dat[k*68 + rq*8 + 4];
        float4 bv = *(const float4*)&pj [k*68 + fq*4];
        float av[8] = {a0.x,a0.y,a0.z,a0.w,a1.x,a1.y,a1.z,a1.w};
        #pragma unroll
        for (int i = 0; i < 8; i++) {
            acc[i][0] = fmaf(av[i], bv.x, acc[i][0]);
            acc[i][1] = fmaf(av[i], bv.y, acc[i][1]);
            acc[i][2] = fmaf(av[i], bv.z, acc[i][2]);
            acc[i][3] = fmaf(av[i], bv.w, acc[i][3]);
        }
    }

    const float ratio = (float)(0.125 * (0.125 + 1e-4));
    #pragma unroll
    for (int i = 0; i < 8; i++) {
        int rho = rbase + rq*8 + i;
        int bs  = rho / 24;
        int h   = rho - bs*24;
        float4 o;
        o.x = fmaxf(acc[i][0]*ratio, 0.f);
        o.y = fmaxf(acc[i][1]*ratio, 0.f);
        o.z = fmaxf(acc[i][2]*ratio, 0.f);
        o.w = fmaxf(acc[i][3]*ratio, 0.f);

        float rs = (o.x + o.y) + (o.z + o.w);
        #pragma unroll
        for (int ofs = 1; ofs < 16; ofs <<= 1)
            rs += __shfl_xor_sync(0xffffffffu, rs, ofs);

        if (h < NHEAD) {
            o.x += 1e-4f; o.y += 1e-4f; o.z += 1e-4f; o.w += 1e-4f;
            *(float4*)&g_qp[((size_t)bs*NHEAD + h)*NFEAT + fq*4] = o;
        } else {
            int kvh = h - NHEAD;
            int b = bs >> 12, t = bs & 4095;
            if (fq == 0) g_z[((size_t)(b*NKVH + kvh))*Sv + t] = rs;
            *(float4*)&g_kp[((size_t)bs*NKVH + kvh)*NFEAT + fq*4] = o;
        }
    }
}

// ---------------- inclusive scan of g_z per (b,kvh), in place -----------------
__global__ void __launch_bounds__(256) zscan_kernel()
{
    const int bkv = blockIdx.x;
    const int tid = threadIdx.x;
    const int lane = tid & 31, warp = tid >> 5;
    __shared__ float wsum[8];
    float carry = 0.f;

    for (int tile = 0; tile < 16; tile++) {
        int t = tile*256 + tid;
        float x = g_z[(size_t)bkv*Sv + t];
        #pragma unroll
        for (int o = 1; o < 32; o <<= 1) {
            float n = __shfl_up_sync(0xffffffffu, x, o);
            if (lane >= o) x += n;
        }
        if (lane == 31) wsum[warp] = x;
        __syncthreads();
        float off = carry;
        for (int w2 = 0; w2 < warp; w2++) off += wsum[w2];
        g_z[(size_t)bkv*Sv + t] = off + x;
        float tot = 0.f;
        #pragma unroll
        for (int w2 = 0; w2 < 8; w2++) tot += wsum[w2];
        carry += tot;
        __syncthreads();
    }
}

// ---------------- per-chunk KV = Kp^T V (64x64) ------------------------------
__global__ void __launch_bounds__(256) chunkkv_kernel()
{
    extern __shared__ float cs[];
    float* Ks = cs;
    float* Vs = cs + 8192;
    const int c   = blockIdx.x;
    const int bkv = blockIdx.y;
    const int b   = bkv >> 3, kvh = bkv & 7;
    const int tid = threadIdx.x;

    #pragma unroll
    for (int j = 0; j < 32; j++) {
        int e = tid + j*256;
        int t = e >> 6, f = e & 63;
        size_t bs = (size_t)(b*Sv + c*CHUNK + t);
        Ks[e] = g_kp[(bs*NKVH + kvh)*NFEAT + f];
        Vs[e] = g_qkv[bs*QKVD + 1536 + kvh*64 + f];
    }
    __syncthreads();

    const int fq = tid >> 4, dq = tid & 15;
    float acc[4][4];
    #pragma unroll
    for (int i = 0; i < 4; i++)
        #pragma unroll
        for (int j = 0; j < 4; j++) acc[i][j] = 0.f;

    #pragma unroll 8
    for (int t = 0; t < 128; t++) {
        float4 a = *(const float4*)&Ks[t*64 + fq*4];
        float4 v = *(const float4*)&Vs[t*64 + dq*4];
        float av[4] = {a.x,a.y,a.z,a.w};
        #pragma unroll
        for (int i = 0; i < 4; i++) {
            acc[i][0] = fmaf(av[i], v.x, acc[i][0]);
            acc[i][1] = fmaf(av[i], v.y, acc[i][1]);
            acc[i][2] = fmaf(av[i], v.z, acc[i][2]);
            acc[i][3] = fmaf(av[i], v.w, acc[i][3]);
        }
    }
    size_t base = ((size_t)bkv*NCHUNK + c)*4096;
    #pragma unroll
    for (int i = 0; i < 4; i++) {
        float4 o = {acc[i][0], acc[i][1], acc[i][2], acc[i][3]};
        *(float4*)&g_kvc[base + (size_t)(fq*4 + i)*64 + dq*4] = o;
    }
}

// ---------------- exclusive chunk-prefix of KV, in place ---------------------
__global__ void __launch_bounds__(256) kvprefix_kernel()
{
    const int bkv = blockIdx.x;
    const int tid = threadIdx.x;
    float acc[16];
    #pragma unroll
    for (int j = 0; j < 16; j++) acc[j] = 0.f;
    for (int c = 0; c < NCHUNK; c++) {
        size_t base = ((size_t)bkv*NCHUNK + c)*4096;
        #pragma unroll
        for (int j = 0; j < 16; j++) {
            size_t idx = base + tid + j*256;
            float cur = g_kvc[idx];
            g_kvc[idx] = acc[j];
            acc[j] += cur;
        }
    }
}

// ---------------- stage D: mma.sync split-bf16 causal combine ----------------
#define SD_QP  72
#define SD_SP  136
#define SD_BYTES (99328*2 + 512)

__global__ void __launch_bounds__(256) stage_d_kernel()
{
    extern __shared__ __nv_bfloat16 sh[];
    __nv_bfloat16* sQh = sh;
    __nv_bfloat16* sQl = sh + 9216;
    __nv_bfloat16* sKh = sh + 18432;
    __nv_bfloat16* sKl = sh + 27648;
    __nv_bfloat16* sVh = sh + 36864;
    __nv_bfloat16* sVl = sh + 46080;
    __nv_bfloat16* sCh = sh + 55296;
    __nv_bfloat16* sCl = sh + 59904;
    __nv_bfloat16* sSh = sh + 64512;
    __nv_bfloat16* sSl = sh + 81920;
    float* dinv = (float*)(sh + 99328);

    const int c   = blockIdx.x;
    const int h   = blockIdx.y;
    const int b   = blockIdx.z;
    const int kvh = h >> 1;
    const int tid = threadIdx.x;
    const size_t t0 = (size_t)b*Sv + c*CHUNK;

    #pragma unroll
    for (int j = 0; j < 32; j++) {
        int e = tid + j*256;
        int t = e >> 6, f = e & 63;
        float q = g_qp[((t0 + t)*NHEAD + h)*NFEAT + f];
        float k = g_kp[((t0 + t)*NKVH + kvh)*NFEAT + f];
        float v = g_qkv[(t0 + t)*QKVD + 1536 + kvh*64 + f];
        __nv_bfloat16 qh = __float2bfloat16(q);
        __nv_bfloat16 kh = __float2bfloat16(k);
        __nv_bfloat16 vh = __float2bfloat16(v);
        sQh[t*SD_QP + f] = qh; sQl[t*SD_QP + f] = __float2bfloat16(q - __bfloat162float(qh));
        sKh[t*SD_QP + f] = kh; sKl[t*SD_QP + f] = __float2bfloat16(k - __bfloat162float(kh));
        sVh[t*SD_QP + f] = vh; sVl[t*SD_QP + f] = __float2bfloat16(v - __bfloat162float(vh));
    }
    #pragma unroll
    for (int j = 0; j < 16; j++) {
        int e = tid + j*256;
        int f = e >> 6, d = e & 63;
        float kv = g_kvc[(((size_t)(b*NKVH + kvh))*NCHUNK + c)*4096 + e];
        __nv_bfloat16 hh = __float2bfloat16(kv);
        sCh[f*SD_QP + d] = hh;
        sCl[f*SD_QP + d] = __float2bfloat16(kv - __bfloat162float(hh));
    }
    __syncthreads();

    if (tid < 128) {
        float s = 0.f;
        #pragma unroll
        for (int f = 0; f < 64; f++)
            s += __bfloat162float(sQh[tid*SD_QP + f]) + __bfloat162float(sQl[tid*SD_QP + f]);
        float z = g_z[((size_t)(b*NKVH + kvh))*Sv + c*CHUNK + tid];
        dinv[tid] = 1.0f / (s*z + 1e-6f);
    }
    __syncthreads();

    const int wid = tid >> 5, lane = tid & 31;
    const int l16 = lane & 15, g = lane >> 2, tg = lane & 3;
    const int mrow = wid * 16;
    const int ahalf = (lane >> 4) * 8;

    {
        float accS[16][4];
        #pragma unroll
        for (int nt = 0; nt < 16; nt++)
            #pragma unroll
            for (int r = 0; r < 4; r++) accS[nt][r] = 0.f;

        #pragma unroll
        for (int k16 = 0; k16 < 64; k16 += 16) {
            int ro = (mrow + l16)*SD_QP + k16 + ahalf;
            uint32_t ah0,ah1,ah2,ah3, al0,al1,al2,al3;
            ldsm_x4(ah0,ah1,ah2,ah3, smem_u32(sQh + ro));
            ldsm_x4(al0,al1,al2,al3, smem_u32(sQl + ro));
            #pragma unroll
            for (int nt = 0; nt < 16; nt++) {
                int bo = (nt*8 + (l16 & 7))*SD_QP + k16 + ((l16 >> 3) & 1)*8;
                uint32_t bh0,bh1,bl0,bl1;
                ldsm_x2(bh0,bh1, smem_u32(sKh + bo));
                ldsm_x2(bl0,bl1, smem_u32(sKl + bo));
                mma_bf16(accS[nt], ah0,ah1,ah2,ah3, bh0,bh1);
                mma_bf16(accS[nt], ah0,ah1,ah2,ah3, bl0,bl1);
                mma_bf16(accS[nt], al0,al1,al2,al3, bh0,bh1);
            }
        }
        #pragma unroll
        for (int nt = 0; nt < 16; nt++) {
            int r0 = mrow + g, r1 = r0 + 8;
            int c0 = nt*8 + tg*2;
            float v00 = (c0     <= r0) ? accS[nt][0] : 0.f;
            float v01 = (c0 + 1 <= r0) ? accS[nt][1] : 0.f;
            float v10 = (c0     <= r1) ? accS[nt][2] : 0.f;
            float v11 = (c0 + 1 <= r1) ? accS[nt][3] : 0.f;
            __nv_bfloat16 h00 = __float2bfloat16(v00), h01 = __float2bfloat16(v01);
            __nv_bfloat16 h10 = __float2bfloat16(v10), h11 = __float2bfloat16(v11);
            *(uint32_t*)&sSh[r0*SD_SP + c0] =
                (uint32_t)__bfloat16_as_ushort(h00) | ((uint32_t)__bfloat16_as_ushort(h01) << 16);
            *(uint32_t*)&sSh[r1*SD_SP + c0] =
                (uint32_t)__bfloat16_as_ushort(h10) | ((uint32_t)__bfloat16_as_ushort(h11) << 16);
            *(uint32_t*)&sSl[r0*SD_SP + c0] =
                pack2(v00 - __bfloat162float(h00), v01 - __bfloat162float(h01));
            *(uint32_t*)&sSl[r1*SD_SP + c0] =
                pack2(v10 - __bfloat162float(h10), v11 - __bfloat162float(h11));
        }
    }
    __syncwarp();

    {
        float acc2[8][4];
        #pragma unroll
        for (int nt = 0; nt < 8; nt++)
            #pragma unroll
            for (int r = 0; r < 4; r++) acc2[nt][r] = 0.f;

        #pragma unroll
        for (int k16 = 0; k16 < 128; k16 += 16) {
            int ro = (mrow + l16)*SD_SP + k16 + ahalf;
            uint32_t ah0,ah1,ah2,ah3, al0,al1,al2,al3;
            ldsm_x4(ah0,ah1,ah2,ah3, smem_u32(sSh + ro));
            ldsm_x4(al0,al1,al2,al3, smem_u32(sSl + ro));
            #pragma unroll
            for (int nt = 0; nt < 8; nt++) {
                int bo = (k16 + l16)*SD_QP + nt*8;
                uint32_t bh0,bh1,bl0,bl1;
                ldsm_x2_t(bh0,bh1, smem_u32(sVh + bo));
                ldsm_x2_t(bl0,bl1, smem_u32(sVl + bo));
                mma_bf16(acc2[nt], ah0,ah1,ah2,ah3, bh0,bh1);
                mma_bf16(acc2[nt], ah0,ah1,ah2,ah3, bl0,bl1);
                mma_bf16(acc2[nt], al0,al1,al2,al3, bh0,bh1);
            }
        }
        #pragma unroll
        for (int k16 = 0; k16 < 64; k16 += 16) {
            int ro = (mrow + l16)*SD_QP + k16 + ahalf;
            uint32_t ah0,ah1,ah2,ah3, al0,al1,al2,al3;
            ldsm_x4(ah0,ah1,ah2,ah3, smem_u32(sQh + ro));
            ldsm_x4(al0,al1,al2,al3, smem_u32(sQl + ro));
            #pragma unroll
            for (int nt = 0; nt < 8; nt++) {
                int bo = (k16 + l16)*SD_QP + nt*8;
                uint32_t bh0,bh1,bl0,bl1;
                ldsm_x2_t(bh0,bh1, smem_u32(sCh + bo));
                ldsm_x2_t(bl0,bl1, smem_u32(sCl + bo));
                mma_bf16(acc2[nt], ah0,ah1,ah2,ah3, bh0,bh1);
                mma_bf16(acc2[nt], ah0,ah1,ah2,ah3, bl0,bl1);
                mma_bf16(acc2[nt], al0,al1,al2,al3, bh0,bh1);
            }
        }

        const int r0 = mrow + g, r1 = r0 + 8;
        const float d0 = dinv[r0], d1 = dinv[r1];
        #pragma unroll
        for (int nt = 0; nt < 8; nt++) {
            int c0 = nt*8 + tg*2;
            float o00 = acc2[nt][0]*d0, o01 = acc2[nt][1]*d0;
            float o10 = acc2[nt][2]*d1, o11 = acc2[nt][3]*d1;
            size_t a0 = (t0 + r0)*1024 + h*64 + c0;
            size_t a1 = (t0 + r1)*1024 + h*64 + c0;
            *(uint32_t*)&g_ah[a0] = pack2h(o00, o01);
            *(uint32_t*)&g_ah[a1] = pack2h(o10, o11);
        }
    }
}

// ---------------- launch ------------------------------------------------------
extern "C" void kernel_launch(void* const* d_in, const int* in_sizes, int n_in,
                              void* d_out, int out_size)
{
    const float* hidden = (const float*)d_in[0];
    const float* cosg   = (const float*)d_in[1];
    const float* sing   = (const float*)d_in[2];
    const float* W_qkv  = (const float*)d_in[3];
    const float* W_o    = (const float*)d_in[4];
    const float* proj   = (const float*)d_in[5];
    float* out = (float*)d_out;

    static bool attr_done = false;
    if (!attr_done) {
        cudaFuncSetAttribute(chunkkv_kernel,
            cudaFuncAttributeMaxDynamicSharedMemorySize, 65536);
        cudaFuncSetAttribute(stage_d_kernel,
            cudaFuncAttributeMaxDynamicSharedMemorySize, SD_BYTES);
        cudaFuncSetAttribute(gemm_mma_kernel,
            cudaFuncAttributeMaxDynamicSharedMemorySize, GM_SMEM);
        attr_done = true;
    }

    float* qkv = nullptr; cudaGetSymbolAddress((void**)&qkv, g_qkv);
    __half *ah, *w1hi, *w1lo, *w2hi, *w2lo;
    cudaGetSymbolAddress((void**)&ah,   g_ah);
    cudaGetSymbolAddress((void**)&w1hi, g_w1hi);
    cudaGetSymbolAddress((void**)&w1lo, g_w1lo);
    cudaGetSymbolAddress((void**)&w2hi, g_w2hi);
    cudaGetSymbolAddress((void**)&w2lo, g_w2lo);

    // 1. convert hidden (fp16) + split W_qkv, 2-pass QKV GEMM
    cvt_h_kernel<<<(MROWS*1024)/1024, 256>>>(hidden, ah, MROWS*1024);
    cvt_split_kernel<<<(2048*1024)/1024, 256>>>(W_qkv, w1hi, w1lo, 2048*1024);
    gemm_mma_kernel<<<dim3(QKVD/128, MROWS/128), 256, GM_SMEM>>>(
        ah, w1hi, w1lo, qkv, QKVD, 1024);

    // 2. rope + feature projection (+ fused kp rowsums into g_z)
    ropeproj_kernel<<<(MROWS*24)/64, 128>>>(cosg, sing, proj);
    // 3. z scan
    zscan_kernel<<<Bv*NKVH, 256>>>();
    // 4. per-chunk KV
    chunkkv_kernel<<<dim3(NCHUNK, Bv*NKVH), 256, 65536>>>();
    // 5. exclusive chunk prefix
    kvprefix_kernel<<<Bv*NKVH, 256>>>();
    // 6. causal combine -> writes fp16 attn directly into g_ah
    stage_d_kernel<<<dim3(NCHUNK, NHEAD, Bv), 256, SD_BYTES>>>();

    // 7. split W_o, 2-pass output GEMM
    cvt_split_kernel<<<(1024*1024)/1024, 256>>>(W_o, w2hi, w2lo, 1024*1024);
    gemm_mma_kernel<<<dim3(1024/128, MROWS/128), 256, GM_SMEM>>>(
        ah, w2hi, w2lo, out, 1024, 1024);
}

// round 13
// speedup vs baseline: 2.8885x; 1.3228x over previous
#include <cuda_runtime.h>
#include <cuda_bf16.h>
#include <cuda_fp16.h>
#include <cstdint>

#define Bv      2
#define Sv      4096
#define QKVD    2048
#define NHEAD   16
#define NKVH    8
#define HDIM    64
#define NFEAT   64
#define CHUNK   128
#define NCHUNK  32
#define MROWS   (Bv*Sv)

// ---------------- scratch (device globals; no allocs allowed) ----------------
__device__ float g_qkv [(size_t)MROWS*QKVD];
__device__ float g_qp  [(size_t)MROWS*NHEAD*NFEAT];
__device__ float g_kp  [(size_t)MROWS*NKVH*NFEAT];
__device__ float g_z   [(size_t)Bv*NKVH*Sv];
__device__ float g_kvc [(size_t)Bv*NKVH*NCHUNK*NFEAT*HDIM];

__device__ __half g_ah [(size_t)MROWS*1024];     // activations fp16
__device__ __half g_w1 [(size_t)2048*1024];      // W_qkv fp16
__device__ __half g_w2 [(size_t)1024*1024];      // W_o fp16

// ---------------- PTX helpers -------------------------------------------------
__device__ __forceinline__ uint32_t smem_u32(const void* p) {
    uint32_t a;
    asm("{ .reg .u64 t; cvta.to.shared.u64 t, %1; cvt.u32.u64 %0, t; }" : "=r"(a) : "l"(p));
    return a;
}
__device__ __forceinline__ void ldsm_x4(uint32_t& r0, uint32_t& r1,
                                        uint32_t& r2, uint32_t& r3, uint32_t a) {
    asm volatile("ldmatrix.sync.aligned.m8n8.x4.shared.b16 {%0,%1,%2,%3}, [%4];"
                 : "=r"(r0), "=r"(r1), "=r"(r2), "=r"(r3) : "r"(a));
}
__device__ __forceinline__ void ldsm_x2(uint32_t& r0, uint32_t& r1, uint32_t a) {
    asm volatile("ldmatrix.sync.aligned.m8n8.x2.shared.b16 {%0,%1}, [%2];"
                 : "=r"(r0), "=r"(r1) : "r"(a));
}
__device__ __forceinline__ void ldsm_x2_t(uint32_t& r0, uint32_t& r1, uint32_t a) {
    asm volatile("ldmatrix.sync.aligned.m8n8.x2.trans.shared.b16 {%0,%1}, [%2];"
                 : "=r"(r0), "=r"(r1) : "r"(a));
}
__device__ __forceinline__ void mma_bf16(float* d,
    uint32_t a0, uint32_t a1, uint32_t a2, uint32_t a3, uint32_t b0, uint32_t b1) {
    asm volatile(
        "mma.sync.aligned.m16n8k16.row.col.f32.bf16.bf16.f32 "
        "{%0,%1,%2,%3}, {%4,%5,%6,%7}, {%8,%9}, {%0,%1,%2,%3};"
        : "+f"(d[0]), "+f"(d[1]), "+f"(d[2]), "+f"(d[3])
        : "r"(a0), "r"(a1), "r"(a2), "r"(a3), "r"(b0), "r"(b1));
}
__device__ __forceinline__ void mma_f16_f32(float* d,
    uint32_t a0, uint32_t a1, uint32_t a2, uint32_t a3, uint32_t b0, uint32_t b1) {
    asm volatile(
        "mma.sync.aligned.m16n8k16.row.col.f32.f16.f16.f32 "
        "{%0,%1,%2,%3}, {%4,%5,%6,%7}, {%8,%9}, {%0,%1,%2,%3};"
        : "+f"(d[0]), "+f"(d[1]), "+f"(d[2]), "+f"(d[3])
        : "r"(a0), "r"(a1), "r"(a2), "r"(a3), "r"(b0), "r"(b1));
}
__device__ __forceinline__ uint32_t pack2(float x, float y) {
    __nv_bfloat16 bx = __float2bfloat16(x), by = __float2bfloat16(y);
    return (uint32_t)__bfloat16_as_ushort(bx) |
           ((uint32_t)__bfloat16_as_ushort(by) << 16);
}
__device__ __forceinline__ uint32_t pack2h(float x, float y) {
    __half hx = __float2half(x), hy = __float2half(y);
    return (uint32_t)__half_as_ushort(hx) |
           ((uint32_t)__half_as_ushort(hy) << 16);
}

// ---------------- fp32 -> fp16 convert ----------------------------------------
__global__ void __launch_bounds__(256) cvt_h_kernel(
    const float* __restrict__ src, __half* __restrict__ dst, int n)
{
    int i = (blockIdx.x * 256 + threadIdx.x) * 4;
    if (i >= n) return;
    float4 v = *(const float4*)(src + i);
    __half2* dp = (__half2*)(dst + i);
    dp[0] = __half2(__float2half(v.x), __float2half(v.y));
    dp[1] = __half2(__float2half(v.z), __float2half(v.w));
}

// ---------------- mma.sync GEMM (1-pass fp16): C = A[M,K] * B[N,K]^T ----------
#define GM_PAD  40
#define GM_BUF  (128*GM_PAD)
#define GM_SMEM (2*2*GM_BUF*2)

__global__ void __launch_bounds__(256) gemm_mma_kernel(
    const __half* __restrict__ A, const __half* __restrict__ B,
    float* __restrict__ C, int N, int K)
{
    extern __shared__ __half smh[];
    const int tid = threadIdx.x;
    const int m0 = blockIdx.y * 128, n0 = blockIdx.x * 128;
    const int row = tid >> 1, off = (tid & 1) * 16;

    const __half* gp0 = A + (size_t)(m0 + row) * K + off;
    const __half* gp1 = B + (size_t)(n0 + row) * K + off;

    const int wid = tid >> 5, lane = tid & 31;
    const int wm = wid >> 2, wn = wid & 3;
    const int l16 = lane & 15;

    float acc[4][4][4];
    #pragma unroll
    for (int mi = 0; mi < 4; mi++)
        #pragma unroll
        for (int ni = 0; ni < 4; ni++)
            #pragma unroll
            for (int r = 0; r < 4; r++) acc[mi][ni][r] = 0.f;

    const int sto = row * GM_PAD + off;
    uint4 ld[2][2];

    ld[0][0] = *(const uint4*)gp0;       ld[0][1] = *(const uint4*)(gp0 + 8);
    ld[1][0] = *(const uint4*)gp1;       ld[1][1] = *(const uint4*)(gp1 + 8);
    #pragma unroll
    for (int arr = 0; arr < 2; arr++) {
        *(uint4*)&smh[arr*GM_BUF + sto]     = ld[arr][0];
        *(uint4*)&smh[arr*GM_BUF + sto + 8] = ld[arr][1];
    }
    __syncthreads();

    const int NKT = K >> 5;
    for (int kt = 0; kt < NKT; kt++) {
        const int b = kt & 1;
        if (kt + 1 < NKT) {
            const int kb = (kt + 1) << 5;
            ld[0][0] = *(const uint4*)(gp0 + kb); ld[0][1] = *(const uint4*)(gp0 + kb + 8);
            ld[1][0] = *(const uint4*)(gp1 + kb); ld[1][1] = *(const uint4*)(gp1 + kb + 8);
        }

        const __half* sA = smh + b*(2*GM_BUF);
        const __half* sB = sA + GM_BUF;

        #pragma unroll
        for (int k16 = 0; k16 < 32; k16 += 16) {
            uint32_t af[4][4];
            #pragma unroll
            for (int mi = 0; mi < 4; mi++) {
                int roff = (wm*64 + mi*16 + l16) * GM_PAD + k16 + (lane >> 4) * 8;
                ldsm_x4(af[mi][0], af[mi][1], af[mi][2], af[mi][3], smem_u32(sA + roff));
            }
            #pragma unroll
            for (int ni = 0; ni < 4; ni++) {
                int boff = (wn*32 + ni*8 + (l16 & 7)) * GM_PAD + k16 + ((l16 >> 3) & 1) * 8;
                uint32_t b0, b1;
                ldsm_x2(b0, b1, smem_u32(sB + boff));
                #pragma unroll
                for (int mi = 0; mi < 4; mi++)
                    mma_f16_f32(acc[mi][ni], af[mi][0], af[mi][1], af[mi][2], af[mi][3], b0, b1);
            }
        }

        if (kt + 1 < NKT) {
            __half* dst = smh + (b ^ 1)*(2*GM_BUF);
            #pragma unroll
            for (int arr = 0; arr < 2; arr++) {
                *(uint4*)&dst[arr*GM_BUF + sto]     = ld[arr][0];
                *(uint4*)&dst[arr*GM_BUF + sto + 8] = ld[arr][1];
            }
        }
        __syncthreads();
    }

    const int g = lane >> 2, tg = lane & 3;
    #pragma unroll
    for (int mi = 0; mi < 4; mi++) {
        #pragma unroll
        for (int ni = 0; ni < 4; ni++) {
            int r0 = m0 + wm*64 + mi*16 + g;
            int c0 = n0 + wn*32 + ni*8 + tg*2;
            float2 lo = {acc[mi][ni][0], acc[mi][ni][1]};
            float2 hi = {acc[mi][ni][2], acc[mi][ni][3]};
            *(float2*)&C[(size_t)r0 * N + c0]       = lo;
            *(float2*)&C[(size_t)(r0 + 8) * N + c0] = hi;
        }
    }
}

// ---------------- RoPE + relu feature projection + fused kp rowsum -----------
__global__ void __launch_bounds__(128) ropeproj_kernel(
    const float* __restrict__ cosg, const float* __restrict__ sing,
    const float* __restrict__ proj)
{
    __shared__ float dat[64*68];   // [d][r]
    __shared__ float pj [64*68];   // [d][f]
    const int tid = threadIdx.x;
    const int rbase = blockIdx.x * 64;

    #pragma unroll
    for (int j = 0; j < 32; j++) {
        int i = tid + j*128;
        int f = i >> 6, d = i & 63;
        pj[d*68 + f] = proj[i];
    }
    #pragma unroll
    for (int j = 0; j < 32; j++) {
        int e = tid + j*128;
        int r = e >> 6, d = e & 63;
        int rho = rbase + r;
        int bs  = rho / 24;
        int h   = rho - bs*24;
        int s   = bs & (Sv-1);
        size_t base = (size_t)bs*QKVD + h*64;
        float val  = g_qkv[base + d];
        int   pd   = (d < 32) ? d + 32 : d - 32;
        float part = g_qkv[base + pd];
        float rot  = (d < 32) ? -part : part;
        dat[d*68 + r] = fmaf(val, cosg[s*64 + d], rot * sing[s*64 + d]);
    }
    __syncthreads();

    const int rq = tid >> 4, fq = tid & 15;
    float acc[8][4];
    #pragma unroll
    for (int i = 0; i < 8; i++)
        #pragma unroll
        for (int j = 0; j < 4; j++) acc[i][j] = 0.f;

    #pragma unroll
    for (int k = 0; k < 64; k++) {
        float4 a0 = *(const float4*)&dat[k*68 + rq*8];
        float4 a1 = *(const float4*)&dat[k*68 + rq*8 + 4];
        float4 bv = *(const float4*)&pj [k*68 + fq*4];
        float av[8] = {a0.x,a0.y,a0.z,a0.w,a1.x,a1.y,a1.z,a1.w};
        #pragma unroll
        for (int i = 0; i < 8; i++) {
            acc[i][0] = fmaf(av[i], bv.x, acc[i][0]);
            acc[i][1] = fmaf(av[i], bv.y, acc[i][1]);
            acc[i][2] = fmaf(av[i], bv.z, acc[i][2]);
            acc[i][3] = fmaf(av[i], bv.w, acc[i][3]);
        }
    }

    const float ratio = (float)(0.125 * (0.125 + 1e-4));
    #pragma unroll
    for (int i = 0; i < 8; i++) {
        int rho = rbase + rq*8 + i;
        int bs  = rho / 24;
        int h   = rho - bs*24;
        float4 o;
        o.x = fmaxf(acc[i][0]*ratio, 0.f);
        o.y = fmaxf(acc[i][1]*ratio, 0.f);
        o.z = fmaxf(acc[i][2]*ratio, 0.f);
        o.w = fmaxf(acc[i][3]*ratio, 0.f);

        float rs = (o.x + o.y) + (o.z + o.w);
        #pragma unroll
        for (int ofs = 1; ofs < 16; ofs <<= 1)
            rs += __shfl_xor_sync(0xffffffffu, rs, ofs);

        if (h < NHEAD) {
            o.x += 1e-4f; o.y += 1e-4f; o.z += 1e-4f; o.w += 1e-4f;
            *(float4*)&g_qp[((size_t)bs*NHEAD + h)*NFEAT + fq*4] = o;
        } else {
            int kvh = h - NHEAD;
            int b = bs >> 12, t = bs & 4095;
            if (fq == 0) g_z[((size_t)(b*NKVH + kvh))*Sv + t] = rs;
            *(float4*)&g_kp[((size_t)bs*NKVH + kvh)*NFEAT + fq*4] = o;
        }
    }
}

// ---------------- inclusive scan of g_z per (b,kvh), in place -----------------
__global__ void __launch_bounds__(256) zscan_kernel()
{
    const int bkv = blockIdx.x;
    const int tid = threadIdx.x;
    const int lane = tid & 31, warp = tid >> 5;
    __shared__ float wsum[8];
    float carry = 0.f;

    for (int tile = 0; tile < 16; tile++) {
        int t = tile*256 + tid;
        float x = g_z[(size_t)bkv*Sv + t];
        #pragma unroll
        for (int o = 1; o < 32; o <<= 1) {
            float n = __shfl_up_sync(0xffffffffu, x, o);
            if (lane >= o) x += n;
        }
        if (lane == 31) wsum[warp] = x;
        __syncthreads();
        float off = carry;
        for (int w2 = 0; w2 < warp; w2++) off += wsum[w2];
        g_z[(size_t)bkv*Sv + t] = off + x;
        float tot = 0.f;
        #pragma unroll
        for (int w2 = 0; w2 < 8; w2++) tot += wsum[w2];
        carry += tot;
        __syncthreads();
    }
}

// ---------------- per-chunk KV = Kp^T V (64x64) ------------------------------
__global__ void __launch_bounds__(256) chunkkv_kernel()
{
    extern __shared__ float cs[];
    float* Ks = cs;
    float* Vs = cs + 8192;
    const int c   = blockIdx.x;
    const int bkv = blockIdx.y;
    const int b   = bkv >> 3, kvh = bkv & 7;
    const int tid = threadIdx.x;

    #pragma unroll
    for (int j = 0; j < 32; j++) {
        int e = tid + j*256;
        int t = e >> 6, f = e & 63;
        size_t bs = (size_t)(b*Sv + c*CHUNK + t);
        Ks[e] = g_kp[(bs*NKVH + kvh)*NFEAT + f];
        Vs[e] = g_qkv[bs*QKVD + 1536 + kvh*64 + f];
    }
    __syncthreads();

    const int fq = tid >> 4, dq = tid & 15;
    float acc[4][4];
    #pragma unroll
    for (int i = 0; i < 4; i++)
        #pragma unroll
        for (int j = 0; j < 4; j++) acc[i][j] = 0.f;

    #pragma unroll 8
    for (int t = 0; t < 128; t++) {
        float4 a = *(const float4*)&Ks[t*64 + fq*4];
        float4 v = *(const float4*)&Vs[t*64 + dq*4];
        float av[4] = {a.x,a.y,a.z,a.w};
        #pragma unroll
        for (int i = 0; i < 4; i++) {
            acc[i][0] = fmaf(av[i], v.x, acc[i][0]);
            acc[i][1] = fmaf(av[i], v.y, acc[i][1]);
            acc[i][2] = fmaf(av[i], v.z, acc[i][2]);
            acc[i][3] = fmaf(av[i], v.w, acc[i][3]);
        }
    }
    size_t base = ((size_t)bkv*NCHUNK + c)*4096;
    #pragma unroll
    for (int i = 0; i < 4; i++) {
        float4 o = {acc[i][0], acc[i][1], acc[i][2], acc[i][3]};
        *(float4*)&g_kvc[base + (size_t)(fq*4 + i)*64 + dq*4] = o;
    }
}

// ---------------- exclusive chunk-prefix of KV, in place ---------------------
__global__ void __launch_bounds__(256) kvprefix_kernel()
{
    const int bkv = blockIdx.x;
    const int tid = threadIdx.x;
    float acc[16];
    #pragma unroll
    for (int j = 0; j < 16; j++) acc[j] = 0.f;
    for (int c = 0; c < NCHUNK; c++) {
        size_t base = ((size_t)bkv*NCHUNK + c)*4096;
        #pragma unroll
        for (int j = 0; j < 16; j++) {
            size_t idx = base + tid + j*256;
            float cur = g_kvc[idx];
            g_kvc[idx] = acc[j];
            acc[j] += cur;
        }
    }
}

// ---------------- stage D: mma.sync split-bf16 causal combine ----------------
#define SD_QP  72
#define SD_SP  136
#define SD_BYTES (99328*2 + 512)

__global__ void __launch_bounds__(256) stage_d_kernel()
{
    extern __shared__ __nv_bfloat16 sh[];
    __nv_bfloat16* sQh = sh;
    __nv_bfloat16* sQl = sh + 9216;
    __nv_bfloat16* sKh = sh + 18432;
    __nv_bfloat16* sKl = sh + 27648;
    __nv_bfloat16* sVh = sh + 36864;
    __nv_bfloat16* sVl = sh + 46080;
    __nv_bfloat16* sCh = sh + 55296;
    __nv_bfloat16* sCl = sh + 59904;
    __nv_bfloat16* sSh = sh + 64512;
    __nv_bfloat16* sSl = sh + 81920;
    float* dinv = (float*)(sh + 99328);

    const int c   = blockIdx.x;
    const int h   = blockIdx.y;
    const int b   = blockIdx.z;
    const int kvh = h >> 1;
    const int tid = threadIdx.x;
    const size_t t0 = (size_t)b*Sv + c*CHUNK;

    #pragma unroll
    for (int j = 0; j < 32; j++) {
        int e = tid + j*256;
        int t = e >> 6, f = e & 63;
        float q = g_qp[((t0 + t)*NHEAD + h)*NFEAT + f];
        float k = g_kp[((t0 + t)*NKVH + kvh)*NFEAT + f];
        float v = g_qkv[(t0 + t)*QKVD + 1536 + kvh*64 + f];
        __nv_bfloat16 qh = __float2bfloat16(q);
        __nv_bfloat16 kh = __float2bfloat16(k);
        __nv_bfloat16 vh = __float2bfloat16(v);
        sQh[t*SD_QP + f] = qh; sQl[t*SD_QP + f] = __float2bfloat16(q - __bfloat162float(qh));
        sKh[t*SD_QP + f] = kh; sKl[t*SD_QP + f] = __float2bfloat16(k - __bfloat162float(kh));
        sVh[t*SD_QP + f] = vh; sVl[t*SD_QP + f] = __float2bfloat16(v - __bfloat162float(vh));
    }
    #pragma unroll
    for (int j = 0; j < 16; j++) {
        int e = tid + j*256;
        int f = e >> 6, d = e & 63;
        float kv = g_kvc[(((size_t)(b*NKVH + kvh))*NCHUNK + c)*4096 + e];
        __nv_bfloat16 hh = __float2bfloat16(kv);
        sCh[f*SD_QP + d] = hh;
        sCl[f*SD_QP + d] = __float2bfloat16(kv - __bfloat162float(hh));
    }
    __syncthreads();

    if (tid < 128) {
        float s = 0.f;
        #pragma unroll
        for (int f = 0; f < 64; f++)
            s += __bfloat162float(sQh[tid*SD_QP + f]) + __bfloat162float(sQl[tid*SD_QP + f]);
        float z = g_z[((size_t)(b*NKVH + kvh))*Sv + c*CHUNK + tid];
        dinv[tid] = 1.0f / (s*z + 1e-6f);
    }
    __syncthreads();

    const int wid = tid >> 5, lane = tid & 31;
    const int l16 = lane & 15, g = lane >> 2, tg = lane & 3;
    const int mrow = wid * 16;
    const int ahalf = (lane >> 4) * 8;

    {
        float accS[16][4];
        #pragma unroll
        for (int nt = 0; nt < 16; nt++)
            #pragma unroll
            for (int r = 0; r < 4; r++) accS[nt][r] = 0.f;

        #pragma unroll
        for (int k16 = 0; k16 < 64; k16 += 16) {
            int ro = (mrow + l16)*SD_QP + k16 + ahalf;
            uint32_t ah0,ah1,ah2,ah3, al0,al1,al2,al3;
            ldsm_x4(ah0,ah1,ah2,ah3, smem_u32(sQh + ro));
            ldsm_x4(al0,al1,al2,al3, smem_u32(sQl + ro));
            #pragma unroll
            for (int nt = 0; nt < 16; nt++) {
                int bo = (nt*8 + (l16 & 7))*SD_QP + k16 + ((l16 >> 3) & 1)*8;
                uint32_t bh0,bh1,bl0,bl1;
                ldsm_x2(bh0,bh1, smem_u32(sKh + bo));
                ldsm_x2(bl0,bl1, smem_u32(sKl + bo));
                mma_bf16(accS[nt], ah0,ah1,ah2,ah3, bh0,bh1);
                mma_bf16(accS[nt], ah0,ah1,ah2,ah3, bl0,bl1);
                mma_bf16(accS[nt], al0,al1,al2,al3, bh0,bh1);
            }
        }
        #pragma unroll
        for (int nt = 0; nt < 16; nt++) {
            int r0 = mrow + g, r1 = r0 + 8;
            int c0 = nt*8 + tg*2;
            float v00 = (c0     <= r0) ? accS[nt][0] : 0.f;
            float v01 = (c0 + 1 <= r0) ? accS[nt][1] : 0.f;
            float v10 = (c0     <= r1) ? accS[nt][2] : 0.f;
            float v11 = (c0 + 1 <= r1) ? accS[nt][3] : 0.f;
            __nv_bfloat16 h00 = __float2bfloat16(v00), h01 = __float2bfloat16(v01);
            __nv_bfloat16 h10 = __float2bfloat16(v10), h11 = __float2bfloat16(v11);
            *(uint32_t*)&sSh[r0*SD_SP + c0] =
                (uint32_t)__bfloat16_as_ushort(h00) | ((uint32_t)__bfloat16_as_ushort(h01) << 16);
            *(uint32_t*)&sSh[r1*SD_SP + c0] =
                (uint32_t)__bfloat16_as_ushort(h10) | ((uint32_t)__bfloat16_as_ushort(h11) << 16);
            *(uint32_t*)&sSl[r0*SD_SP + c0] =
                pack2(v00 - __bfloat162float(h00), v01 - __bfloat162float(h01));
            *(uint32_t*)&sSl[r1*SD_SP + c0] =
                pack2(v10 - __bfloat162float(h10), v11 - __bfloat162float(h11));
        }
    }
    __syncwarp();

    {
        float acc2[8][4];
        #pragma unroll
        for (int nt = 0; nt < 8; nt++)
            #pragma unroll
            for (int r = 0; r < 4; r++) acc2[nt][r] = 0.f;

        #pragma unroll
        for (int k16 = 0; k16 < 128; k16 += 16) {
            int ro = (mrow + l16)*SD_SP + k16 + ahalf;
            uint32_t ah0,ah1,ah2,ah3, al0,al1,al2,al3;
            ldsm_x4(ah0,ah1,ah2,ah3, smem_u32(sSh + ro));
            ldsm_x4(al0,al1,al2,al3, smem_u32(sSl + ro));
            #pragma unroll
            for (int nt = 0; nt < 8; nt++) {
                int bo = (k16 + l16)*SD_QP + nt*8;
                uint32_t bh0,bh1,bl0,bl1;
                ldsm_x2_t(bh0,bh1, smem_u32(sVh + bo));
                ldsm_x2_t(bl0,bl1, smem_u32(sVl + bo));
                mma_bf16(acc2[nt], ah0,ah1,ah2,ah3, bh0,bh1);
                mma_bf16(acc2[nt], ah0,ah1,ah2,ah3, bl0,bl1);
                mma_bf16(acc2[nt], al0,al1,al2,al3, bh0,bh1);
            }
        }
        #pragma unroll
        for (int k16 = 0; k16 < 64; k16 += 16) {
            int ro = (mrow + l16)*SD_QP + k16 + ahalf;
            uint32_t ah0,ah1,ah2,ah3, al0,al1,al2,al3;
            ldsm_x4(ah0,ah1,ah2,ah3, smem_u32(sQh + ro));
            ldsm_x4(al0,al1,al2,al3, smem_u32(sQl + ro));
            #pragma unroll
            for (int nt = 0; nt < 8; nt++) {
                int bo = (k16 + l16)*SD_QP + nt*8;
                uint32_t bh0,bh1,bl0,bl1;
                ldsm_x2_t(bh0,bh1, smem_u32(sCh + bo));
                ldsm_x2_t(bl0,bl1, smem_u32(sCl + bo));
                mma_bf16(acc2[nt], ah0,ah1,ah2,ah3, bh0,bh1);
                mma_bf16(acc2[nt], ah0,ah1,ah2,ah3, bl0,bl1);
                mma_bf16(acc2[nt], al0,al1,al2,al3, bh0,bh1);
            }
        }

        const int r0 = mrow + g, r1 = r0 + 8;
        const float d0 = dinv[r0], d1 = dinv[r1];
        #pragma unroll
        for (int nt = 0; nt < 8; nt++) {
            int c0 = nt*8 + tg*2;
            float o00 = acc2[nt][0]*d0, o01 = acc2[nt][1]*d0;
            float o10 = acc2[nt][2]*d1, o11 = acc2[nt][3]*d1;
            size_t a0 = (t0 + r0)*1024 + h*64 + c0;
            size_t a1 = (t0 + r1)*1024 + h*64 + c0;
            *(uint32_t*)&g_ah[a0] = pack2h(o00, o01);
            *(uint32_t*)&g_ah[a1] = pack2h(o10, o11);
        }
    }
}

// ---------------- launch ------------------------------------------------------
extern "C" void kernel_launch(void* const* d_in, const int* in_sizes, int n_in,
                              void* d_out, int out_size)
{
    const float* hidden = (const float*)d_in[0];
    const float* cosg   = (const float*)d_in[1];
    const float* sing   = (const float*)d_in[2];
    const float* W_qkv  = (const float*)d_in[3];
    const float* W_o    = (const float*)d_in[4];
    const float* proj   = (const float*)d_in[5];
    float* out = (float*)d_out;

    static bool attr_done = false;
    if (!attr_done) {
        cudaFuncSetAttribute(chunkkv_kernel,
            cudaFuncAttributeMaxDynamicSharedMemorySize, 65536);
        cudaFuncSetAttribute(stage_d_kernel,
            cudaFuncAttributeMaxDynamicSharedMemorySize, SD_BYTES);
        cudaFuncSetAttribute(gemm_mma_kernel,
            cudaFuncAttributeMaxDynamicSharedMemorySize, GM_SMEM);
        attr_done = true;
    }

    float* qkv = nullptr; cudaGetSymbolAddress((void**)&qkv, g_qkv);
    __half *ah, *w1, *w2;
    cudaGetSymbolAddress((void**)&ah, g_ah);
    cudaGetSymbolAddress((void**)&w1, g_w1);
    cudaGetSymbolAddress((void**)&w2, g_w2);

    // 1. convert hidden + W_qkv to fp16, 1-pass QKV GEMM
    cvt_h_kernel<<<(MROWS*1024)/1024, 256>>>(hidden, ah, MROWS*1024);
    cvt_h_kernel<<<(2048*1024)/1024, 256>>>(W_qkv, w1, 2048*1024);
    gemm_mma_kernel<<<dim3(QKVD/128, MROWS/128), 256, GM_SMEM>>>(
        ah, w1, qkv, QKVD, 1024);

    // 2. rope + feature projection (+ fused kp rowsums into g_z)
    ropeproj_kernel<<<(MROWS*24)/64, 128>>>(cosg, sing, proj);
    // 3. z scan
    zscan_kernel<<<Bv*NKVH, 256>>>();
    // 4. per-chunk KV
    chunkkv_kernel<<<dim3(NCHUNK, Bv*NKVH), 256, 65536>>>();
    // 5. exclusive chunk prefix
    kvprefix_kernel<<<Bv*NKVH, 256>>>();
    // 6. causal combine -> writes fp16 attn directly into g_ah
    stage_d_kernel<<<dim3(NCHUNK, NHEAD, Bv), 256, SD_BYTES>>>();

    // 7. convert W_o to fp16, 1-pass output GEMM
    cvt_h_kernel<<<(1024*1024)/1024, 256>>>(W_o, w2, 1024*1024);
    gemm_mma_kernel<<<dim3(1024/128, MROWS/128), 256, GM_SMEM>>>(
        ah, w2, out, 1024, 1024);
}

// round 14
// speedup vs baseline: 3.0870x; 1.0687x over previous
#include <cuda_runtime.h>
#include <cuda_bf16.h>
#include <cuda_fp16.h>
#include <cstdint>

#define Bv      2
#define Sv      4096
#define QKVD    2048
#define NHEAD   16
#define NKVH    8
#define HDIM    64
#define NFEAT   64
#define CHUNK   128
#define NCHUNK  32
#define MROWS   (Bv*Sv)
#define LOSCALE 2048.0f
#define LOINV   (1.0f/2048.0f)

// ---------------- scratch (device globals; no allocs allowed) ----------------
__device__ float g_qkv [(size_t)MROWS*QKVD];
__device__ float g_qp  [(size_t)MROWS*NHEAD*NFEAT];
__device__ float g_kp  [(size_t)MROWS*NKVH*NFEAT];
__device__ float g_z   [(size_t)Bv*NKVH*Sv];
__device__ float g_kvc [(size_t)Bv*NKVH*NCHUNK*NFEAT*HDIM];

__device__ __half g_ah [(size_t)MROWS*1024];     // activations fp16
__device__ __half g_w1 [(size_t)2048*1024];      // W_qkv fp16
__device__ __half g_w2 [(size_t)1024*1024];      // W_o fp16

// ---------------- PTX helpers -------------------------------------------------
__device__ __forceinline__ uint32_t smem_u32(const void* p) {
    uint32_t a;
    asm("{ .reg .u64 t; cvta.to.shared.u64 t, %1; cvt.u32.u64 %0, t; }" : "=r"(a) : "l"(p));
    return a;
}
__device__ __forceinline__ void ldsm_x4(uint32_t& r0, uint32_t& r1,
                                        uint32_t& r2, uint32_t& r3, uint32_t a) {
    asm volatile("ldmatrix.sync.aligned.m8n8.x4.shared.b16 {%0,%1,%2,%3}, [%4];"
                 : "=r"(r0), "=r"(r1), "=r"(r2), "=r"(r3) : "r"(a));
}
__device__ __forceinline__ void ldsm_x2(uint32_t& r0, uint32_t& r1, uint32_t a) {
    asm volatile("ldmatrix.sync.aligned.m8n8.x2.shared.b16 {%0,%1}, [%2];"
                 : "=r"(r0), "=r"(r1) : "r"(a));
}
__device__ __forceinline__ void ldsm_x2_t(uint32_t& r0, uint32_t& r1, uint32_t a) {
    asm volatile("ldmatrix.sync.aligned.m8n8.x2.trans.shared.b16 {%0,%1}, [%2];"
                 : "=r"(r0), "=r"(r1) : "r"(a));
}
__device__ __forceinline__ void mma_f16_f32(float* d,
    uint32_t a0, uint32_t a1, uint32_t a2, uint32_t a3, uint32_t b0, uint32_t b1) {
    asm volatile(
        "mma.sync.aligned.m16n8k16.row.col.f32.f16.f16.f32 "
        "{%0,%1,%2,%3}, {%4,%5,%6,%7}, {%8,%9}, {%0,%1,%2,%3};"
        : "+f"(d[0]), "+f"(d[1]), "+f"(d[2]), "+f"(d[3])
        : "r"(a0), "r"(a1), "r"(a2), "r"(a3), "r"(b0), "r"(b1));
}
__device__ __forceinline__ uint32_t pack2h(float x, float y) {
    __half hx = __float2half(x), hy = __float2half(y);
    return (uint32_t)__half_as_ushort(hx) |
           ((uint32_t)__half_as_ushort(hy) << 16);
}

// ---------------- fp32 -> fp16 convert ----------------------------------------
__global__ void __launch_bounds__(256) cvt_h_kernel(
    const float* __restrict__ src, __half* __restrict__ dst, int n)
{
    int i = (blockIdx.x * 256 + threadIdx.x) * 4;
    if (i >= n) return;
    float4 v = *(const float4*)(src + i);
    __half2* dp = (__half2*)(dst + i);
    dp[0] = __half2(__float2half(v.x), __float2half(v.y));
    dp[1] = __half2(__float2half(v.z), __float2half(v.w));
}

// ---------------- mma.sync GEMM (1-pass fp16): C = A[M,K] * B[N,K]^T ----------
#define GM_PAD  40
#define GM_BUF  (128*GM_PAD)
#define GM_SMEM (2*2*GM_BUF*2)

__global__ void __launch_bounds__(256) gemm_mma_kernel(
    const __half* __restrict__ A, const __half* __restrict__ B,
    float* __restrict__ C, int N, int K)
{
    extern __shared__ __half smh[];
    const int tid = threadIdx.x;
    const int m0 = blockIdx.y * 128, n0 = blockIdx.x * 128;
    const int row = tid >> 1, off = (tid & 1) * 16;

    const __half* gp0 = A + (size_t)(m0 + row) * K + off;
    const __half* gp1 = B + (size_t)(n0 + row) * K + off;

    const int wid = tid >> 5, lane = tid & 31;
    const int wm = wid >> 2, wn = wid & 3;
    const int l16 = lane & 15;

    float acc[4][4][4];
    #pragma unroll
    for (int mi = 0; mi < 4; mi++)
        #pragma unroll
        for (int ni = 0; ni < 4; ni++)
            #pragma unroll
            for (int r = 0; r < 4; r++) acc[mi][ni][r] = 0.f;

    const int sto = row * GM_PAD + off;
    uint4 ld[2][2];

    ld[0][0] = *(const uint4*)gp0;       ld[0][1] = *(const uint4*)(gp0 + 8);
    ld[1][0] = *(const uint4*)gp1;       ld[1][1] = *(const uint4*)(gp1 + 8);
    #pragma unroll
    for (int arr = 0; arr < 2; arr++) {
        *(uint4*)&smh[arr*GM_BUF + sto]     = ld[arr][0];
        *(uint4*)&smh[arr*GM_BUF + sto + 8] = ld[arr][1];
    }
    __syncthreads();

    const int NKT = K >> 5;
    for (int kt = 0; kt < NKT; kt++) {
        const int b = kt & 1;
        if (kt + 1 < NKT) {
            const int kb = (kt + 1) << 5;
            ld[0][0] = *(const uint4*)(gp0 + kb); ld[0][1] = *(const uint4*)(gp0 + kb + 8);
            ld[1][0] = *(const uint4*)(gp1 + kb); ld[1][1] = *(const uint4*)(gp1 + kb + 8);
        }

        const __half* sA = smh + b*(2*GM_BUF);
        const __half* sB = sA + GM_BUF;

        #pragma unroll
        for (int k16 = 0; k16 < 32; k16 += 16) {
            uint32_t af[4][4];
            #pragma unroll
            for (int mi = 0; mi < 4; mi++) {
                int roff = (wm*64 + mi*16 + l16) * GM_PAD + k16 + (lane >> 4) * 8;
                ldsm_x4(af[mi][0], af[mi][1], af[mi][2], af[mi][3], smem_u32(sA + roff));
            }
            #pragma unroll
            for (int ni = 0; ni < 4; ni++) {
                int boff = (wn*32 + ni*8 + (l16 & 7)) * GM_PAD + k16 + ((l16 >> 3) & 1) * 8;
                uint32_t b0, b1;
                ldsm_x2(b0, b1, smem_u32(sB + boff));
                #pragma unroll
                for (int mi = 0; mi < 4; mi++)
                    mma_f16_f32(acc[mi][ni], af[mi][0], af[mi][1], af[mi][2], af[mi][3], b0, b1);
            }
        }

        if (kt + 1 < NKT) {
            __half* dst = smh + (b ^ 1)*(2*GM_BUF);
            #pragma unroll
            for (int arr = 0; arr < 2; arr++) {
                *(uint4*)&dst[arr*GM_BUF + sto]     = ld[arr][0];
                *(uint4*)&dst[arr*GM_BUF + sto + 8] = ld[arr][1];
            }
        }
        __syncthreads();
    }

    const int g = lane >> 2, tg = lane & 3;
    #pragma unroll
    for (int mi = 0; mi < 4; mi++) {
        #pragma unroll
        for (int ni = 0; ni < 4; ni++) {
            int r0 = m0 + wm*64 + mi*16 + g;
            int c0 = n0 + wn*32 + ni*8 + tg*2;
            float2 lo = {acc[mi][ni][0], acc[mi][ni][1]};
            float2 hi = {acc[mi][ni][2], acc[mi][ni][3]};
            *(float2*)&C[(size_t)r0 * N + c0]       = lo;
            *(float2*)&C[(size_t)(r0 + 8) * N + c0] = hi;
        }
    }
}

// ---------------- RoPE + relu feature projection + fused kp rowsum -----------
__global__ void __launch_bounds__(128) ropeproj_kernel(
    const float* __restrict__ cosg, const float* __restrict__ sing,
    const float* __restrict__ proj)
{
    __shared__ float dat[64*68];   // [d][r]
    __shared__ float pj [64*68];   // [d][f]
    const int tid = threadIdx.x;
    const int rbase = blockIdx.x * 64;

    #pragma unroll
    for (int j = 0; j < 32; j++) {
        int i = tid + j*128;
        int f = i >> 6, d = i & 63;
        pj[d*68 + f] = proj[i];
    }
    #pragma unroll
    for (int j = 0; j < 32; j++) {
        int e = tid + j*128;
        int r = e >> 6, d = e & 63;
        int rho = rbase + r;
        int bs  = rho / 24;
        int h   = rho - bs*24;
        int s   = bs & (Sv-1);
        size_t base = (size_t)bs*QKVD + h*64;
        float val  = g_qkv[base + d];
        int   pd   = (d < 32) ? d + 32 : d - 32;
        float part = g_qkv[base + pd];
        float rot  = (d < 32) ? -part : part;
        dat[d*68 + r] = fmaf(val, cosg[s*64 + d], rot * sing[s*64 + d]);
    }
    __syncthreads();

    const int rq = tid >> 4, fq = tid & 15;
    float acc[8][4];
    #pragma unroll
    for (int i = 0; i < 8; i++)
        #pragma unroll
        for (int j = 0; j < 4; j++) acc[i][j] = 0.f;

    #pragma unroll
    for (int k = 0; k < 64; k++) {
        float4 a0 = *(const float4*)&dat[k*68 + rq*8];
        float4 a1 = *(const float4*)&dat[k*68 + rq*8 + 4];
        float4 bv = *(const float4*)&pj [k*68 + fq*4];
        float av[8] = {a0.x,a0.y,a0.z,a0.w,a1.x,a1.y,a1.z,a1.w};
        #pragma unroll
        for (int i = 0; i < 8; i++) {
            acc[i][0] = fmaf(av[i], bv.x, acc[i][0]);
            acc[i][1] = fmaf(av[i], bv.y, acc[i][1]);
            acc[i][2] = fmaf(av[i], bv.z, acc[i][2]);
            acc[i][3] = fmaf(av[i], bv.w, acc[i][3]);
        }
    }

    const float ratio = (float)(0.125 * (0.125 + 1e-4));
    #pragma unroll
    for (int i = 0; i < 8; i++) {
        int rho = rbase + rq*8 + i;
        int bs  = rho / 24;
        int h   = rho - bs*24;
        float4 o;
        o.x = fmaxf(acc[i][0]*ratio, 0.f);
        o.y = fmaxf(acc[i][1]*ratio, 0.f);
        o.z = fmaxf(acc[i][2]*ratio, 0.f);
        o.w = fmaxf(acc[i][3]*ratio, 0.f);

        float rs = (o.x + o.y) + (o.z + o.w);
        #pragma unroll
        for (int ofs = 1; ofs < 16; ofs <<= 1)
            rs += __shfl_xor_sync(0xffffffffu, rs, ofs);

        if (h < NHEAD) {
            o.x += 1e-4f; o.y += 1e-4f; o.z += 1e-4f; o.w += 1e-4f;
            *(float4*)&g_qp[((size_t)bs*NHEAD + h)*NFEAT + fq*4] = o;
        } else {
            int kvh = h - NHEAD;
            int b = bs >> 12, t = bs & 4095;
            if (fq == 0) g_z[((size_t)(b*NKVH + kvh))*Sv + t] = rs;
            *(float4*)&g_kp[((size_t)bs*NKVH + kvh)*NFEAT + fq*4] = o;
        }
    }
}

// ---------------- inclusive scan of g_z per (b,kvh), in place -----------------
__global__ void __launch_bounds__(256) zscan_kernel()
{
    const int bkv = blockIdx.x;
    const int tid = threadIdx.x;
    const int lane = tid & 31, warp = tid >> 5;
    __shared__ float wsum[8];
    float carry = 0.f;

    for (int tile = 0; tile < 16; tile++) {
        int t = tile*256 + tid;
        float x = g_z[(size_t)bkv*Sv + t];
        #pragma unroll
        for (int o = 1; o < 32; o <<= 1) {
            float n = __shfl_up_sync(0xffffffffu, x, o);
            if (lane >= o) x += n;
        }
        if (lane == 31) wsum[warp] = x;
        __syncthreads();
        float off = carry;
        for (int w2 = 0; w2 < warp; w2++) off += wsum[w2];
        g_z[(size_t)bkv*Sv + t] = off + x;
        float tot = 0.f;
        #pragma unroll
        for (int w2 = 0; w2 < 8; w2++) tot += wsum[w2];
        carry += tot;
        __syncthreads();
    }
}

// ---------------- per-chunk KV = Kp^T V (64x64) ------------------------------
__global__ void __launch_bounds__(256) chunkkv_kernel()
{
    extern __shared__ float cs[];
    float* Ks = cs;
    float* Vs = cs + 8192;
    const int c   = blockIdx.x;
    const int bkv = blockIdx.y;
    const int b   = bkv >> 3, kvh = bkv & 7;
    const int tid = threadIdx.x;

    #pragma unroll
    for (int j = 0; j < 32; j++) {
        int e = tid + j*256;
        int t = e >> 6, f = e & 63;
        size_t bs = (size_t)(b*Sv + c*CHUNK + t);
        Ks[e] = g_kp[(bs*NKVH + kvh)*NFEAT + f];
        Vs[e] = g_qkv[bs*QKVD + 1536 + kvh*64 + f];
    }
    __syncthreads();

    const int fq = tid >> 4, dq = tid & 15;
    float acc[4][4];
    #pragma unroll
    for (int i = 0; i < 4; i++)
        #pragma unroll
        for (int j = 0; j < 4; j++) acc[i][j] = 0.f;

    #pragma unroll 8
    for (int t = 0; t < 128; t++) {
        float4 a = *(const float4*)&Ks[t*64 + fq*4];
        float4 v = *(const float4*)&Vs[t*64 + dq*4];
        float av[4] = {a.x,a.y,a.z,a.w};
        #pragma unroll
        for (int i = 0; i < 4; i++) {
            acc[i][0] = fmaf(av[i], v.x, acc[i][0]);
            acc[i][1] = fmaf(av[i], v.y, acc[i][1]);
            acc[i][2] = fmaf(av[i], v.z, acc[i][2]);
            acc[i][3] = fmaf(av[i], v.w, acc[i][3]);
        }
    }
    size_t base = ((size_t)bkv*NCHUNK + c)*4096;
    #pragma unroll
    for (int i = 0; i < 4; i++) {
        float4 o = {acc[i][0], acc[i][1], acc[i][2], acc[i][3]};
        *(float4*)&g_kvc[base + (size_t)(fq*4 + i)*64 + dq*4] = o;
    }
}

// ---------------- exclusive chunk-prefix of KV, in place ---------------------
__global__ void __launch_bounds__(256) kvprefix_kernel()
{
    const int bkv = blockIdx.x;
    const int tid = threadIdx.x;
    float acc[16];
    #pragma unroll
    for (int j = 0; j < 16; j++) acc[j] = 0.f;
    for (int c = 0; c < NCHUNK; c++) {
        size_t base = ((size_t)bkv*NCHUNK + c)*4096;
        #pragma unroll
        for (int j = 0; j < 16; j++) {
            size_t idx = base + tid + j*256;
            float cur = g_kvc[idx];
            g_kvc[idx] = acc[j];
            acc[j] += cur;
        }
    }
}

// ---------------- stage D: 2-pass fp16 split causal combine ------------------
// Q and S split hi/lo (lo prescaled x2048); K, V, KVpref single fp16.
#define SD_QP  72
#define SD_SP  136
// halves offsets
#define O_QH   0
#define O_QL   9216
#define O_K    18432
#define O_V    27648
#define O_C    36864
#define O_SH   41472
#define O_SL   58880
#define SD_HALVES 76288
#define SD_BYTES  (SD_HALVES*2 + 512)

__global__ void __launch_bounds__(256) stage_d_kernel()
{
    extern __shared__ __half shd[];
    __half* sQh = shd + O_QH;
    __half* sQl = shd + O_QL;
    __half* sK  = shd + O_K;
    __half* sV  = shd + O_V;
    __half* sC  = shd + O_C;
    __half* sSh = shd + O_SH;
    __half* sSl = shd + O_SL;
    float* dinv = (float*)(shd + SD_HALVES);

    const int c   = blockIdx.x;
    const int h   = blockIdx.y;
    const int b   = blockIdx.z;
    const int kvh = h >> 1;
    const int tid = threadIdx.x;
    const size_t t0 = (size_t)b*Sv + c*CHUNK;

    // load + convert
    #pragma unroll
    for (int j = 0; j < 32; j++) {
        int e = tid + j*256;
        int t = e >> 6, f = e & 63;
        float q = g_qp[((t0 + t)*NHEAD + h)*NFEAT + f];
        float k = g_kp[((t0 + t)*NKVH + kvh)*NFEAT + f];
        float v = g_qkv[(t0 + t)*QKVD + 1536 + kvh*64 + f];
        __half qh = __float2half(q);
        sQh[t*SD_QP + f] = qh;
        sQl[t*SD_QP + f] = __float2half((q - __half2float(qh)) * LOSCALE);
        sK [t*SD_QP + f] = __float2half(k);
        sV [t*SD_QP + f] = __float2half(v);
    }
    #pragma unroll
    for (int j = 0; j < 16; j++) {
        int e = tid + j*256;
        int f = e >> 6, d = e & 63;
        float kv = g_kvc[(((size_t)(b*NKVH + kvh))*NCHUNK + c)*4096 + e];
        sC[f*SD_QP + d] = __float2half(kv);
    }
    __syncthreads();

    if (tid < 128) {
        float s = 0.f;
        #pragma unroll
        for (int f = 0; f < 64; f++)
            s += __half2float(sQh[tid*SD_QP + f])
               + __half2float(sQl[tid*SD_QP + f]) * LOINV;
        float z = g_z[((size_t)(b*NKVH + kvh))*Sv + c*CHUNK + tid];
        dinv[tid] = 1.0f / (s*z + 1e-6f);
    }
    __syncthreads();

    const int wid = tid >> 5, lane = tid & 31;
    const int l16 = lane & 15, g = lane >> 2, tg = lane & 3;
    const int mrow = wid * 16;
    const int ahalf = (lane >> 4) * 8;

    // phase 1: S = Qh*K + (Ql*K)/2048, tril mask, split-store to fp16 hi/lo
    {
        float accH[16][4], accL[16][4];
        #pragma unroll
        for (int nt = 0; nt < 16; nt++)
            #pragma unroll
            for (int r = 0; r < 4; r++) { accH[nt][r] = 0.f; accL[nt][r] = 0.f; }

        #pragma unroll
        for (int k16 = 0; k16 < 64; k16 += 16) {
            int ro = (mrow + l16)*SD_QP + k16 + ahalf;
            uint32_t qh0,qh1,qh2,qh3, ql0,ql1,ql2,ql3;
            ldsm_x4(qh0,qh1,qh2,qh3, smem_u32(sQh + ro));
            ldsm_x4(ql0,ql1,ql2,ql3, smem_u32(sQl + ro));
            #pragma unroll
            for (int nt = 0; nt < 16; nt++) {
                int bo = (nt*8 + (l16 & 7))*SD_QP + k16 + ((l16 >> 3) & 1)*8;
                uint32_t b0,b1;
                ldsm_x2(b0,b1, smem_u32(sK + bo));
                mma_f16_f32(accH[nt], qh0,qh1,qh2,qh3, b0,b1);
                mma_f16_f32(accL[nt], ql0,ql1,ql2,ql3, b0,b1);
            }
        }
        #pragma unroll
        for (int nt = 0; nt < 16; nt++) {
            int r0 = mrow + g, r1 = r0 + 8;
            int c0 = nt*8 + tg*2;
            float v00 = (c0     <= r0) ? fmaf(accL[nt][0], LOINV, accH[nt][0]) : 0.f;
            float v01 = (c0 + 1 <= r0) ? fmaf(accL[nt][1], LOINV, accH[nt][1]) : 0.f;
            float v10 = (c0     <= r1) ? fmaf(accL[nt][2], LOINV, accH[nt][2]) : 0.f;
            float v11 = (c0 + 1 <= r1) ? fmaf(accL[nt][3], LOINV, accH[nt][3]) : 0.f;
            __half h00 = __float2half(v00), h01 = __float2half(v01);
            __half h10 = __float2half(v10), h11 = __float2half(v11);
            *(uint32_t*)&sSh[r0*SD_SP + c0] =
                (uint32_t)__half_as_ushort(h00) | ((uint32_t)__half_as_ushort(h01) << 16);
            *(uint32_t*)&sSh[r1*SD_SP + c0] =
                (uint32_t)__half_as_ushort(h10) | ((uint32_t)__half_as_ushort(h11) << 16);
            *(uint32_t*)&sSl[r0*SD_SP + c0] =
                pack2h((v00 - __half2float(h00))*LOSCALE, (v01 - __half2float(h01))*LOSCALE);
            *(uint32_t*)&sSl[r1*SD_SP + c0] =
                pack2h((v10 - __half2float(h10))*LOSCALE, (v11 - __half2float(h11))*LOSCALE);
        }
    }
    __syncwarp();

    // phase 2: num = Sh*V + (Sl*V)/2048 + Qh*C + (Ql*C)/2048, scale, store fp16
    {
        float accH[8][4], accL[8][4];
        #pragma unroll
        for (int nt = 0; nt < 8; nt++)
            #pragma unroll
            for (int r = 0; r < 4; r++) { accH[nt][r] = 0.f; accL[nt][r] = 0.f; }

        #pragma unroll
        for (int k16 = 0; k16 < 128; k16 += 16) {
            int ro = (mrow + l16)*SD_SP + k16 + ahalf;
            uint32_t sh0,sh1,sh2,sh3, sl0,sl1,sl2,sl3;
            ldsm_x4(sh0,sh1,sh2,sh3, smem_u32(sSh + ro));
            ldsm_x4(sl0,sl1,sl2,sl3, smem_u32(sSl + ro));
            #pragma unroll
            for (int nt = 0; nt < 8; nt++) {
                int bo = (k16 + l16)*SD_QP + nt*8;
                uint32_t b0,b1;
                ldsm_x2_t(b0,b1, smem_u32(sV + bo));
                mma_f16_f32(accH[nt], sh0,sh1,sh2,sh3, b0,b1);
                mma_f16_f32(accL[nt], sl0,sl1,sl2,sl3, b0,b1);
            }
        }
        #pragma unroll
        for (int k16 = 0; k16 < 64; k16 += 16) {
            int ro = (mrow + l16)*SD_QP + k16 + ahalf;
            uint32_t qh0,qh1,qh2,qh3, ql0,ql1,ql2,ql3;
            ldsm_x4(qh0,qh1,qh2,qh3, smem_u32(sQh + ro));
            ldsm_x4(ql0,ql1,ql2,ql3, smem_u32(sQl + ro));
            #pragma unroll
            for (int nt = 0; nt < 8; nt++) {
                int bo = (k16 + l16)*SD_QP + nt*8;
                uint32_t b0,b1;
                ldsm_x2_t(b0,b1, smem_u32(sC + bo));
                mma_f16_f32(accH[nt], qh0,qh1,qh2,qh3, b0,b1);
                mma_f16_f32(accL[nt], ql0,ql1,ql2,ql3, b0,b1);
            }
        }

        const int r0 = mrow + g, r1 = r0 + 8;
        const float d0 = dinv[r0], d1 = dinv[r1];
        #pragma unroll
        for (int nt = 0; nt < 8; nt++) {
            int c0 = nt*8 + tg*2;
            float o00 = fmaf(accL[nt][0], LOINV, accH[nt][0]) * d0;
            float o01 = fmaf(accL[nt][1], LOINV, accH[nt][1]) * d0;
            float o10 = fmaf(accL[nt][2], LOINV, accH[nt][2]) * d1;
            float o11 = fmaf(accL[nt][3], LOINV, accH[nt][3]) * d1;
            size_t a0 = (t0 + r0)*1024 + h*64 + c0;
            size_t a1 = (t0 + r1)*1024 + h*64 + c0;
            *(uint32_t*)&g_ah[a0] = pack2h(o00, o01);
            *(uint32_t*)&g_ah[a1] = pack2h(o10, o11);
        }
    }
}

// ---------------- launch ------------------------------------------------------
extern "C" void kernel_launch(void* const* d_in, const int* in_sizes, int n_in,
                              void* d_out, int out_size)
{
    const float* hidden = (const float*)d_in[0];
    const float* cosg   = (const float*)d_in[1];
    const float* sing   = (const float*)d_in[2];
    const float* W_qkv  = (const float*)d_in[3];
    const float* W_o    = (const float*)d_in[4];
    const float* proj   = (const float*)d_in[5];
    float* out = (float*)d_out;

    static bool attr_done = false;
    if (!attr_done) {
        cudaFuncSetAttribute(chunkkv_kernel,
            cudaFuncAttributeMaxDynamicSharedMemorySize, 65536);
        cudaFuncSetAttribute(stage_d_kernel,
            cudaFuncAttributeMaxDynamicSharedMemorySize, SD_BYTES);
        cudaFuncSetAttribute(gemm_mma_kernel,
            cudaFuncAttributeMaxDynamicSharedMemorySize, GM_SMEM);
        attr_done = true;
    }

    float* qkv = nullptr; cudaGetSymbolAddress((void**)&qkv, g_qkv);
    __half *ah, *w1, *w2;
    cudaGetSymbolAddress((void**)&ah, g_ah);
    cudaGetSymbolAddress((void**)&w1, g_w1);
    cudaGetSymbolAddress((void**)&w2, g_w2);

    // 1. convert hidden + W_qkv to fp16, 1-pass QKV GEMM
    cvt_h_kernel<<<(MROWS*1024)/1024, 256>>>(hidden, ah, MROWS*1024);
    cvt_h_kernel<<<(2048*1024)/1024, 256>>>(W_qkv, w1, 2048*1024);
    gemm_mma_kernel<<<dim3(QKVD/128, MROWS/128), 256, GM_SMEM>>>(
        ah, w1, qkv, QKVD, 1024);

    // 2. rope + feature projection (+ fused kp rowsums into g_z)
    ropeproj_kernel<<<(MROWS*24)/64, 128>>>(cosg, sing, proj);
    // 3. z scan
    zscan_kernel<<<Bv*NKVH, 256>>>();
    // 4. per-chunk KV
    chunkkv_kernel<<<dim3(NCHUNK, Bv*NKVH), 256, 65536>>>();
    // 5. exclusive chunk prefix
    kvprefix_kernel<<<Bv*NKVH, 256>>>();
    // 6. causal combine (2-pass fp16 split) -> fp16 attn into g_ah
    stage_d_kernel<<<dim3(NCHUNK, NHEAD, Bv), 256, SD_BYTES>>>();

    // 7. convert W_o to fp16, 1-pass output GEMM
    cvt_h_kernel<<<(1024*1024)/1024, 256>>>(W_o, w2, 1024*1024);
    gemm_mma_kernel<<<dim3(1024/128, MROWS/128), 256, GM_SMEM>>>(
        ah, w2, out, 1024, 1024);
}

// round 15
// speedup vs baseline: 3.3804x; 1.0950x over previous
#include <cuda_runtime.h>
#include <cuda_bf16.h>
#include <cuda_fp16.h>
#include <cstdint>

#define Bv      2
#define Sv      4096
#define QKVD    2048
#define NHEAD   16
#define NKVH    8
#define HDIM    64
#define NFEAT   64
#define CHUNK   128
#define NCHUNK  32
#define MROWS   (Bv*Sv)
#define LOSCALE 2048.0f
#define LOINV   (1.0f/2048.0f)

// ---------------- scratch (device globals; no allocs allowed) ----------------
__device__ float g_qkv [(size_t)MROWS*QKVD];
__device__ float g_qp  [(size_t)MROWS*NHEAD*NFEAT];
__device__ float g_kp  [(size_t)MROWS*NKVH*NFEAT];
__device__ float g_z   [(size_t)Bv*NKVH*Sv];
__device__ float g_kvc [(size_t)Bv*NKVH*NCHUNK*NFEAT*HDIM];

__device__ __half g_ah [(size_t)MROWS*1024];     // activations fp16
__device__ __half g_w1 [(size_t)2048*1024];      // W_qkv fp16
__device__ __half g_w2 [(size_t)1024*1024];      // W_o fp16

// ---------------- PTX helpers -------------------------------------------------
__device__ __forceinline__ uint32_t smem_u32(const void* p) {
    uint32_t a;
    asm("{ .reg .u64 t; cvta.to.shared.u64 t, %1; cvt.u32.u64 %0, t; }" : "=r"(a) : "l"(p));
    return a;
}
__device__ __forceinline__ void ldsm_x4(uint32_t& r0, uint32_t& r1,
                                        uint32_t& r2, uint32_t& r3, uint32_t a) {
    asm volatile("ldmatrix.sync.aligned.m8n8.x4.shared.b16 {%0,%1,%2,%3}, [%4];"
                 : "=r"(r0), "=r"(r1), "=r"(r2), "=r"(r3) : "r"(a));
}
__device__ __forceinline__ void ldsm_x2(uint32_t& r0, uint32_t& r1, uint32_t a) {
    asm volatile("ldmatrix.sync.aligned.m8n8.x2.shared.b16 {%0,%1}, [%2];"
                 : "=r"(r0), "=r"(r1) : "r"(a));
}
__device__ __forceinline__ void ldsm_x2_t(uint32_t& r0, uint32_t& r1, uint32_t a) {
    asm volatile("ldmatrix.sync.aligned.m8n8.x2.trans.shared.b16 {%0,%1}, [%2];"
                 : "=r"(r0), "=r"(r1) : "r"(a));
}
__device__ __forceinline__ void mma_f16_f32(float* d,
    uint32_t a0, uint32_t a1, uint32_t a2, uint32_t a3, uint32_t b0, uint32_t b1) {
    asm volatile(
        "mma.sync.aligned.m16n8k16.row.col.f32.f16.f16.f32 "
        "{%0,%1,%2,%3}, {%4,%5,%6,%7}, {%8,%9}, {%0,%1,%2,%3};"
        : "+f"(d[0]), "+f"(d[1]), "+f"(d[2]), "+f"(d[3])
        : "r"(a0), "r"(a1), "r"(a2), "r"(a3), "r"(b0), "r"(b1));
}
__device__ __forceinline__ uint32_t pack2h(float x, float y) {
    __half hx = __float2half(x), hy = __float2half(y);
    return (uint32_t)__half_as_ushort(hx) |
           ((uint32_t)__half_as_ushort(hy) << 16);
}

// ---------------- fp32 -> fp16 convert ----------------------------------------
__global__ void __launch_bounds__(256) cvt_h_kernel(
    const float* __restrict__ src, __half* __restrict__ dst, int n)
{
    int i = (blockIdx.x * 256 + threadIdx.x) * 4;
    if (i >= n) return;
    float4 v = *(const float4*)(src + i);
    __half2* dp = (__half2*)(dst + i);
    dp[0] = __half2(__float2half(v.x), __float2half(v.y));
    dp[1] = __half2(__float2half(v.z), __float2half(v.w));
}

// ---------------- mma.sync GEMM (1-pass fp16): C = A[M,K] * B[N,K]^T ----------
#define GM_PAD  40
#define GM_BUF  (128*GM_PAD)
#define GM_SMEM (2*2*GM_BUF*2)

__global__ void __launch_bounds__(256) gemm_mma_kernel(
    const __half* __restrict__ A, const __half* __restrict__ B,
    float* __restrict__ C, int N, int K)
{
    extern __shared__ __half smh[];
    const int tid = threadIdx.x;
    const int m0 = blockIdx.y * 128, n0 = blockIdx.x * 128;
    const int row = tid >> 1, off = (tid & 1) * 16;

    const __half* gp0 = A + (size_t)(m0 + row) * K + off;
    const __half* gp1 = B + (size_t)(n0 + row) * K + off;

    const int wid = tid >> 5, lane = tid & 31;
    const int wm = wid >> 2, wn = wid & 3;
    const int l16 = lane & 15;

    float acc[4][4][4];
    #pragma unroll
    for (int mi = 0; mi < 4; mi++)
        #pragma unroll
        for (int ni = 0; ni < 4; ni++)
            #pragma unroll
            for (int r = 0; r < 4; r++) acc[mi][ni][r] = 0.f;

    const int sto = row * GM_PAD + off;
    uint4 ld[2][2];

    ld[0][0] = *(const uint4*)gp0;       ld[0][1] = *(const uint4*)(gp0 + 8);
    ld[1][0] = *(const uint4*)gp1;       ld[1][1] = *(const uint4*)(gp1 + 8);
    #pragma unroll
    for (int arr = 0; arr < 2; arr++) {
        *(uint4*)&smh[arr*GM_BUF + sto]     = ld[arr][0];
        *(uint4*)&smh[arr*GM_BUF + sto + 8] = ld[arr][1];
    }
    __syncthreads();

    const int NKT = K >> 5;
    for (int kt = 0; kt < NKT; kt++) {
        const int b = kt & 1;
        if (kt + 1 < NKT) {
            const int kb = (kt + 1) << 5;
            ld[0][0] = *(const uint4*)(gp0 + kb); ld[0][1] = *(const uint4*)(gp0 + kb + 8);
            ld[1][0] = *(const uint4*)(gp1 + kb); ld[1][1] = *(const uint4*)(gp1 + kb + 8);
        }

        const __half* sA = smh + b*(2*GM_BUF);
        const __half* sB = sA + GM_BUF;

        #pragma unroll
        for (int k16 = 0; k16 < 32; k16 += 16) {
            uint32_t af[4][4];
            #pragma unroll
            for (int mi = 0; mi < 4; mi++) {
                int roff = (wm*64 + mi*16 + l16) * GM_PAD + k16 + (lane >> 4) * 8;
                ldsm_x4(af[mi][0], af[mi][1], af[mi][2], af[mi][3], smem_u32(sA + roff));
            }
            #pragma unroll
            for (int ni = 0; ni < 4; ni++) {
                int boff = (wn*32 + ni*8 + (l16 & 7)) * GM_PAD + k16 + ((l16 >> 3) & 1) * 8;
                uint32_t b0, b1;
                ldsm_x2(b0, b1, smem_u32(sB + boff));
                #pragma unroll
                for (int mi = 0; mi < 4; mi++)
                    mma_f16_f32(acc[mi][ni], af[mi][0], af[mi][1], af[mi][2], af[mi][3], b0, b1);
            }
        }

        if (kt + 1 < NKT) {
            __half* dst = smh + (b ^ 1)*(2*GM_BUF);
            #pragma unroll
            for (int arr = 0; arr < 2; arr++) {
                *(uint4*)&dst[arr*GM_BUF + sto]     = ld[arr][0];
                *(uint4*)&dst[arr*GM_BUF + sto + 8] = ld[arr][1];
            }
        }
        __syncthreads();
    }

    const int g = lane >> 2, tg = lane & 3;
    #pragma unroll
    for (int mi = 0; mi < 4; mi++) {
        #pragma unroll
        for (int ni = 0; ni < 4; ni++) {
            int r0 = m0 + wm*64 + mi*16 + g;
            int c0 = n0 + wn*32 + ni*8 + tg*2;
            float2 lo = {acc[mi][ni][0], acc[mi][ni][1]};
            float2 hi = {acc[mi][ni][2], acc[mi][ni][3]};
            *(float2*)&C[(size_t)r0 * N + c0]       = lo;
            *(float2*)&C[(size_t)(r0 + 8) * N + c0] = hi;
        }
    }
}

// ---------------- RoPE + relu feature projection on tensor cores -------------
// Per block: 64 rows (b*s*head flattened), 64 feats, 64 dims.
// dat fp16 [r][d] built by RoPE in fp32; proj fp16 [f][d]; mma.sync matmul;
// fused rowsum (for z) via quad shfl; fp32 outputs unchanged.
#define RP_P 72
__global__ void __launch_bounds__(128) ropeproj_kernel(
    const float* __restrict__ cosg, const float* __restrict__ sing,
    const float* __restrict__ proj)
{
    __shared__ __half dat[64*RP_P];
    __shared__ __half pj [64*RP_P];
    const int tid = threadIdx.x;
    const int rbase = blockIdx.x * 64;

    #pragma unroll
    for (int j = 0; j < 32; j++) {
        int i = tid + j*128;
        int f = i >> 6, d = i & 63;
        pj[f*RP_P + d] = __float2half(proj[i]);
    }
    // RoPE: each iteration handles one (d, d+32) pair of one row.
    #pragma unroll
    for (int j = 0; j < 16; j++) {
        int e = tid + j*128;            // 0..2047
        int r = e >> 5, d = e & 31;
        int rho = rbase + r;
        int bs  = rho / 24;
        int h   = rho - bs*24;
        int s   = bs & (Sv-1);
        size_t base = (size_t)bs*QKVD + h*64;
        float x1 = g_qkv[base + d];
        float x2 = g_qkv[base + d + 32];
        float cc = cosg[s*64 + d];
        float ss = sing[s*64 + d];
        dat[r*RP_P + d]      = __float2half(fmaf(x1, cc, -x2 * ss));
        dat[r*RP_P + d + 32] = __float2half(fmaf(x2, cc,  x1 * ss));
    }
    __syncthreads();

    const int wid = tid >> 5, lane = tid & 31;
    const int l16 = lane & 15, g = lane >> 2, tg = lane & 3;
    const int mrow = wid * 16;
    const int ahalf = (lane >> 4) * 8;

    float acc[8][4];
    #pragma unroll
    for (int nt = 0; nt < 8; nt++)
        #pragma unroll
        for (int r = 0; r < 4; r++) acc[nt][r] = 0.f;

    #pragma unroll
    for (int k16 = 0; k16 < 64; k16 += 16) {
        int ro = (mrow + l16)*RP_P + k16 + ahalf;
        uint32_t a0,a1,a2,a3;
        ldsm_x4(a0,a1,a2,a3, smem_u32(dat + ro));
        #pragma unroll
        for (int nt = 0; nt < 8; nt++) {
            int bo = (nt*8 + (l16 & 7))*RP_P + k16 + ((l16 >> 3) & 1)*8;
            uint32_t b0,b1;
            ldsm_x2(b0,b1, smem_u32(pj + bo));
            mma_f16_f32(acc[nt], a0,a1,a2,a3, b0,b1);
        }
    }

    // epilogue: relu*ratio, rowsum, q/k routing (fp32 outputs)
    const float ratio = (float)(0.125 * (0.125 + 1e-4));
    float o[8][4];
    float rs0 = 0.f, rs1 = 0.f;
    #pragma unroll
    for (int nt = 0; nt < 8; nt++) {
        o[nt][0] = fmaxf(acc[nt][0]*ratio, 0.f);
        o[nt][1] = fmaxf(acc[nt][1]*ratio, 0.f);
        o[nt][2] = fmaxf(acc[nt][2]*ratio, 0.f);
        o[nt][3] = fmaxf(acc[nt][3]*ratio, 0.f);
        rs0 += o[nt][0] + o[nt][1];
        rs1 += o[nt][2] + o[nt][3];
    }
    rs0 += __shfl_xor_sync(0xffffffffu, rs0, 1);
    rs0 += __shfl_xor_sync(0xffffffffu, rs0, 2);
    rs1 += __shfl_xor_sync(0xffffffffu, rs1, 1);
    rs1 += __shfl_xor_sync(0xffffffffu, rs1, 2);

    #pragma unroll
    for (int half = 0; half < 2; half++) {
        int r   = mrow + g + half*8;
        int rho = rbase + r;
        int bs  = rho / 24;
        int h   = rho - bs*24;
        float rs = half ? rs1 : rs0;
        if (h < NHEAD) {
            float* dst = &g_qp[((size_t)bs*NHEAD + h)*NFEAT];
            #pragma unroll
            for (int nt = 0; nt < 8; nt++) {
                float2 v = {o[nt][half*2] + 1e-4f, o[nt][half*2+1] + 1e-4f};
                *(float2*)&dst[nt*8 + tg*2] = v;
            }
        } else {
            int kvh = h - NHEAD;
            int b = bs >> 12, t = bs & 4095;
            float* dst = &g_kp[((size_t)bs*NKVH + kvh)*NFEAT];
            #pragma unroll
            for (int nt = 0; nt < 8; nt++) {
                float2 v = {o[nt][half*2], o[nt][half*2+1]};
                *(float2*)&dst[nt*8 + tg*2] = v;
            }
            if (tg == 0) g_z[((size_t)(b*NKVH + kvh))*Sv + t] = rs;
        }
    }
}

// ---------------- inclusive scan of g_z per (b,kvh), in place -----------------
__global__ void __launch_bounds__(256) zscan_kernel()
{
    const int bkv = blockIdx.x;
    const int tid = threadIdx.x;
    const int lane = tid & 31, warp = tid >> 5;
    __shared__ float wsum[8];
    float carry = 0.f;

    for (int tile = 0; tile < 16; tile++) {
        int t = tile*256 + tid;
        float x = g_z[(size_t)bkv*Sv + t];
        #pragma unroll
        for (int o = 1; o < 32; o <<= 1) {
            float n = __shfl_up_sync(0xffffffffu, x, o);
            if (lane >= o) x += n;
        }
        if (lane == 31) wsum[warp] = x;
        __syncthreads();
        float off = carry;
        for (int w2 = 0; w2 < warp; w2++) off += wsum[w2];
        g_z[(size_t)bkv*Sv + t] = off + x;
        float tot = 0.f;
        #pragma unroll
        for (int w2 = 0; w2 < 8; w2++) tot += wsum[w2];
        carry += tot;
        __syncthreads();
    }
}

// ---------------- per-chunk KV = Kp^T V (64x64) ------------------------------
__global__ void __launch_bounds__(256) chunkkv_kernel()
{
    extern __shared__ float cs[];
    float* Ks = cs;
    float* Vs = cs + 8192;
    const int c   = blockIdx.x;
    const int bkv = blockIdx.y;
    const int b   = bkv >> 3, kvh = bkv & 7;
    const int tid = threadIdx.x;

    #pragma unroll
    for (int j = 0; j < 32; j++) {
        int e = tid + j*256;
        int t = e >> 6, f = e & 63;
        size_t bs = (size_t)(b*Sv + c*CHUNK + t);
        Ks[e] = g_kp[(bs*NKVH + kvh)*NFEAT + f];
        Vs[e] = g_qkv[bs*QKVD + 1536 + kvh*64 + f];
    }
    __syncthreads();

    const int fq = tid >> 4, dq = tid & 15;
    float acc[4][4];
    #pragma unroll
    for (int i = 0; i < 4; i++)
        #pragma unroll
        for (int j = 0; j < 4; j++) acc[i][j] = 0.f;

    #pragma unroll 8
    for (int t = 0; t < 128; t++) {
        float4 a = *(const float4*)&Ks[t*64 + fq*4];
        float4 v = *(const float4*)&Vs[t*64 + dq*4];
        float av[4] = {a.x,a.y,a.z,a.w};
        #pragma unroll
        for (int i = 0; i < 4; i++) {
            acc[i][0] = fmaf(av[i], v.x, acc[i][0]);
            acc[i][1] = fmaf(av[i], v.y, acc[i][1]);
            acc[i][2] = fmaf(av[i], v.z, acc[i][2]);
            acc[i][3] = fmaf(av[i], v.w, acc[i][3]);
        }
    }
    size_t base = ((size_t)bkv*NCHUNK + c)*4096;
    #pragma unroll
    for (int i = 0; i < 4; i++) {
        float4 o = {acc[i][0], acc[i][1], acc[i][2], acc[i][3]};
        *(float4*)&g_kvc[base + (size_t)(fq*4 + i)*64 + dq*4] = o;
    }
}

// ---------------- exclusive chunk-prefix of KV, in place ---------------------
__global__ void __launch_bounds__(256) kvprefix_kernel()
{
    const int bkv = blockIdx.x;
    const int tid = threadIdx.x;
    float acc[16];
    #pragma unroll
    for (int j = 0; j < 16; j++) acc[j] = 0.f;
    for (int c = 0; c < NCHUNK; c++) {
        size_t base = ((size_t)bkv*NCHUNK + c)*4096;
        #pragma unroll
        for (int j = 0; j < 16; j++) {
            size_t idx = base + tid + j*256;
            float cur = g_kvc[idx];
            g_kvc[idx] = acc[j];
            acc[j] += cur;
        }
    }
}

// ---------------- stage D: 2-pass fp16 split causal combine ------------------
#define SD_QP  72
#define SD_SP  136
#define O_QH   0
#define O_QL   9216
#define O_K    18432
#define O_V    27648
#define O_C    36864
#define O_SH   41472
#define O_SL   58880
#define SD_HALVES 76288
#define SD_BYTES  (SD_HALVES*2 + 512)

__global__ void __launch_bounds__(256) stage_d_kernel()
{
    extern __shared__ __half shd[];
    __half* sQh = shd + O_QH;
    __half* sQl = shd + O_QL;
    __half* sK  = shd + O_K;
    __half* sV  = shd + O_V;
    __half* sC  = shd + O_C;
    __half* sSh = shd + O_SH;
    __half* sSl = shd + O_SL;
    float* dinv = (float*)(shd + SD_HALVES);

    const int c   = blockIdx.x;
    const int h   = blockIdx.y;
    const int b   = blockIdx.z;
    const int kvh = h >> 1;
    const int tid = threadIdx.x;
    const size_t t0 = (size_t)b*Sv + c*CHUNK;

    #pragma unroll
    for (int j = 0; j < 32; j++) {
        int e = tid + j*256;
        int t = e >> 6, f = e & 63;
        float q = g_qp[((t0 + t)*NHEAD + h)*NFEAT + f];
        float k = g_kp[((t0 + t)*NKVH + kvh)*NFEAT + f];
        float v = g_qkv[(t0 + t)*QKVD + 1536 + kvh*64 + f];
        __half qh = __float2half(q);
        sQh[t*SD_QP + f] = qh;
        sQl[t*SD_QP + f] = __float2half((q - __half2float(qh)) * LOSCALE);
        sK [t*SD_QP + f] = __float2half(k);
        sV [t*SD_QP + f] = __float2half(v);
    }
    #pragma unroll
    for (int j = 0; j < 16; j++) {
        int e = tid + j*256;
        int f = e >> 6, d = e & 63;
        float kv = g_kvc[(((size_t)(b*NKVH + kvh))*NCHUNK + c)*4096 + e];
        sC[f*SD_QP + d] = __float2half(kv);
    }
    __syncthreads();

    if (tid < 128) {
        float s = 0.f;
        #pragma unroll
        for (int f = 0; f < 64; f++)
            s += __half2float(sQh[tid*SD_QP + f])
               + __half2float(sQl[tid*SD_QP + f]) * LOINV;
        float z = g_z[((size_t)(b*NKVH + kvh))*Sv + c*CHUNK + tid];
        dinv[tid] = 1.0f / (s*z + 1e-6f);
    }
    __syncthreads();

    const int wid = tid >> 5, lane = tid & 31;
    const int l16 = lane & 15, g = lane >> 2, tg = lane & 3;
    const int mrow = wid * 16;
    const int ahalf = (lane >> 4) * 8;

    {
        float accH[16][4], accL[16][4];
        #pragma unroll
        for (int nt = 0; nt < 16; nt++)
            #pragma unroll
            for (int r = 0; r < 4; r++) { accH[nt][r] = 0.f; accL[nt][r] = 0.f; }

        #pragma unroll
        for (int k16 = 0; k16 < 64; k16 += 16) {
            int ro = (mrow + l16)*SD_QP + k16 + ahalf;
            uint32_t qh0,qh1,qh2,qh3, ql0,ql1,ql2,ql3;
            ldsm_x4(qh0,qh1,qh2,qh3, smem_u32(sQh + ro));
            ldsm_x4(ql0,ql1,ql2,ql3, smem_u32(sQl + ro));
            #pragma unroll
            for (int nt = 0; nt < 16; nt++) {
                int bo = (nt*8 + (l16 & 7))*SD_QP + k16 + ((l16 >> 3) & 1)*8;
                uint32_t b0,b1;
                ldsm_x2(b0,b1, smem_u32(sK + bo));
                mma_f16_f32(accH[nt], qh0,qh1,qh2,qh3, b0,b1);
                mma_f16_f32(accL[nt], ql0,ql1,ql2,ql3, b0,b1);
            }
        }
        #pragma unroll
        for (int nt = 0; nt < 16; nt++) {
            int r0 = mrow + g, r1 = r0 + 8;
            int c0 = nt*8 + tg*2;
            float v00 = (c0     <= r0) ? fmaf(accL[nt][0], LOINV, accH[nt][0]) : 0.f;
            float v01 = (c0 + 1 <= r0) ? fmaf(accL[nt][1], LOINV, accH[nt][1]) : 0.f;
            float v10 = (c0     <= r1) ? fmaf(accL[nt][2], LOINV, accH[nt][2]) : 0.f;
            float v11 = (c0 + 1 <= r1) ? fmaf(accL[nt][3], LOINV, accH[nt][3]) : 0.f;
            __half h00 = __float2half(v00), h01 = __float2half(v01);
            __half h10 = __float2half(v10), h11 = __float2half(v11);
            *(uint32_t*)&sSh[r0*SD_SP + c0] =
                (uint32_t)__half_as_ushort(h00) | ((uint32_t)__half_as_ushort(h01) << 16);
            *(uint32_t*)&sSh[r1*SD_SP + c0] =
                (uint32_t)__half_as_ushort(h10) | ((uint32_t)__half_as_ushort(h11) << 16);
            *(uint32_t*)&sSl[r0*SD_SP + c0] =
                pack2h((v00 - __half2float(h00))*LOSCALE, (v01 - __half2float(h01))*LOSCALE);
            *(uint32_t*)&sSl[r1*SD_SP + c0] =
                pack2h((v10 - __half2float(h10))*LOSCALE, (v11 - __half2float(h11))*LOSCALE);
        }
    }
    __syncwarp();

    {
        float accH[8][4], accL[8][4];
        #pragma unroll
        for (int nt = 0; nt < 8; nt++)
            #pragma unroll
            for (int r = 0; r < 4; r++) { accH[nt][r] = 0.f; accL[nt][r] = 0.f; }

        #pragma unroll
        for (int k16 = 0; k16 < 128; k16 += 16) {
            int ro = (mrow + l16)*SD_SP + k16 + ahalf;
            uint32_t sh0,sh1,sh2,sh3, sl0,sl1,sl2,sl3;
            ldsm_x4(sh0,sh1,sh2,sh3, smem_u32(sSh + ro));
            ldsm_x4(sl0,sl1,sl2,sl3, smem_u32(sSl + ro));
            #pragma unroll
            for (int nt = 0; nt < 8; nt++) {
                int bo = (k16 + l16)*SD_QP + nt*8;
                uint32_t b0,b1;
                ldsm_x2_t(b0,b1, smem_u32(sV + bo));
                mma_f16_f32(accH[nt], sh0,sh1,sh2,sh3, b0,b1);
                mma_f16_f32(accL[nt], sl0,sl1,sl2,sl3, b0,b1);
            }
        }
        #pragma unroll
        for (int k16 = 0; k16 < 64; k16 += 16) {
            int ro = (mrow + l16)*SD_QP + k16 + ahalf;
            uint32_t qh0,qh1,qh2,qh3, ql0,ql1,ql2,ql3;
            ldsm_x4(qh0,qh1,qh2,qh3, smem_u32(sQh + ro));
            ldsm_x4(ql0,ql1,ql2,ql3, smem_u32(sQl + ro));
            #pragma unroll
            for (int nt = 0; nt < 8; nt++) {
                int bo = (k16 + l16)*SD_QP + nt*8;
                uint32_t b0,b1;
                ldsm_x2_t(b0,b1, smem_u32(sC + bo));
                mma_f16_f32(accH[nt], qh0,qh1,qh2,qh3, b0,b1);
                mma_f16_f32(accL[nt], ql0,ql1,ql2,ql3, b0,b1);
            }
        }

        const int r0 = mrow + g, r1 = r0 + 8;
        const float d0 = dinv[r0], d1 = dinv[r1];
        #pragma unroll
        for (int nt = 0; nt < 8; nt++) {
            int c0 = nt*8 + tg*2;
            float o00 = fmaf(accL[nt][0], LOINV, accH[nt][0]) * d0;
            float o01 = fmaf(accL[nt][1], LOINV, accH[nt][1]) * d0;
            float o10 = fmaf(accL[nt][2], LOINV, accH[nt][2]) * d1;
            float o11 = fmaf(accL[nt][3], LOINV, accH[nt][3]) * d1;
            size_t a0 = (t0 + r0)*1024 + h*64 + c0;
            size_t a1 = (t0 + r1)*1024 + h*64 + c0;
            *(uint32_t*)&g_ah[a0] = pack2h(o00, o01);
            *(uint32_t*)&g_ah[a1] = pack2h(o10, o11);
        }
    }
}

// ---------------- launch ------------------------------------------------------
extern "C" void kernel_launch(void* const* d_in, const int* in_sizes, int n_in,
                              void* d_out, int out_size)
{
    const float* hidden = (const float*)d_in[0];
    const float* cosg   = (const float*)d_in[1];
    const float* sing   = (const float*)d_in[2];
    const float* W_qkv  = (const float*)d_in[3];
    const float* W_o    = (const float*)d_in[4];
    const float* proj   = (const float*)d_in[5];
    float* out = (float*)d_out;

    static bool attr_done = false;
    if (!attr_done) {
        cudaFuncSetAttribute(chunkkv_kernel,
            cudaFuncAttributeMaxDynamicSharedMemorySize, 65536);
        cudaFuncSetAttribute(stage_d_kernel,
            cudaFuncAttributeMaxDynamicSharedMemorySize, SD_BYTES);
        cudaFuncSetAttribute(gemm_mma_kernel,
            cudaFuncAttributeMaxDynamicSharedMemorySize, GM_SMEM);
        attr_done = true;
    }

    float* qkv = nullptr; cudaGetSymbolAddress((void**)&qkv, g_qkv);
    __half *ah, *w1, *w2;
    cudaGetSymbolAddress((void**)&ah, g_ah);
    cudaGetSymbolAddress((void**)&w1, g_w1);
    cudaGetSymbolAddress((void**)&w2, g_w2);

    // 1. convert hidden + W_qkv to fp16, 1-pass QKV GEMM
    cvt_h_kernel<<<(MROWS*1024)/1024, 256>>>(hidden, ah, MROWS*1024);
    cvt_h_kernel<<<(2048*1024)/1024, 256>>>(W_qkv, w1, 2048*1024);
    gemm_mma_kernel<<<dim3(QKVD/128, MROWS/128), 256, GM_SMEM>>>(
        ah, w1, qkv, QKVD, 1024);

    // 2. rope + feature projection on tensor cores (+ fused kp rowsums)
    ropeproj_kernel<<<(MROWS*24)/64, 128>>>(cosg, sing, proj);
    // 3. z scan
    zscan_kernel<<<Bv*NKVH, 256>>>();
    // 4. per-chunk KV
    chunkkv_kernel<<<dim3(NCHUNK, Bv*NKVH), 256, 65536>>>();
    // 5. exclusive chunk prefix
    kvprefix_kernel<<<Bv*NKVH, 256>>>();
    // 6. causal combine (2-pass fp16 split) -> fp16 attn into g_ah
    stage_d_kernel<<<dim3(NCHUNK, NHEAD, Bv), 256, SD_BYTES>>>();

    // 7. convert W_o to fp16, 1-pass output GEMM
    cvt_h_kernel<<<(1024*1024)/1024, 256>>>(W_o, w2, 1024*1024);
    gemm_mma_kernel<<<dim3(1024/128, MROWS/128), 256, GM_SMEM>>>(
        ah, w2, out, 1024, 1024);
}

// round 16
// speedup vs baseline: 3.6732x; 1.0866x over previous
#include <cuda_runtime.h>
#include <cuda_bf16.h>
#include <cuda_fp16.h>
#include <cstdint>

#define Bv      2
#define Sv      4096
#define QKVD    2048
#define NHEAD   16
#define NKVH    8
#define HDIM    64
#define NFEAT   64
#define CHUNK   128
#define NCHUNK  32
#define MROWS   (Bv*Sv)

// ---------------- scratch (device globals; no allocs allowed) ----------------
__device__ float g_qkv [(size_t)MROWS*QKVD];
__device__ float g_qp  [(size_t)MROWS*NHEAD*NFEAT];
__device__ float g_kp  [(size_t)MROWS*NKVH*NFEAT];
__device__ float g_z   [(size_t)Bv*NKVH*Sv];
__device__ float g_kvc [(size_t)Bv*NKVH*NCHUNK*NFEAT*HDIM];

__device__ __half g_ah [(size_t)MROWS*1024];     // activations fp16
__device__ __half g_w1 [(size_t)2048*1024];      // W_qkv fp16
__device__ __half g_w2 [(size_t)1024*1024];      // W_o fp16

// ---------------- PTX helpers -------------------------------------------------
__device__ __forceinline__ uint32_t smem_u32(const void* p) {
    uint32_t a;
    asm("{ .reg .u64 t; cvta.to.shared.u64 t, %1; cvt.u32.u64 %0, t; }" : "=r"(a) : "l"(p));
    return a;
}
__device__ __forceinline__ void ldsm_x4(uint32_t& r0, uint32_t& r1,
                                        uint32_t& r2, uint32_t& r3, uint32_t a) {
    asm volatile("ldmatrix.sync.aligned.m8n8.x4.shared.b16 {%0,%1,%2,%3}, [%4];"
                 : "=r"(r0), "=r"(r1), "=r"(r2), "=r"(r3) : "r"(a));
}
__device__ __forceinline__ void ldsm_x2(uint32_t& r0, uint32_t& r1, uint32_t a) {
    asm volatile("ldmatrix.sync.aligned.m8n8.x2.shared.b16 {%0,%1}, [%2];"
                 : "=r"(r0), "=r"(r1) : "r"(a));
}
__device__ __forceinline__ void ldsm_x2_t(uint32_t& r0, uint32_t& r1, uint32_t a) {
    asm volatile("ldmatrix.sync.aligned.m8n8.x2.trans.shared.b16 {%0,%1}, [%2];"
                 : "=r"(r0), "=r"(r1) : "r"(a));
}
__device__ __forceinline__ void mma_f16_f32(float* d,
    uint32_t a0, uint32_t a1, uint32_t a2, uint32_t a3, uint32_t b0, uint32_t b1) {
    asm volatile(
        "mma.sync.aligned.m16n8k16.row.col.f32.f16.f16.f32 "
        "{%0,%1,%2,%3}, {%4,%5,%6,%7}, {%8,%9}, {%0,%1,%2,%3};"
        : "+f"(d[0]), "+f"(d[1]), "+f"(d[2]), "+f"(d[3])
        : "r"(a0), "r"(a1), "r"(a2), "r"(a3), "r"(b0), "r"(b1));
}
__device__ __forceinline__ uint32_t pack2h(float x, float y) {
    __half hx = __float2half(x), hy = __float2half(y);
    return (uint32_t)__half_as_ushort(hx) |
           ((uint32_t)__half_as_ushort(hy) << 16);
}

// ---------------- fp32 -> fp16 convert ----------------------------------------
__global__ void __launch_bounds__(256) cvt_h_kernel(
    const float* __restrict__ src, __half* __restrict__ dst, int n)
{
    int i = (blockIdx.x * 256 + threadIdx.x) * 4;
    if (i >= n) return;
    float4 v = *(const float4*)(src + i);
    __half2* dp = (__half2*)(dst + i);
    dp[0] = __half2(__float2half(v.x), __float2half(v.y));
    dp[1] = __half2(__float2half(v.z), __float2half(v.w));
}

// ---------------- mma.sync GEMM (1-pass fp16): C = A[M,K] * B[N,K]^T ----------
#define GM_PAD  40
#define GM_BUF  (128*GM_PAD)
#define GM_SMEM (2*2*GM_BUF*2)

__global__ void __launch_bounds__(256) gemm_mma_kernel(
    const __half* __restrict__ A, const __half* __restrict__ B,
    float* __restrict__ C, int N, int K)
{
    extern __shared__ __half smh[];
    const int tid = threadIdx.x;
    const int m0 = blockIdx.y * 128, n0 = blockIdx.x * 128;
    const int row = tid >> 1, off = (tid & 1) * 16;

    const __half* gp0 = A + (size_t)(m0 + row) * K + off;
    const __half* gp1 = B + (size_t)(n0 + row) * K + off;

    const int wid = tid >> 5, lane = tid & 31;
    const int wm = wid >> 2, wn = wid & 3;
    const int l16 = lane & 15;

    float acc[4][4][4];
    #pragma unroll
    for (int mi = 0; mi < 4; mi++)
        #pragma unroll
        for (int ni = 0; ni < 4; ni++)
            #pragma unroll
            for (int r = 0; r < 4; r++) acc[mi][ni][r] = 0.f;

    const int sto = row * GM_PAD + off;
    uint4 ld[2][2];

    ld[0][0] = *(const uint4*)gp0;       ld[0][1] = *(const uint4*)(gp0 + 8);
    ld[1][0] = *(const uint4*)gp1;       ld[1][1] = *(const uint4*)(gp1 + 8);
    #pragma unroll
    for (int arr = 0; arr < 2; arr++) {
        *(uint4*)&smh[arr*GM_BUF + sto]     = ld[arr][0];
        *(uint4*)&smh[arr*GM_BUF + sto + 8] = ld[arr][1];
    }
    __syncthreads();

    const int NKT = K >> 5;
    for (int kt = 0; kt < NKT; kt++) {
        const int b = kt & 1;
        if (kt + 1 < NKT) {
            const int kb = (kt + 1) << 5;
            ld[0][0] = *(const uint4*)(gp0 + kb); ld[0][1] = *(const uint4*)(gp0 + kb + 8);
            ld[1][0] = *(const uint4*)(gp1 + kb); ld[1][1] = *(const uint4*)(gp1 + kb + 8);
        }

        const __half* sA = smh + b*(2*GM_BUF);
        const __half* sB = sA + GM_BUF;

        #pragma unroll
        for (int k16 = 0; k16 < 32; k16 += 16) {
            uint32_t af[4][4];
            #pragma unroll
            for (int mi = 0; mi < 4; mi++) {
                int roff = (wm*64 + mi*16 + l16) * GM_PAD + k16 + (lane >> 4) * 8;
                ldsm_x4(af[mi][0], af[mi][1], af[mi][2], af[mi][3], smem_u32(sA + roff));
            }
            #pragma unroll
            for (int ni = 0; ni < 4; ni++) {
                int boff = (wn*32 + ni*8 + (l16 & 7)) * GM_PAD + k16 + ((l16 >> 3) & 1) * 8;
                uint32_t b0, b1;
                ldsm_x2(b0, b1, smem_u32(sB + boff));
                #pragma unroll
                for (int mi = 0; mi < 4; mi++)
                    mma_f16_f32(acc[mi][ni], af[mi][0], af[mi][1], af[mi][2], af[mi][3], b0, b1);
            }
        }

        if (kt + 1 < NKT) {
            __half* dst = smh + (b ^ 1)*(2*GM_BUF);
            #pragma unroll
            for (int arr = 0; arr < 2; arr++) {
                *(uint4*)&dst[arr*GM_BUF + sto]     = ld[arr][0];
                *(uint4*)&dst[arr*GM_BUF + sto + 8] = ld[arr][1];
            }
        }
        __syncthreads();
    }

    const int g = lane >> 2, tg = lane & 3;
    #pragma unroll
    for (int mi = 0; mi < 4; mi++) {
        #pragma unroll
        for (int ni = 0; ni < 4; ni++) {
            int r0 = m0 + wm*64 + mi*16 + g;
            int c0 = n0 + wn*32 + ni*8 + tg*2;
            float2 lo = {acc[mi][ni][0], acc[mi][ni][1]};
            float2 hi = {acc[mi][ni][2], acc[mi][ni][3]};
            *(float2*)&C[(size_t)r0 * N + c0]       = lo;
            *(float2*)&C[(size_t)(r0 + 8) * N + c0] = hi;
        }
    }
}

// ---------------- RoPE + relu feature projection on tensor cores -------------
#define RP_P 72
__global__ void __launch_bounds__(128) ropeproj_kernel(
    const float* __restrict__ cosg, const float* __restrict__ sing,
    const float* __restrict__ proj)
{
    __shared__ __half dat[64*RP_P];
    __shared__ __half pj [64*RP_P];
    const int tid = threadIdx.x;
    const int rbase = blockIdx.x * 64;

    #pragma unroll
    for (int j = 0; j < 32; j++) {
        int i = tid + j*128;
        int f = i >> 6, d = i & 63;
        pj[f*RP_P + d] = __float2half(proj[i]);
    }
    #pragma unroll
    for (int j = 0; j < 16; j++) {
        int e = tid + j*128;
        int r = e >> 5, d = e & 31;
        int rho = rbase + r;
        int bs  = rho / 24;
        int h   = rho - bs*24;
        int s   = bs & (Sv-1);
        size_t base = (size_t)bs*QKVD + h*64;
        float x1 = g_qkv[base + d];
        float x2 = g_qkv[base + d + 32];
        float cc = cosg[s*64 + d];
        float ss = sing[s*64 + d];
        dat[r*RP_P + d]      = __float2half(fmaf(x1, cc, -x2 * ss));
        dat[r*RP_P + d + 32] = __float2half(fmaf(x2, cc,  x1 * ss));
    }
    __syncthreads();

    const int wid = tid >> 5, lane = tid & 31;
    const int l16 = lane & 15, g = lane >> 2, tg = lane & 3;
    const int mrow = wid * 16;
    const int ahalf = (lane >> 4) * 8;

    float acc[8][4];
    #pragma unroll
    for (int nt = 0; nt < 8; nt++)
        #pragma unroll
        for (int r = 0; r < 4; r++) acc[nt][r] = 0.f;

    #pragma unroll
    for (int k16 = 0; k16 < 64; k16 += 16) {
        int ro = (mrow + l16)*RP_P + k16 + ahalf;
        uint32_t a0,a1,a2,a3;
        ldsm_x4(a0,a1,a2,a3, smem_u32(dat + ro));
        #pragma unroll
        for (int nt = 0; nt < 8; nt++) {
            int bo = (nt*8 + (l16 & 7))*RP_P + k16 + ((l16 >> 3) & 1)*8;
            uint32_t b0,b1;
            ldsm_x2(b0,b1, smem_u32(pj + bo));
            mma_f16_f32(acc[nt], a0,a1,a2,a3, b0,b1);
        }
    }

    const float ratio = (float)(0.125 * (0.125 + 1e-4));
    float o[8][4];
    float rs0 = 0.f, rs1 = 0.f;
    #pragma unroll
    for (int nt = 0; nt < 8; nt++) {
        o[nt][0] = fmaxf(acc[nt][0]*ratio, 0.f);
        o[nt][1] = fmaxf(acc[nt][1]*ratio, 0.f);
        o[nt][2] = fmaxf(acc[nt][2]*ratio, 0.f);
        o[nt][3] = fmaxf(acc[nt][3]*ratio, 0.f);
        rs0 += o[nt][0] + o[nt][1];
        rs1 += o[nt][2] + o[nt][3];
    }
    rs0 += __shfl_xor_sync(0xffffffffu, rs0, 1);
    rs0 += __shfl_xor_sync(0xffffffffu, rs0, 2);
    rs1 += __shfl_xor_sync(0xffffffffu, rs1, 1);
    rs1 += __shfl_xor_sync(0xffffffffu, rs1, 2);

    #pragma unroll
    for (int half = 0; half < 2; half++) {
        int r   = mrow + g + half*8;
        int rho = rbase + r;
        int bs  = rho / 24;
        int h   = rho - bs*24;
        float rs = half ? rs1 : rs0;
        if (h < NHEAD) {
            float* dst = &g_qp[((size_t)bs*NHEAD + h)*NFEAT];
            #pragma unroll
            for (int nt = 0; nt < 8; nt++) {
                float2 v = {o[nt][half*2] + 1e-4f, o[nt][half*2+1] + 1e-4f};
                *(float2*)&dst[nt*8 + tg*2] = v;
            }
        } else {
            int kvh = h - NHEAD;
            int b = bs >> 12, t = bs & 4095;
            float* dst = &g_kp[((size_t)bs*NKVH + kvh)*NFEAT];
            #pragma unroll
            for (int nt = 0; nt < 8; nt++) {
                float2 v = {o[nt][half*2], o[nt][half*2+1]};
                *(float2*)&dst[nt*8 + tg*2] = v;
            }
            if (tg == 0) g_z[((size_t)(b*NKVH + kvh))*Sv + t] = rs;
        }
    }
}

// ---------------- inclusive scan of g_z per (b,kvh), in place -----------------
__global__ void __launch_bounds__(256) zscan_kernel()
{
    const int bkv = blockIdx.x;
    const int tid = threadIdx.x;
    const int lane = tid & 31, warp = tid >> 5;
    __shared__ float wsum[8];
    float carry = 0.f;

    for (int tile = 0; tile < 16; tile++) {
        int t = tile*256 + tid;
        float x = g_z[(size_t)bkv*Sv + t];
        #pragma unroll
        for (int o = 1; o < 32; o <<= 1) {
            float n = __shfl_up_sync(0xffffffffu, x, o);
            if (lane >= o) x += n;
        }
        if (lane == 31) wsum[warp] = x;
        __syncthreads();
        float off = carry;
        for (int w2 = 0; w2 < warp; w2++) off += wsum[w2];
        g_z[(size_t)bkv*Sv + t] = off + x;
        float tot = 0.f;
        #pragma unroll
        for (int w2 = 0; w2 < 8; w2++) tot += wsum[w2];
        carry += tot;
        __syncthreads();
    }
}

// ---------------- per-chunk KV = Kp^T V (64x64) via mma.sync ------------------
// A = Kp^T stored transposed in smem [f][t] (normal ldsm), B = V [t][d] via
// trans ldsm (proven pattern). 128 threads, 4 warps x 16 f-rows.
#define CK_KT 136
#define CK_VP 72
__global__ void __launch_bounds__(128) chunkkv_kernel()
{
    __shared__ __half Kt[64*CK_KT];   // [f][t]
    __shared__ __half Vs[128*CK_VP];  // [t][d]
    const int c   = blockIdx.x;
    const int bkv = blockIdx.y;
    const int b   = bkv >> 3, kvh = bkv & 7;
    const int tid = threadIdx.x;

    #pragma unroll
    for (int j = 0; j < 64; j++) {
        int e = tid + j*128;
        int t = e >> 6, f = e & 63;
        size_t bs = (size_t)(b*Sv + c*CHUNK + t);
        Kt[f*CK_KT + t] = __float2half(g_kp[(bs*NKVH + kvh)*NFEAT + f]);
        Vs[t*CK_VP + f] = __float2half(g_qkv[bs*QKVD + 1536 + kvh*64 + f]);
    }
    __syncthreads();

    const int wid = tid >> 5, lane = tid & 31;
    const int l16 = lane & 15, g = lane >> 2, tg = lane & 3;
    const int mrow = wid * 16;
    const int ahalf = (lane >> 4) * 8;

    float acc[8][4];
    #pragma unroll
    for (int nt = 0; nt < 8; nt++)
        #pragma unroll
        for (int r = 0; r < 4; r++) acc[nt][r] = 0.f;

    #pragma unroll
    for (int k16 = 0; k16 < 128; k16 += 16) {
        int ro = (mrow + l16)*CK_KT + k16 + ahalf;
        uint32_t a0,a1,a2,a3;
        ldsm_x4(a0,a1,a2,a3, smem_u32(Kt + ro));
        #pragma unroll
        for (int nt = 0; nt < 8; nt++) {
            int bo = (k16 + l16)*CK_VP + nt*8;
            uint32_t b0,b1;
            ldsm_x2_t(b0,b1, smem_u32(Vs + bo));
            mma_f16_f32(acc[nt], a0,a1,a2,a3, b0,b1);
        }
    }

    size_t base = ((size_t)bkv*NCHUNK + c)*4096;
    #pragma unroll
    for (int nt = 0; nt < 8; nt++) {
        int r0 = mrow + g, r1 = r0 + 8;
        int c0 = nt*8 + tg*2;
        float2 v0 = {acc[nt][0], acc[nt][1]};
        float2 v1 = {acc[nt][2], acc[nt][3]};
        *(float2*)&g_kvc[base + (size_t)r0*64 + c0] = v0;
        *(float2*)&g_kvc[base + (size_t)r1*64 + c0] = v1;
    }
}

// ---------------- exclusive chunk-prefix of KV, in place ---------------------
__global__ void __launch_bounds__(256) kvprefix_kernel()
{
    const int bkv = blockIdx.x;
    const int tid = threadIdx.x;
    float acc[16];
    #pragma unroll
    for (int j = 0; j < 16; j++) acc[j] = 0.f;
    for (int c = 0; c < NCHUNK; c++) {
        size_t base = ((size_t)bkv*NCHUNK + c)*4096;
        #pragma unroll
        for (int j = 0; j < 16; j++) {
            size_t idx = base + tid + j*256;
            float cur = g_kvc[idx];
            g_kvc[idx] = acc[j];
            acc[j] += cur;
        }
    }
}

// ---------------- stage D: 1-pass fp16 causal combine ------------------------
#define SD_QP  72
#define SD_SP  136
#define O_Q    0
#define O_K    9216
#define O_V    18432
#define O_C    27648
#define O_S    32256
#define SD_HALVES 49664
#define SD_BYTES  (SD_HALVES*2 + 512)

__global__ void __launch_bounds__(256) stage_d_kernel()
{
    extern __shared__ __half shd[];
    __half* sQ = shd + O_Q;
    __half* sK = shd + O_K;
    __half* sV = shd + O_V;
    __half* sC = shd + O_C;
    __half* sS = shd + O_S;
    float* dinv = (float*)(shd + SD_HALVES);

    const int c   = blockIdx.x;
    const int h   = blockIdx.y;
    const int b   = blockIdx.z;
    const int kvh = h >> 1;
    const int tid = threadIdx.x;
    const size_t t0 = (size_t)b*Sv + c*CHUNK;

    #pragma unroll
    for (int j = 0; j < 32; j++) {
        int e = tid + j*256;
        int t = e >> 6, f = e & 63;
        sQ[t*SD_QP + f] = __float2half(g_qp[((t0 + t)*NHEAD + h)*NFEAT + f]);
        sK[t*SD_QP + f] = __float2half(g_kp[((t0 + t)*NKVH + kvh)*NFEAT + f]);
        sV[t*SD_QP + f] = __float2half(g_qkv[(t0 + t)*QKVD + 1536 + kvh*64 + f]);
    }
    #pragma unroll
    for (int j = 0; j < 16; j++) {
        int e = tid + j*256;
        int f = e >> 6, d = e & 63;
        sC[f*SD_QP + d] = __float2half(
            g_kvc[(((size_t)(b*NKVH + kvh))*NCHUNK + c)*4096 + e]);
    }
    __syncthreads();

    if (tid < 128) {
        float s = 0.f;
        #pragma unroll
        for (int f = 0; f < 64; f++)
            s += __half2float(sQ[tid*SD_QP + f]);
        float z = g_z[((size_t)(b*NKVH + kvh))*Sv + c*CHUNK + tid];
        dinv[tid] = 1.0f / (s*z + 1e-6f);
    }
    __syncthreads();

    const int wid = tid >> 5, lane = tid & 31;
    const int l16 = lane & 15, g = lane >> 2, tg = lane & 3;
    const int mrow = wid * 16;
    const int ahalf = (lane >> 4) * 8;

    // phase 1: S = tril(Q K^T), single pass, store fp16
    {
        float accS[16][4];
        #pragma unroll
        for (int nt = 0; nt < 16; nt++)
            #pragma unroll
            for (int r = 0; r < 4; r++) accS[nt][r] = 0.f;

        #pragma unroll
        for (int k16 = 0; k16 < 64; k16 += 16) {
            int ro = (mrow + l16)*SD_QP + k16 + ahalf;
            uint32_t a0,a1,a2,a3;
            ldsm_x4(a0,a1,a2,a3, smem_u32(sQ + ro));
            #pragma unroll
            for (int nt = 0; nt < 16; nt++) {
                int bo = (nt*8 + (l16 & 7))*SD_QP + k16 + ((l16 >> 3) & 1)*8;
                uint32_t b0,b1;
                ldsm_x2(b0,b1, smem_u32(sK + bo));
                mma_f16_f32(accS[nt], a0,a1,a2,a3, b0,b1);
            }
        }
        #pragma unroll
        for (int nt = 0; nt < 16; nt++) {
            int r0 = mrow + g, r1 = r0 + 8;
            int c0 = nt*8 + tg*2;
            float v00 = (c0     <= r0) ? accS[nt][0] : 0.f;
            float v01 = (c0 + 1 <= r0) ? accS[nt][1] : 0.f;
            float v10 = (c0     <= r1) ? accS[nt][2] : 0.f;
            float v11 = (c0 + 1 <= r1) ? accS[nt][3] : 0.f;
            *(uint32_t*)&sS[r0*SD_SP + c0] = pack2h(v00, v01);
            *(uint32_t*)&sS[r1*SD_SP + c0] = pack2h(v10, v11);
        }
    }
    __syncwarp();

    // phase 2: num = S*V + Q*C, scale, store fp16
    {
        float acc[8][4];
        #pragma unroll
        for (int nt = 0; nt < 8; nt++)
            #pragma unroll
            for (int r = 0; r < 4; r++) acc[nt][r] = 0.f;

        #pragma unroll
        for (int k16 = 0; k16 < 128; k16 += 16) {
            int ro = (mrow + l16)*SD_SP + k16 + ahalf;
            uint32_t a0,a1,a2,a3;
            ldsm_x4(a0,a1,a2,a3, smem_u32(sS + ro));
            #pragma unroll
            for (int nt = 0; nt < 8; nt++) {
                int bo = (k16 + l16)*SD_QP + nt*8;
                uint32_t b0,b1;
                ldsm_x2_t(b0,b1, smem_u32(sV + bo));
                mma_f16_f32(acc[nt], a0,a1,a2,a3, b0,b1);
            }
        }
        #pragma unroll
        for (int k16 = 0; k16 < 64; k16 += 16) {
            int ro = (mrow + l16)*SD_QP + k16 + ahalf;
            uint32_t a0,a1,a2,a3;
            ldsm_x4(a0,a1,a2,a3, smem_u32(sQ + ro));
            #pragma unroll
            for (int nt = 0; nt < 8; nt++) {
                int bo = (k16 + l16)*SD_QP + nt*8;
                uint32_t b0,b1;
                ldsm_x2_t(b0,b1, smem_u32(sC + bo));
                mma_f16_f32(acc[nt], a0,a1,a2,a3, b0,b1);
            }
        }

        const int r0 = mrow + g, r1 = r0 + 8;
        const float d0 = dinv[r0], d1 = dinv[r1];
        #pragma unroll
        for (int nt = 0; nt < 8; nt++) {
            int c0 = nt*8 + tg*2;
            float o00 = acc[nt][0]*d0, o01 = acc[nt][1]*d0;
            float o10 = acc[nt][2]*d1, o11 = acc[nt][3]*d1;
            size_t a0 = (t0 + r0)*1024 + h*64 + c0;
            size_t a1 = (t0 + r1)*1024 + h*64 + c0;
            *(uint32_t*)&g_ah[a0] = pack2h(o00, o01);
            *(uint32_t*)&g_ah[a1] = pack2h(o10, o11);
        }
    }
}

// ---------------- launch ------------------------------------------------------
extern "C" void kernel_launch(void* const* d_in, const int* in_sizes, int n_in,
                              void* d_out, int out_size)
{
    const float* hidden = (const float*)d_in[0];
    const float* cosg   = (const float*)d_in[1];
    const float* sing   = (const float*)d_in[2];
    const float* W_qkv  = (const float*)d_in[3];
    const float* W_o    = (const float*)d_in[4];
    const float* proj   = (const float*)d_in[5];
    float* out = (float*)d_out;

    static bool attr_done = false;
    if (!attr_done) {
        cudaFuncSetAttribute(stage_d_kernel,
            cudaFuncAttributeMaxDynamicSharedMemorySize, SD_BYTES);
        cudaFuncSetAttribute(gemm_mma_kernel,
            cudaFuncAttributeMaxDynamicSharedMemorySize, GM_SMEM);
        attr_done = true;
    }

    float* qkv = nullptr; cudaGetSymbolAddress((void**)&qkv, g_qkv);
    __half *ah, *w1, *w2;
    cudaGetSymbolAddress((void**)&ah, g_ah);
    cudaGetSymbolAddress((void**)&w1, g_w1);
    cudaGetSymbolAddress((void**)&w2, g_w2);

    // 1. convert hidden + W_qkv to fp16, 1-pass QKV GEMM
    cvt_h_kernel<<<(MROWS*1024)/1024, 256>>>(hidden, ah, MROWS*1024);
    cvt_h_kernel<<<(2048*1024)/1024, 256>>>(W_qkv, w1, 2048*1024);
    gemm_mma_kernel<<<dim3(QKVD/128, MROWS/128), 256, GM_SMEM>>>(
        ah, w1, qkv, QKVD, 1024);

    // 2. rope + feature projection on tensor cores (+ fused kp rowsums)
    ropeproj_kernel<<<(MROWS*24)/64, 128>>>(cosg, sing, proj);
    // 3. z scan
    zscan_kernel<<<Bv*NKVH, 256>>>();
    // 4. per-chunk KV (mma.sync)
    chunkkv_kernel<<<dim3(NCHUNK, Bv*NKVH), 128>>>();
    // 5. exclusive chunk prefix
    kvprefix_kernel<<<Bv*NKVH, 256>>>();
    // 6. causal combine (1-pass fp16) -> fp16 attn into g_ah
    stage_d_kernel<<<dim3(NCHUNK, NHEAD, Bv), 256, SD_BYTES>>>();

    // 7. convert W_o to fp16, 1-pass output GEMM
    cvt_h_kernel<<<(1024*1024)/1024, 256>>>(W_o, w2, 1024*1024);
    gemm_mma_kernel<<<dim3(1024/128, MROWS/128), 256, GM_SMEM>>>(
        ah, w2, out, 1024, 1024);
}